// round 1
// baseline (speedup 1.0000x reference)
#include <cuda_runtime.h>

// Problem constants
#define BB 4
#define TT 2048
#define HH 16
#define DH 64
#define CC 1024
#define MM (BB * TT)   // 8192 rows

// Scratch (device globals -- allocation-free per harness rules)
static __device__ float g_q[(size_t)MM * CC];
static __device__ float g_k[(size_t)MM * CC];
static __device__ float g_v[(size_t)MM * CC];
static __device__ float g_attn[(size_t)MM * CC];

// ---------------------------------------------------------------------------
// GEMM: Y = X @ W^T   (X: [M, C], W: [N=C, C], both K-contiguous)
// 64x64 block tile, 256 threads, 4x4 microtile, K-chunk 32.
// to_heads=1: write Y into [b, h, t, d] layout (for Q/K/V feeding attention).
// to_heads=0: write Y into plain [m, n] layout.
// ---------------------------------------------------------------------------
__global__ void __launch_bounds__(256) gemm_wt_kernel(
    const float* __restrict__ X, const float* __restrict__ W,
    float* __restrict__ Y, int to_heads)
{
    __shared__ float Xs[64][33];
    __shared__ float Ws[64][33];

    const int tid = threadIdx.x;
    const int n0 = blockIdx.x * 64;
    const int m0 = blockIdx.y * 64;
    const int ty = tid >> 4;      // 0..15
    const int tx = tid & 15;      // 0..15

    float acc[4][4] = {};

    for (int k0 = 0; k0 < CC; k0 += 32) {
        // cooperative load of X tile [64x32] and W tile [64x32]
        #pragma unroll
        for (int i = tid; i < 64 * 32; i += 256) {
            const int r = i >> 5;
            const int c = i & 31;
            Xs[r][c] = X[(size_t)(m0 + r) * CC + k0 + c];
            Ws[r][c] = W[(size_t)(n0 + r) * CC + k0 + c];
        }
        __syncthreads();

        #pragma unroll
        for (int kk = 0; kk < 32; kk++) {
            float a[4], b[4];
            #pragma unroll
            for (int i = 0; i < 4; i++) a[i] = Xs[ty * 4 + i][kk];
            #pragma unroll
            for (int j = 0; j < 4; j++) b[j] = Ws[tx * 4 + j][kk];
            #pragma unroll
            for (int i = 0; i < 4; i++)
                #pragma unroll
                for (int j = 0; j < 4; j++)
                    acc[i][j] = fmaf(a[i], b[j], acc[i][j]);
        }
        __syncthreads();
    }

    #pragma unroll
    for (int i = 0; i < 4; i++) {
        const int m = m0 + ty * 4 + i;
        #pragma unroll
        for (int j = 0; j < 4; j++) {
            const int n = n0 + tx * 4 + j;
            if (to_heads) {
                const int b  = m >> 11;        // m / 2048
                const int t  = m & 2047;
                const int h  = n >> 6;         // n / 64
                const int d  = n & 63;
                Y[(((size_t)(b * HH + h) * TT) + t) * DH + d] = acc[i][j];
            } else {
                Y[(size_t)m * CC + n] = acc[i][j];
            }
        }
    }
}

// ---------------------------------------------------------------------------
// Flash attention (fp32, causal). One block per (q-tile of 64 rows, b*h).
// 256 threads. Q/K/V layout: [b*h, t, 64]. Output to [b, t, h*64+d] (= plain
// [m, c] layout ready for the output projection GEMM).
// ---------------------------------------------------------------------------
__global__ void __launch_bounds__(256) flash_attn_kernel(
    const float* __restrict__ Q, const float* __restrict__ K,
    const float* __restrict__ V, float* __restrict__ O)
{
    extern __shared__ float sm[];
    float* Qs  = sm;                 // 64*65
    float* Ks  = Qs + 64 * 65;       // 64*65
    float* Vs  = Ks + 64 * 65;       // 64*65
    float* Ss  = Vs + 64 * 65;       // 64*65
    float* m_s = Ss + 64 * 65;       // 64
    float* l_s = m_s + 64;           // 64
    float* c_s = l_s + 64;           // 64 (rescale factor per row)

    const int tid = threadIdx.x;
    // heavy tiles (large qi) first to reduce wave-tail imbalance
    const int qi = (int)gridDim.x - 1 - (int)blockIdx.x;
    const int bh = blockIdx.y;
    const int q0 = qi * 64;

    const size_t base = (size_t)bh * TT * DH;

    // load Q tile
    #pragma unroll
    for (int i = tid; i < 64 * 64; i += 256) {
        const int r = i >> 6, d = i & 63;
        Qs[r * 65 + d] = Q[base + (size_t)(q0 + r) * DH + d];
    }
    if (tid < 64) { m_s[tid] = -1e30f; l_s[tid] = 0.0f; }

    const int ty = tid >> 4, tx = tid & 15;
    float o[4][4] = {};
    const float scale = 0.125f;   // 1/sqrt(64)

    __syncthreads();

    for (int j = 0; j <= qi; j++) {
        // load K, V tiles
        #pragma unroll
        for (int i = tid; i < 64 * 64; i += 256) {
            const int r = i >> 6, d = i & 63;
            Ks[r * 65 + d] = K[base + (size_t)(j * 64 + r) * DH + d];
            Vs[r * 65 + d] = V[base + (size_t)(j * 64 + r) * DH + d];
        }
        __syncthreads();

        // S = scale * Qs @ Ks^T  (64x64), with causal mask on diagonal tile
        float s[4][4] = {};
        #pragma unroll 8
        for (int kk = 0; kk < 64; kk++) {
            float a[4], b[4];
            #pragma unroll
            for (int i = 0; i < 4; i++) a[i] = Qs[(ty * 4 + i) * 65 + kk];
            #pragma unroll
            for (int jj = 0; jj < 4; jj++) b[jj] = Ks[(tx * 4 + jj) * 65 + kk];
            #pragma unroll
            for (int i = 0; i < 4; i++)
                #pragma unroll
                for (int jj = 0; jj < 4; jj++)
                    s[i][jj] = fmaf(a[i], b[jj], s[i][jj]);
        }
        #pragma unroll
        for (int i = 0; i < 4; i++) {
            const int rl = ty * 4 + i;
            #pragma unroll
            for (int jj = 0; jj < 4; jj++) {
                const int cl = tx * 4 + jj;
                float v = s[i][jj] * scale;
                if (j == qi && cl > rl) v = -1e30f;
                Ss[rl * 65 + cl] = v;
            }
        }
        __syncthreads();

        // online softmax: 4 threads per row, each scans 16 columns
        {
            const int row = tid >> 2;
            const int seg = tid & 3;
            const int c0 = seg * 16;
            float mx = -1e30f;
            #pragma unroll
            for (int c = 0; c < 16; c++) mx = fmaxf(mx, Ss[row * 65 + c0 + c]);
            mx = fmaxf(mx, __shfl_xor_sync(0xffffffffu, mx, 1));
            mx = fmaxf(mx, __shfl_xor_sync(0xffffffffu, mx, 2));
            const float mold = m_s[row];
            const float mnew = fmaxf(mold, mx);
            const float rescale = __expf(mold - mnew);
            float sum = 0.0f;
            #pragma unroll
            for (int c = 0; c < 16; c++) {
                float p = __expf(Ss[row * 65 + c0 + c] - mnew);
                Ss[row * 65 + c0 + c] = p;
                sum += p;
            }
            sum += __shfl_xor_sync(0xffffffffu, sum, 1);
            sum += __shfl_xor_sync(0xffffffffu, sum, 2);
            if (seg == 0) {
                m_s[row] = mnew;
                c_s[row] = rescale;
                l_s[row] = l_s[row] * rescale + sum;
            }
        }
        __syncthreads();

        // O = O * rescale + P @ V
        #pragma unroll
        for (int i = 0; i < 4; i++) {
            const float rs = c_s[ty * 4 + i];
            #pragma unroll
            for (int jj = 0; jj < 4; jj++) o[i][jj] *= rs;
        }
        #pragma unroll 8
        for (int c = 0; c < 64; c++) {
            float p[4], v[4];
            #pragma unroll
            for (int i = 0; i < 4; i++) p[i] = Ss[(ty * 4 + i) * 65 + c];
            #pragma unroll
            for (int jj = 0; jj < 4; jj++) v[jj] = Vs[c * 65 + tx * 4 + jj];
            #pragma unroll
            for (int i = 0; i < 4; i++)
                #pragma unroll
                for (int jj = 0; jj < 4; jj++)
                    o[i][jj] = fmaf(p[i], v[jj], o[i][jj]);
        }
        __syncthreads();
    }

    // normalize and write out in [b, t, h*64+d] layout
    const int b = bh >> 4;
    const int h = bh & 15;
    #pragma unroll
    for (int i = 0; i < 4; i++) {
        const int rl = ty * 4 + i;
        const float inv_l = 1.0f / l_s[rl];
        const int trow = q0 + rl;
        #pragma unroll
        for (int jj = 0; jj < 4; jj++) {
            const int d = tx * 4 + jj;
            O[((size_t)b * TT + trow) * CC + h * DH + d] = o[i][jj] * inv_l;
        }
    }
}

// ---------------------------------------------------------------------------
// Launch
// ---------------------------------------------------------------------------
extern "C" void kernel_launch(void* const* d_in, const int* in_sizes, int n_in,
                              void* d_out, int out_size)
{
    const float* x   = (const float*)d_in[0];
    const float* W_Q = (const float*)d_in[1];
    const float* W_K = (const float*)d_in[2];
    const float* W_V = (const float*)d_in[3];
    const float* W_O = (const float*)d_in[4];
    float* out = (float*)d_out;

    float *q, *k, *v, *attn;
    cudaGetSymbolAddress((void**)&q,    g_q);
    cudaGetSymbolAddress((void**)&k,    g_k);
    cudaGetSymbolAddress((void**)&v,    g_v);
    cudaGetSymbolAddress((void**)&attn, g_attn);

    const int attn_smem = (4 * 64 * 65 + 3 * 64) * (int)sizeof(float);
    cudaFuncSetAttribute(flash_attn_kernel,
                         cudaFuncAttributeMaxDynamicSharedMemorySize, attn_smem);

    dim3 gemm_grid(CC / 64, MM / 64);
    gemm_wt_kernel<<<gemm_grid, 256>>>(x, W_Q, q, 1);
    gemm_wt_kernel<<<gemm_grid, 256>>>(x, W_K, k, 1);
    gemm_wt_kernel<<<gemm_grid, 256>>>(x, W_V, v, 1);

    dim3 attn_grid(TT / 64, BB * HH);
    flash_attn_kernel<<<attn_grid, 256, attn_smem>>>(q, k, v, attn);

    gemm_wt_kernel<<<gemm_grid, 256>>>(attn, W_O, out, 0);
}

// round 3
// speedup vs baseline: 1.6630x; 1.6630x over previous
#include <cuda_runtime.h>
#include <cuda_bf16.h>
#include <cstdint>

// Problem constants
#define BB 4
#define TT 2048
#define HH 16
#define DH 64
#define CC 1024
#define MM (BB * TT)   // 8192 rows

// ---------------------------------------------------------------------------
// Scratch (device globals -- allocation-free per harness rules)
// ---------------------------------------------------------------------------
static __device__ __align__(16) float g_q[(size_t)MM * CC];
static __device__ __align__(16) float g_k[(size_t)MM * CC];
static __device__ __align__(16) float g_v[(size_t)MM * CC];
static __device__ __align__(16) float g_attn[(size_t)MM * CC];

static __device__ __align__(16) __nv_bfloat16 g_xhi[(size_t)MM * CC];
static __device__ __align__(16) __nv_bfloat16 g_xlo[(size_t)MM * CC];
static __device__ __align__(16) __nv_bfloat16 g_ahi[(size_t)MM * CC];
static __device__ __align__(16) __nv_bfloat16 g_alo[(size_t)MM * CC];
static __device__ __align__(16) __nv_bfloat16 g_whi[4][(size_t)CC * CC];
static __device__ __align__(16) __nv_bfloat16 g_wlo[4][(size_t)CC * CC];

// ---------------------------------------------------------------------------
// PTX helpers (portable: sm_80+ features only -- compute_103 safe)
// ---------------------------------------------------------------------------
__device__ __forceinline__ uint32_t smem_u32(const void* p) {
    uint32_t a;
    asm("{ .reg .u64 t; cvta.to.shared.u64 t, %1; cvt.u32.u64 %0, t; }"
        : "=r"(a) : "l"(p));
    return a;
}

#define CP_ASYNC16(saddr, gaddr) \
    asm volatile("cp.async.cg.shared.global [%0], [%1], 16;" \
                 :: "r"(saddr), "l"(gaddr))
#define CP_COMMIT() asm volatile("cp.async.commit_group;" ::: "memory")
#define CP_WAIT0()  asm volatile("cp.async.wait_group 0;" ::: "memory")

#define LDSM4(r, addr)                                                          \
    asm volatile("ldmatrix.sync.aligned.m8n8.x4.shared.b16 {%0,%1,%2,%3}, [%4];"\
                 : "=r"((r)[0]), "=r"((r)[1]), "=r"((r)[2]), "=r"((r)[3])       \
                 : "r"(addr))

#define MMA16816(c, a, b)                                                       \
    asm volatile("mma.sync.aligned.m16n8k16.row.col.f32.bf16.bf16.f32 "         \
                 "{%0,%1,%2,%3}, {%4,%5,%6,%7}, {%8,%9}, {%0,%1,%2,%3};"        \
                 : "+f"((c)[0]), "+f"((c)[1]), "+f"((c)[2]), "+f"((c)[3])       \
                 : "r"((a)[0]), "r"((a)[1]), "r"((a)[2]), "r"((a)[3]),          \
                   "r"((b)[0]), "r"((b)[1]))

// ---------------------------------------------------------------------------
// fp32 -> (hi, lo) bf16 split
// ---------------------------------------------------------------------------
__global__ void __launch_bounds__(256) split_bf16_kernel(
    const float* __restrict__ in, __nv_bfloat16* __restrict__ hi,
    __nv_bfloat16* __restrict__ lo, int n4)
{
    int i = blockIdx.x * 256 + threadIdx.x;
    if (i >= n4) return;
    float4 v = ((const float4*)in)[i];
    __nv_bfloat16 h0 = __float2bfloat16(v.x);
    __nv_bfloat16 h1 = __float2bfloat16(v.y);
    __nv_bfloat16 h2 = __float2bfloat16(v.z);
    __nv_bfloat16 h3 = __float2bfloat16(v.w);
    __nv_bfloat162 hp0(h0, h1), hp1(h2, h3);
    __nv_bfloat162 lp0(__float2bfloat16(v.x - __bfloat162float(h0)),
                       __float2bfloat16(v.y - __bfloat162float(h1)));
    __nv_bfloat162 lp1(__float2bfloat16(v.z - __bfloat162float(h2)),
                       __float2bfloat16(v.w - __bfloat162float(h3)));
    uint2 ho, loo;
    ho.x = *(uint32_t*)&hp0;  ho.y = *(uint32_t*)&hp1;
    loo.x = *(uint32_t*)&lp0; loo.y = *(uint32_t*)&lp1;
    ((uint2*)hi)[i] = ho;
    ((uint2*)lo)[i] = loo;
}

// ---------------------------------------------------------------------------
// Split-bf16 tensor-core GEMM via mma.sync:
//   Y[M, N] = A[M, K] @ B[N, K]^T  with A,B given as (hi, lo) bf16 pairs.
// BM=128, BN=128, BK=32. 256 threads = 8 warps (2 x 4), warp tile 64x32.
// Double-buffered cp.async smem pipeline. Rows padded to 40 bf16 (80 B) for
// conflict-free ldmatrix. to_heads=1 writes [b, h, t, d] layout.
// ---------------------------------------------------------------------------
#define BM 128
#define BN 128
#define BK 32
#define NK (CC / BK)          // 32 chunks
#define ROWB 80               // bytes per smem row (32 bf16 + 8 pad)
#define SUBT (128 * ROWB)     // 10240 bytes per sub-tile
#define BUFB (4 * SUBT)       // 40960 per buffer (Ahi, Alo, Bhi, Blo)
#define GEMM_SMEM (2 * BUFB)  // 81920

__device__ __forceinline__ void load_chunk_async(
    uint32_t sb, int buf, int tid,
    const __nv_bfloat16* __restrict__ Ahi, const __nv_bfloat16* __restrict__ Alo,
    const __nv_bfloat16* __restrict__ Bhi, const __nv_bfloat16* __restrict__ Blo,
    int m0, int n0, int k0)
{
    const uint32_t base = sb + buf * BUFB;
    const __nv_bfloat16* gps[4] = {Ahi, Alo, Bhi, Blo};
    const int rb[4] = {m0, m0, n0, n0};
    #pragma unroll
    for (int it = 0; it < 8; it++) {
        const int sub = it >> 1;
        const int j = (it & 1) * 256 + tid;   // 0..511
        const int row = j >> 2;
        const int c16 = j & 3;
        const uint32_t saddr = base + sub * SUBT + row * ROWB + c16 * 16;
        const void* gaddr = gps[sub] + (size_t)(rb[sub] + row) * CC + k0 + c16 * 8;
        CP_ASYNC16(saddr, gaddr);
    }
}

__global__ void __launch_bounds__(256) gemm_tc_kernel(
    const __nv_bfloat16* __restrict__ Ahi, const __nv_bfloat16* __restrict__ Alo,
    const __nv_bfloat16* __restrict__ Bhi, const __nv_bfloat16* __restrict__ Blo,
    float* __restrict__ Y, int to_heads)
{
    extern __shared__ char smem[];
    const uint32_t sb = smem_u32(smem);
    const int tid = threadIdx.x;
    const int lane = tid & 31;
    const int wid = tid >> 5;
    const int wm = (wid >> 2) * 64;   // warp m offset (0 or 64)
    const int wn = (wid & 3) * 32;    // warp n offset (0, 32, 64, 96)
    const int n0 = blockIdx.x * BN;
    const int m0 = blockIdx.y * BM;

    float acc[4][4][4] = {};   // [m-tile][n-tile][frag]

    load_chunk_async(sb, 0, tid, Ahi, Alo, Bhi, Blo, m0, n0, 0);
    CP_COMMIT();

    // precomputed ldmatrix intra-warp offsets
    const int a_row = (lane & 15);               // row within 16
    const int a_koff = (lane >> 4) << 3;         // 0 or 8
    const int b_row = ((lane >> 4) << 3) + (lane & 7);   // row within 16
    const int b_koff = ((lane >> 3) & 1) << 3;   // 0 or 8

    for (int c = 0; c < NK; c++) {
        CP_WAIT0();
        __syncthreads();
        if (c + 1 < NK) {
            load_chunk_async(sb, (c + 1) & 1, tid, Ahi, Alo, Bhi, Blo,
                             m0, n0, (c + 1) * BK);
            CP_COMMIT();
        }

        const uint32_t ab = sb + (c & 1) * BUFB;
        const uint32_t bb = ab + 2 * SUBT;

        #pragma unroll
        for (int ks = 0; ks < 2; ks++) {
            uint32_t ah[16], al[16], bh[8], bl[8];
            #pragma unroll
            for (int mt = 0; mt < 4; mt++) {
                const uint32_t off =
                    (uint32_t)((wm + mt * 16 + a_row) * ROWB + (ks * 16 + a_koff) * 2);
                LDSM4(&ah[mt * 4], ab + off);
                LDSM4(&al[mt * 4], ab + SUBT + off);
            }
            #pragma unroll
            for (int nt2 = 0; nt2 < 2; nt2++) {
                const uint32_t off =
                    (uint32_t)((wn + nt2 * 16 + b_row) * ROWB + (ks * 16 + b_koff) * 2);
                LDSM4(&bh[nt2 * 4], bb + off);
                LDSM4(&bl[nt2 * 4], bb + SUBT + off);
            }
            #pragma unroll
            for (int mt = 0; mt < 4; mt++)
                #pragma unroll
                for (int nt = 0; nt < 4; nt++) {
                    float* cc = acc[mt][nt];
                    MMA16816(cc, &ah[mt * 4], &bh[nt * 2]);
                    MMA16816(cc, &ah[mt * 4], &bl[nt * 2]);
                    MMA16816(cc, &al[mt * 4], &bh[nt * 2]);
                }
        }
        __syncthreads();
    }

    // epilogue: registers -> smem staging -> coalesced global stores
    float* es = (float*)smem;   // [128][132]
    const int er = lane >> 2;
    const int ec = (lane & 3) * 2;
    #pragma unroll
    for (int mt = 0; mt < 4; mt++)
        #pragma unroll
        for (int nt = 0; nt < 4; nt++) {
            const int r = wm + mt * 16 + er;
            const int cl = wn + nt * 8 + ec;
            *(float2*)&es[r * 132 + cl] =
                make_float2(acc[mt][nt][0], acc[mt][nt][1]);
            *(float2*)&es[(r + 8) * 132 + cl] =
                make_float2(acc[mt][nt][2], acc[mt][nt][3]);
        }
    __syncthreads();

    #pragma unroll
    for (int it = 0; it < 16; it++) {
        const int i = tid + it * 256;       // 0..4095 float4 slots
        const int r = i >> 5;
        const int c4 = (i & 31) * 4;
        float4 v = *(float4*)&es[r * 132 + c4];
        const int m = m0 + r;
        const int n = n0 + c4;
        if (to_heads) {
            const int b = m >> 11, t = m & 2047, h = n >> 6, d = n & 63;
            *(float4*)&Y[(((size_t)(b * HH + h) * TT) + t) * DH + d] = v;
        } else {
            *(float4*)&Y[(size_t)m * CC + n] = v;
        }
    }
}

// ---------------------------------------------------------------------------
// Flash attention (fp32, causal) -- unchanged (passing, 1.215 ms)
// ---------------------------------------------------------------------------
__global__ void __launch_bounds__(256) flash_attn_kernel(
    const float* __restrict__ Q, const float* __restrict__ K,
    const float* __restrict__ V, float* __restrict__ O)
{
    extern __shared__ float sm[];
    float* Qs  = sm;
    float* Ks  = Qs + 64 * 65;
    float* Vs  = Ks + 64 * 65;
    float* Ss  = Vs + 64 * 65;
    float* m_s = Ss + 64 * 65;
    float* l_s = m_s + 64;
    float* c_s = l_s + 64;

    const int tid = threadIdx.x;
    const int qi = (int)gridDim.x - 1 - (int)blockIdx.x;
    const int bh = blockIdx.y;
    const int q0 = qi * 64;
    const size_t base = (size_t)bh * TT * DH;

    #pragma unroll
    for (int i = tid; i < 64 * 64; i += 256) {
        const int r = i >> 6, d = i & 63;
        Qs[r * 65 + d] = Q[base + (size_t)(q0 + r) * DH + d];
    }
    if (tid < 64) { m_s[tid] = -1e30f; l_s[tid] = 0.0f; }

    const int ty = tid >> 4, tx = tid & 15;
    float o[4][4] = {};
    const float scale = 0.125f;

    __syncthreads();

    for (int j = 0; j <= qi; j++) {
        #pragma unroll
        for (int i = tid; i < 64 * 64; i += 256) {
            const int r = i >> 6, d = i & 63;
            Ks[r * 65 + d] = K[base + (size_t)(j * 64 + r) * DH + d];
            Vs[r * 65 + d] = V[base + (size_t)(j * 64 + r) * DH + d];
        }
        __syncthreads();

        float s[4][4] = {};
        #pragma unroll 8
        for (int kk = 0; kk < 64; kk++) {
            float a[4], b[4];
            #pragma unroll
            for (int i = 0; i < 4; i++) a[i] = Qs[(ty * 4 + i) * 65 + kk];
            #pragma unroll
            for (int jj = 0; jj < 4; jj++) b[jj] = Ks[(tx * 4 + jj) * 65 + kk];
            #pragma unroll
            for (int i = 0; i < 4; i++)
                #pragma unroll
                for (int jj = 0; jj < 4; jj++)
                    s[i][jj] = fmaf(a[i], b[jj], s[i][jj]);
        }
        #pragma unroll
        for (int i = 0; i < 4; i++) {
            const int rl = ty * 4 + i;
            #pragma unroll
            for (int jj = 0; jj < 4; jj++) {
                const int cl = tx * 4 + jj;
                float v = s[i][jj] * scale;
                if (j == qi && cl > rl) v = -1e30f;
                Ss[rl * 65 + cl] = v;
            }
        }
        __syncthreads();

        {
            const int row = tid >> 2;
            const int seg = tid & 3;
            const int c0 = seg * 16;
            float mx = -1e30f;
            #pragma unroll
            for (int c = 0; c < 16; c++) mx = fmaxf(mx, Ss[row * 65 + c0 + c]);
            mx = fmaxf(mx, __shfl_xor_sync(0xffffffffu, mx, 1));
            mx = fmaxf(mx, __shfl_xor_sync(0xffffffffu, mx, 2));
            const float mold = m_s[row];
            const float mnew = fmaxf(mold, mx);
            const float rescale = __expf(mold - mnew);
            float sum = 0.0f;
            #pragma unroll
            for (int c = 0; c < 16; c++) {
                float p = __expf(Ss[row * 65 + c0 + c] - mnew);
                Ss[row * 65 + c0 + c] = p;
                sum += p;
            }
            sum += __shfl_xor_sync(0xffffffffu, sum, 1);
            sum += __shfl_xor_sync(0xffffffffu, sum, 2);
            if (seg == 0) {
                m_s[row] = mnew;
                c_s[row] = rescale;
                l_s[row] = l_s[row] * rescale + sum;
            }
        }
        __syncthreads();

        #pragma unroll
        for (int i = 0; i < 4; i++) {
            const float rs = c_s[ty * 4 + i];
            #pragma unroll
            for (int jj = 0; jj < 4; jj++) o[i][jj] *= rs;
        }
        #pragma unroll 8
        for (int c = 0; c < 64; c++) {
            float p[4], v[4];
            #pragma unroll
            for (int i = 0; i < 4; i++) p[i] = Ss[(ty * 4 + i) * 65 + c];
            #pragma unroll
            for (int jj = 0; jj < 4; jj++) v[jj] = Vs[c * 65 + tx * 4 + jj];
            #pragma unroll
            for (int i = 0; i < 4; i++)
                #pragma unroll
                for (int jj = 0; jj < 4; jj++)
                    o[i][jj] = fmaf(p[i], v[jj], o[i][jj]);
        }
        __syncthreads();
    }

    const int b = bh >> 4;
    const int h = bh & 15;
    #pragma unroll
    for (int i = 0; i < 4; i++) {
        const int rl = ty * 4 + i;
        const float inv_l = 1.0f / l_s[rl];
        const int trow = q0 + rl;
        #pragma unroll
        for (int jj = 0; jj < 4; jj++) {
            const int d = tx * 4 + jj;
            O[((size_t)b * TT + trow) * CC + h * DH + d] = o[i][jj] * inv_l;
        }
    }
}

// ---------------------------------------------------------------------------
// Launch
// ---------------------------------------------------------------------------
extern "C" void kernel_launch(void* const* d_in, const int* in_sizes, int n_in,
                              void* d_out, int out_size)
{
    const float* x   = (const float*)d_in[0];
    const float* W_Q = (const float*)d_in[1];
    const float* W_K = (const float*)d_in[2];
    const float* W_V = (const float*)d_in[3];
    const float* W_O = (const float*)d_in[4];
    float* out = (float*)d_out;

    float *q, *k, *v, *attn;
    cudaGetSymbolAddress((void**)&q,    g_q);
    cudaGetSymbolAddress((void**)&k,    g_k);
    cudaGetSymbolAddress((void**)&v,    g_v);
    cudaGetSymbolAddress((void**)&attn, g_attn);

    __nv_bfloat16 *xhi, *xlo, *ahi, *alo, *whi, *wlo;
    cudaGetSymbolAddress((void**)&xhi, g_xhi);
    cudaGetSymbolAddress((void**)&xlo, g_xlo);
    cudaGetSymbolAddress((void**)&ahi, g_ahi);
    cudaGetSymbolAddress((void**)&alo, g_alo);
    cudaGetSymbolAddress((void**)&whi, g_whi);
    cudaGetSymbolAddress((void**)&wlo, g_wlo);

    const int attn_smem = (4 * 64 * 65 + 3 * 64) * (int)sizeof(float);
    cudaFuncSetAttribute(flash_attn_kernel,
                         cudaFuncAttributeMaxDynamicSharedMemorySize, attn_smem);
    cudaFuncSetAttribute(gemm_tc_kernel,
                         cudaFuncAttributeMaxDynamicSharedMemorySize, GEMM_SMEM);

    const size_t WSZ = (size_t)CC * CC;

    const int nx4 = (MM * CC) / 4;
    const int nw4 = (CC * CC) / 4;
    split_bf16_kernel<<<(nx4 + 255) / 256, 256>>>(x, xhi, xlo, nx4);
    const float* Ws[4] = {W_Q, W_K, W_V, W_O};
    for (int i = 0; i < 4; i++)
        split_bf16_kernel<<<(nw4 + 255) / 256, 256>>>(Ws[i], whi + i * WSZ, wlo + i * WSZ, nw4);

    dim3 gemm_grid(CC / BN, MM / BM);   // (8, 64)
    gemm_tc_kernel<<<gemm_grid, 256, GEMM_SMEM>>>(xhi, xlo, whi + 0 * WSZ, wlo + 0 * WSZ, q, 1);
    gemm_tc_kernel<<<gemm_grid, 256, GEMM_SMEM>>>(xhi, xlo, whi + 1 * WSZ, wlo + 1 * WSZ, k, 1);
    gemm_tc_kernel<<<gemm_grid, 256, GEMM_SMEM>>>(xhi, xlo, whi + 2 * WSZ, wlo + 2 * WSZ, v, 1);

    dim3 attn_grid(TT / 64, BB * HH);
    flash_attn_kernel<<<attn_grid, 256, attn_smem>>>(q, k, v, attn);

    split_bf16_kernel<<<(nx4 + 255) / 256, 256>>>(attn, ahi, alo, nx4);
    gemm_tc_kernel<<<gemm_grid, 256, GEMM_SMEM>>>(ahi, alo, whi + 3 * WSZ, wlo + 3 * WSZ, out, 0);
}

// round 4
// speedup vs baseline: 3.0577x; 1.8387x over previous
#include <cuda_runtime.h>
#include <cuda_bf16.h>
#include <cstdint>

// Problem constants
#define BB 4
#define TT 2048
#define HH 16
#define DH 64
#define CC 1024
#define MM (BB * TT)   // 8192 rows

// ---------------------------------------------------------------------------
// Scratch (device globals -- allocation-free per harness rules)
// ---------------------------------------------------------------------------
static __device__ __align__(16) __nv_bfloat16 g_xhi[(size_t)MM * CC];
static __device__ __align__(16) __nv_bfloat16 g_xlo[(size_t)MM * CC];
static __device__ __align__(16) __nv_bfloat16 g_whi[4][(size_t)CC * CC];
static __device__ __align__(16) __nv_bfloat16 g_wlo[4][(size_t)CC * CC];
static __device__ __align__(16) __nv_bfloat16 g_qhi[(size_t)MM * CC];
static __device__ __align__(16) __nv_bfloat16 g_qlo[(size_t)MM * CC];
static __device__ __align__(16) __nv_bfloat16 g_khi[(size_t)MM * CC];
static __device__ __align__(16) __nv_bfloat16 g_klo[(size_t)MM * CC];
static __device__ __align__(16) __nv_bfloat16 g_vhi[(size_t)MM * CC];
static __device__ __align__(16) __nv_bfloat16 g_vlo[(size_t)MM * CC];
static __device__ __align__(16) __nv_bfloat16 g_ahi[(size_t)MM * CC];
static __device__ __align__(16) __nv_bfloat16 g_alo[(size_t)MM * CC];

// ---------------------------------------------------------------------------
// PTX helpers (sm_80+ portable -- compute_103 safe)
// ---------------------------------------------------------------------------
__device__ __forceinline__ uint32_t smem_u32(const void* p) {
    uint32_t a;
    asm("{ .reg .u64 t; cvta.to.shared.u64 t, %1; cvt.u32.u64 %0, t; }"
        : "=r"(a) : "l"(p));
    return a;
}

#define CP_ASYNC16(saddr, gaddr) \
    asm volatile("cp.async.cg.shared.global [%0], [%1], 16;" \
                 :: "r"(saddr), "l"(gaddr))
#define CP_COMMIT() asm volatile("cp.async.commit_group;" ::: "memory")
#define CP_WAIT0()  asm volatile("cp.async.wait_group 0;" ::: "memory")
#define CP_WAIT1()  asm volatile("cp.async.wait_group 1;" ::: "memory")

#define LDSM4(r, addr)                                                          \
    asm volatile("ldmatrix.sync.aligned.m8n8.x4.shared.b16 {%0,%1,%2,%3}, [%4];"\
                 : "=r"((r)[0]), "=r"((r)[1]), "=r"((r)[2]), "=r"((r)[3])       \
                 : "r"(addr))

#define LDSM4T(r, addr)                                                         \
    asm volatile("ldmatrix.sync.aligned.m8n8.x4.trans.shared.b16 {%0,%1,%2,%3}, [%4];" \
                 : "=r"((r)[0]), "=r"((r)[1]), "=r"((r)[2]), "=r"((r)[3])       \
                 : "r"(addr))

#define MMA16816(c, a, b)                                                       \
    asm volatile("mma.sync.aligned.m16n8k16.row.col.f32.bf16.bf16.f32 "         \
                 "{%0,%1,%2,%3}, {%4,%5,%6,%7}, {%8,%9}, {%0,%1,%2,%3};"        \
                 : "+f"((c)[0]), "+f"((c)[1]), "+f"((c)[2]), "+f"((c)[3])       \
                 : "r"((a)[0]), "r"((a)[1]), "r"((a)[2]), "r"((a)[3]),          \
                   "r"((b)[0]), "r"((b)[1]))

// exp2(y) for y <= 0, FMA/ALU pipes only (no MUFU). |rel err| ~2e-6.
__device__ __forceinline__ float fexp2(float y) {
    y = fmaxf(y, -126.0f);
    float t = __fadd_rn(y, 12582912.0f);
    int   e = __float_as_int(t) << 23;
    float f = __fsub_rn(y, __fsub_rn(t, 12582912.0f));
    float p =              1.3333558146e-3f;
    p = fmaf(p, f, 9.6181291077e-3f);
    p = fmaf(p, f, 5.5504108664e-2f);
    p = fmaf(p, f, 2.4022650696e-1f);
    p = fmaf(p, f, 6.9314718056e-1f);
    p = fmaf(p, f, 1.0f);
    return __uint_as_float((uint32_t)(__float_as_int(p) + e));
}

// fp32 pair -> packed bf16 hi pair (truncation) + bf16 lo pair (residual, RN)
__device__ __forceinline__ void pack_split(float v0, float v1,
                                           uint32_t& hi, uint32_t& lo) {
    uint32_t b0 = __float_as_uint(v0), b1 = __float_as_uint(v1);
    hi = __byte_perm(b0, b1, 0x7632);
    float h0 = __uint_as_float(b0 & 0xFFFF0000u);
    float h1 = __uint_as_float(b1 & 0xFFFF0000u);
    __nv_bfloat162 lp = __floats2bfloat162_rn(v0 - h0, v1 - h1);
    lo = *(uint32_t*)&lp;
}

// ---------------------------------------------------------------------------
// fp32 -> (hi, lo) bf16 split (for x and weights)
// ---------------------------------------------------------------------------
__global__ void __launch_bounds__(256) split_bf16_kernel(
    const float* __restrict__ in, __nv_bfloat16* __restrict__ hi,
    __nv_bfloat16* __restrict__ lo, int n4)
{
    int i = blockIdx.x * 256 + threadIdx.x;
    if (i >= n4) return;
    float4 v = ((const float4*)in)[i];
    uint32_t h01, l01, h23, l23;
    pack_split(v.x, v.y, h01, l01);
    pack_split(v.z, v.w, h23, l23);
    ((uint2*)hi)[i] = make_uint2(h01, h23);
    ((uint2*)lo)[i] = make_uint2(l01, l23);
}

// ---------------------------------------------------------------------------
// Split-bf16 tensor-core GEMM: Y[M,N] = A[M,K] @ B[N,K]^T
// mode 1: write (hi, lo) bf16 to Yhi/Ylo in [b, h, t, d] layout
// mode 0: write fp32 to Yf in [m, n] layout
// ---------------------------------------------------------------------------
#define BM 128
#define BN 128
#define BK 32
#define NK (CC / BK)
#define ROWB 80
#define SUBT (128 * ROWB)
#define BUFB (4 * SUBT)
#define GEMM_SMEM (2 * BUFB)  // 81920

__device__ __forceinline__ void load_chunk_async(
    uint32_t sb, int buf, int tid,
    const __nv_bfloat16* __restrict__ Ahi, const __nv_bfloat16* __restrict__ Alo,
    const __nv_bfloat16* __restrict__ Bhi, const __nv_bfloat16* __restrict__ Blo,
    int m0, int n0, int k0)
{
    const uint32_t base = sb + buf * BUFB;
    const __nv_bfloat16* gps[4] = {Ahi, Alo, Bhi, Blo};
    const int rb[4] = {m0, m0, n0, n0};
    #pragma unroll
    for (int it = 0; it < 8; it++) {
        const int sub = it >> 1;
        const int j = (it & 1) * 256 + tid;
        const int row = j >> 2;
        const int c16 = j & 3;
        const uint32_t saddr = base + sub * SUBT + row * ROWB + c16 * 16;
        const void* gaddr = gps[sub] + (size_t)(rb[sub] + row) * CC + k0 + c16 * 8;
        CP_ASYNC16(saddr, gaddr);
    }
}

__global__ void __launch_bounds__(256) gemm_tc_kernel(
    const __nv_bfloat16* __restrict__ Ahi, const __nv_bfloat16* __restrict__ Alo,
    const __nv_bfloat16* __restrict__ Bhi, const __nv_bfloat16* __restrict__ Blo,
    float* __restrict__ Yf, __nv_bfloat16* __restrict__ Yhi,
    __nv_bfloat16* __restrict__ Ylo, int to_heads)
{
    extern __shared__ char smem[];
    const uint32_t sb = smem_u32(smem);
    const int tid = threadIdx.x;
    const int lane = tid & 31;
    const int wid = tid >> 5;
    const int wm = (wid >> 2) * 64;
    const int wn = (wid & 3) * 32;
    const int n0 = blockIdx.x * BN;
    const int m0 = blockIdx.y * BM;

    float acc[4][4][4] = {};

    load_chunk_async(sb, 0, tid, Ahi, Alo, Bhi, Blo, m0, n0, 0);
    CP_COMMIT();

    const int a_row = (lane & 15);
    const int a_koff = (lane >> 4) << 3;
    const int b_row = ((lane >> 4) << 3) + (lane & 7);
    const int b_koff = ((lane >> 3) & 1) << 3;

    for (int c = 0; c < NK; c++) {
        CP_WAIT0();
        __syncthreads();
        if (c + 1 < NK) {
            load_chunk_async(sb, (c + 1) & 1, tid, Ahi, Alo, Bhi, Blo,
                             m0, n0, (c + 1) * BK);
            CP_COMMIT();
        }

        const uint32_t ab = sb + (c & 1) * BUFB;
        const uint32_t bb = ab + 2 * SUBT;

        #pragma unroll
        for (int ks = 0; ks < 2; ks++) {
            uint32_t ah[16], al[16], bh[8], bl[8];
            #pragma unroll
            for (int mt = 0; mt < 4; mt++) {
                const uint32_t off =
                    (uint32_t)((wm + mt * 16 + a_row) * ROWB + (ks * 16 + a_koff) * 2);
                LDSM4(&ah[mt * 4], ab + off);
                LDSM4(&al[mt * 4], ab + SUBT + off);
            }
            #pragma unroll
            for (int nt2 = 0; nt2 < 2; nt2++) {
                const uint32_t off =
                    (uint32_t)((wn + nt2 * 16 + b_row) * ROWB + (ks * 16 + b_koff) * 2);
                LDSM4(&bh[nt2 * 4], bb + off);
                LDSM4(&bl[nt2 * 4], bb + SUBT + off);
            }
            #pragma unroll
            for (int mt = 0; mt < 4; mt++)
                #pragma unroll
                for (int nt = 0; nt < 4; nt++) {
                    float* cc = acc[mt][nt];
                    MMA16816(cc, &ah[mt * 4], &bh[nt * 2]);
                    MMA16816(cc, &ah[mt * 4], &bl[nt * 2]);
                    MMA16816(cc, &al[mt * 4], &bh[nt * 2]);
                }
        }
        __syncthreads();
    }

    // epilogue: registers -> smem staging -> coalesced global stores
    float* es = (float*)smem;   // [128][132]
    const int er = lane >> 2;
    const int ec = (lane & 3) * 2;
    #pragma unroll
    for (int mt = 0; mt < 4; mt++)
        #pragma unroll
        for (int nt = 0; nt < 4; nt++) {
            const int r = wm + mt * 16 + er;
            const int cl = wn + nt * 8 + ec;
            *(float2*)&es[r * 132 + cl] =
                make_float2(acc[mt][nt][0], acc[mt][nt][1]);
            *(float2*)&es[(r + 8) * 132 + cl] =
                make_float2(acc[mt][nt][2], acc[mt][nt][3]);
        }
    __syncthreads();

    #pragma unroll
    for (int it = 0; it < 16; it++) {
        const int i = tid + it * 256;
        const int r = i >> 5;
        const int c4 = (i & 31) * 4;
        float4 v = *(float4*)&es[r * 132 + c4];
        const int m = m0 + r;
        const int n = n0 + c4;
        if (to_heads) {
            const int b = m >> 11, t = m & 2047, h = n >> 6, d = n & 63;
            const size_t idx = (((size_t)(b * HH + h) * TT) + t) * DH + d;
            uint32_t h01, l01, h23, l23;
            pack_split(v.x, v.y, h01, l01);
            pack_split(v.z, v.w, h23, l23);
            *(uint2*)&Yhi[idx] = make_uint2(h01, h23);
            *(uint2*)&Ylo[idx] = make_uint2(l01, l23);
        } else {
            *(float4*)&Yf[(size_t)m * CC + n] = v;
        }
    }
}

// ---------------------------------------------------------------------------
// Tensor-core flash attention (causal). BM=128 Q rows, BKV=64, d=64.
// 256 threads = 8 warps, each warp owns 16 Q rows. Split-bf16 (3 MMA) for
// both QK^T and P.V. Softmax exp on the FMA pipe. Outputs (hi, lo) bf16 in
// [m, c] layout for the output-projection GEMM.
// ---------------------------------------------------------------------------
#define AROW 144
#define SMQH 0
#define SMQL (128 * AROW)            // 18432
#define SMKV (2 * 128 * AROW)        // 36864
#define STAGEB (4 * 64 * AROW)       // 36864
#define KO_KH 0
#define KO_KL (64 * AROW)            // 9216
#define KO_VH (2 * 64 * AROW)
#define KO_VL (3 * 64 * AROW)
#define ATTN_SMEM (SMKV + 2 * STAGEB)  // 110592
#define SCALE_L2E 0.1803368801111763f  // 0.125 * log2(e)

__device__ __forceinline__ void load_kv_stage(
    uint32_t sb, int stage, int tid, size_t gbase, int kv0,
    const __nv_bfloat16* __restrict__ khi, const __nv_bfloat16* __restrict__ klo,
    const __nv_bfloat16* __restrict__ vhi, const __nv_bfloat16* __restrict__ vlo)
{
    const uint32_t base = sb + SMKV + stage * STAGEB;
    const __nv_bfloat16* gps[4] = {khi, klo, vhi, vlo};
    #pragma unroll
    for (int it = 0; it < 8; it++) {
        const int idx = tid + it * 256;         // 0..2047
        const int arr = idx >> 9;               // 0..3
        const int r = (idx >> 3) & 63;
        const int c = idx & 7;
        const uint32_t dst = base + arr * (64 * AROW) + r * AROW + c * 16;
        CP_ASYNC16(dst, gps[arr] + gbase + (size_t)(kv0 + r) * DH + c * 8);
    }
}

__global__ void __launch_bounds__(256, 1) flash_attn_tc_kernel(
    const __nv_bfloat16* __restrict__ qhi, const __nv_bfloat16* __restrict__ qlo,
    const __nv_bfloat16* __restrict__ khi, const __nv_bfloat16* __restrict__ klo,
    const __nv_bfloat16* __restrict__ vhi, const __nv_bfloat16* __restrict__ vlo,
    __nv_bfloat16* __restrict__ Ohi, __nv_bfloat16* __restrict__ Olo)
{
    extern __shared__ char smem[];
    const uint32_t sb = smem_u32(smem);
    const int tid = threadIdx.x;
    const int lane = tid & 31;
    const int wid = tid >> 5;
    const int wm = wid * 16;
    const int qi = 15 - (int)blockIdx.x;     // heavy tiles first
    const int bh = blockIdx.y;
    const int q0 = qi * 128;
    const size_t gbase = (size_t)bh * TT * DH;

    // ldmatrix lane offsets
    const int a_row = lane & 15;
    const int a_koff = (lane >> 4) << 3;
    const int b_row = ((lane >> 4) << 3) + (lane & 7);
    const int b_koff = ((lane >> 3) & 1) << 3;
    const int v_krow = (lane & 7) + (((lane >> 3) & 1) << 3);
    const int v_noff = (lane >> 4) << 3;

    // group 0: Q tile + KV stage 0
    #pragma unroll
    for (int it = 0; it < 8; it++) {
        const int idx = tid + it * 256;      // 0..2047
        const int r = (idx >> 3) & 127;
        const int c = idx & 7;
        const int isLo = idx >> 10;
        const uint32_t dst = sb + (isLo ? SMQL : SMQH) + r * AROW + c * 16;
        const __nv_bfloat16* src = isLo ? qlo : qhi;
        CP_ASYNC16(dst, src + gbase + (size_t)(q0 + r) * DH + c * 8);
    }
    load_kv_stage(sb, 0, tid, gbase, 0, khi, klo, vhi, vlo);
    CP_COMMIT();

    const int nkv = 2 * qi + 2;
    float m0 = -1e30f, m1 = -1e30f, l0 = 0.0f, l1 = 0.0f;
    float oacc[8][4] = {};
    const int r0 = lane >> 2;          // row in warp tile (and +8)
    const int cb = (lane & 3) * 2;

    for (int j = 0; j < nkv; j++) {
        if (j + 1 < nkv) {
            load_kv_stage(sb, (j + 1) & 1, tid, gbase, (j + 1) * 64,
                          khi, klo, vhi, vlo);
            CP_COMMIT();
            CP_WAIT1();
        } else {
            CP_WAIT0();
        }
        __syncthreads();

        const uint32_t kvb = sb + SMKV + (j & 1) * STAGEB;

        // ---- S = Q K^T (3-split) ----
        float sacc[8][4] = {};
        #pragma unroll
        for (int ks = 0; ks < 4; ks++) {
            uint32_t ah[4], al[4];
            const uint32_t aoff =
                (uint32_t)((wm + a_row) * AROW + (ks * 16 + a_koff) * 2);
            LDSM4(ah, sb + SMQH + aoff);
            LDSM4(al, sb + SMQL + aoff);
            #pragma unroll
            for (int ng = 0; ng < 4; ng++) {
                uint32_t bhf[4], blf[4];
                const uint32_t boff =
                    (uint32_t)((ng * 16 + b_row) * AROW + (ks * 16 + b_koff) * 2);
                LDSM4(bhf, kvb + KO_KH + boff);
                LDSM4(blf, kvb + KO_KL + boff);
                float* s0 = sacc[2 * ng];
                float* s1 = sacc[2 * ng + 1];
                MMA16816(s0, ah, &bhf[0]);
                MMA16816(s0, ah, &blf[0]);
                MMA16816(s0, al, &bhf[0]);
                MMA16816(s1, ah, &bhf[2]);
                MMA16816(s1, ah, &blf[2]);
                MMA16816(s1, al, &bhf[2]);
            }
        }

        // ---- scale (log2 domain) + causal mask ----
        const int kv0 = j * 64;
        const bool needmask = (kv0 + 63 > q0 + wm);
        const int tq0 = q0 + wm + r0;
        #pragma unroll
        for (int nt = 0; nt < 8; nt++) {
            #pragma unroll
            for (int e = 0; e < 4; e++) {
                float z = sacc[nt][e] * SCALE_L2E;
                if (needmask) {
                    const int tk = kv0 + nt * 8 + cb + (e & 1);
                    const int tq = tq0 + ((e >> 1) << 3);
                    if (tk > tq) z = -1e30f;
                }
                sacc[nt][e] = z;
            }
        }

        // ---- online softmax (quad-reduced row stats) ----
        float zm0 = -1e30f, zm1 = -1e30f;
        #pragma unroll
        for (int nt = 0; nt < 8; nt++) {
            zm0 = fmaxf(zm0, fmaxf(sacc[nt][0], sacc[nt][1]));
            zm1 = fmaxf(zm1, fmaxf(sacc[nt][2], sacc[nt][3]));
        }
        zm0 = fmaxf(zm0, __shfl_xor_sync(0xffffffffu, zm0, 1));
        zm0 = fmaxf(zm0, __shfl_xor_sync(0xffffffffu, zm0, 2));
        zm1 = fmaxf(zm1, __shfl_xor_sync(0xffffffffu, zm1, 1));
        zm1 = fmaxf(zm1, __shfl_xor_sync(0xffffffffu, zm1, 2));
        const float mn0 = fmaxf(m0, zm0);
        const float mn1 = fmaxf(m1, zm1);
        const float rs0 = fexp2(m0 - mn0);
        const float rs1 = fexp2(m1 - mn1);
        float sum0 = 0.0f, sum1 = 0.0f;
        #pragma unroll
        for (int nt = 0; nt < 8; nt++) {
            float p0 = fexp2(sacc[nt][0] - mn0);
            float p1 = fexp2(sacc[nt][1] - mn0);
            float p2 = fexp2(sacc[nt][2] - mn1);
            float p3 = fexp2(sacc[nt][3] - mn1);
            sacc[nt][0] = p0; sacc[nt][1] = p1;
            sacc[nt][2] = p2; sacc[nt][3] = p3;
            sum0 += p0 + p1;
            sum1 += p2 + p3;
        }
        sum0 += __shfl_xor_sync(0xffffffffu, sum0, 1);
        sum0 += __shfl_xor_sync(0xffffffffu, sum0, 2);
        sum1 += __shfl_xor_sync(0xffffffffu, sum1, 1);
        sum1 += __shfl_xor_sync(0xffffffffu, sum1, 2);
        l0 = l0 * rs0 + sum0;
        l1 = l1 * rs1 + sum1;
        m0 = mn0;
        m1 = mn1;

        // ---- rescale O ----
        #pragma unroll
        for (int nt = 0; nt < 8; nt++) {
            oacc[nt][0] *= rs0;
            oacc[nt][1] *= rs0;
            oacc[nt][2] *= rs1;
            oacc[nt][3] *= rs1;
        }

        // ---- pack P into split A-fragments ----
        uint32_t pah[4][4], pal[4][4];
        #pragma unroll
        for (int kt = 0; kt < 4; kt++) {
            pack_split(sacc[2 * kt][0],     sacc[2 * kt][1],     pah[kt][0], pal[kt][0]);
            pack_split(sacc[2 * kt][2],     sacc[2 * kt][3],     pah[kt][1], pal[kt][1]);
            pack_split(sacc[2 * kt + 1][0], sacc[2 * kt + 1][1], pah[kt][2], pal[kt][2]);
            pack_split(sacc[2 * kt + 1][2], sacc[2 * kt + 1][3], pah[kt][3], pal[kt][3]);
        }

        // ---- O += P V (3-split), V via ldmatrix.trans ----
        #pragma unroll
        for (int ks = 0; ks < 4; ks++) {
            #pragma unroll
            for (int ng = 0; ng < 4; ng++) {
                uint32_t vhf[4], vlf[4];
                const uint32_t voff =
                    (uint32_t)((ks * 16 + v_krow) * AROW + (ng * 16 + v_noff) * 2);
                LDSM4T(vhf, kvb + KO_VH + voff);
                LDSM4T(vlf, kvb + KO_VL + voff);
                float* o0 = oacc[2 * ng];
                float* o1 = oacc[2 * ng + 1];
                MMA16816(o0, pah[ks], &vhf[0]);
                MMA16816(o0, pah[ks], &vlf[0]);
                MMA16816(o0, pal[ks], &vhf[0]);
                MMA16816(o1, pah[ks], &vhf[2]);
                MMA16816(o1, pah[ks], &vlf[2]);
                MMA16816(o1, pal[ks], &vhf[2]);
            }
        }
        __syncthreads();
    }

    // ---- epilogue: normalize, split to (hi, lo) bf16, write [m, c] ----
    const float inv0 = 1.0f / l0;
    const float inv1 = 1.0f / l1;
    const int b = bh >> 4;
    const int h = bh & 15;
    const int trow0 = q0 + wm + r0;
    const int trow1 = trow0 + 8;
    #pragma unroll
    for (int nt = 0; nt < 8; nt++) {
        const int col = h * DH + nt * 8 + cb;
        uint32_t hp, lp;
        pack_split(oacc[nt][0] * inv0, oacc[nt][1] * inv0, hp, lp);
        const size_t idx0 = ((size_t)b * TT + trow0) * CC + col;
        *(uint32_t*)&Ohi[idx0] = hp;
        *(uint32_t*)&Olo[idx0] = lp;
        pack_split(oacc[nt][2] * inv1, oacc[nt][3] * inv1, hp, lp);
        const size_t idx1 = ((size_t)b * TT + trow1) * CC + col;
        *(uint32_t*)&Ohi[idx1] = hp;
        *(uint32_t*)&Olo[idx1] = lp;
    }
}

// ---------------------------------------------------------------------------
// Launch
// ---------------------------------------------------------------------------
extern "C" void kernel_launch(void* const* d_in, const int* in_sizes, int n_in,
                              void* d_out, int out_size)
{
    const float* x   = (const float*)d_in[0];
    const float* W_Q = (const float*)d_in[1];
    const float* W_K = (const float*)d_in[2];
    const float* W_V = (const float*)d_in[3];
    const float* W_O = (const float*)d_in[4];
    float* out = (float*)d_out;

    __nv_bfloat16 *xhi, *xlo, *whi, *wlo;
    __nv_bfloat16 *qh, *ql, *kh, *kl, *vh, *vl, *ah, *al;
    cudaGetSymbolAddress((void**)&xhi, g_xhi);
    cudaGetSymbolAddress((void**)&xlo, g_xlo);
    cudaGetSymbolAddress((void**)&whi, g_whi);
    cudaGetSymbolAddress((void**)&wlo, g_wlo);
    cudaGetSymbolAddress((void**)&qh, g_qhi);
    cudaGetSymbolAddress((void**)&ql, g_qlo);
    cudaGetSymbolAddress((void**)&kh, g_khi);
    cudaGetSymbolAddress((void**)&kl, g_klo);
    cudaGetSymbolAddress((void**)&vh, g_vhi);
    cudaGetSymbolAddress((void**)&vl, g_vlo);
    cudaGetSymbolAddress((void**)&ah, g_ahi);
    cudaGetSymbolAddress((void**)&al, g_alo);

    cudaFuncSetAttribute(gemm_tc_kernel,
                         cudaFuncAttributeMaxDynamicSharedMemorySize, GEMM_SMEM);
    cudaFuncSetAttribute(flash_attn_tc_kernel,
                         cudaFuncAttributeMaxDynamicSharedMemorySize, ATTN_SMEM);

    const size_t WSZ = (size_t)CC * CC;
    const int nx4 = (MM * CC) / 4;
    const int nw4 = (CC * CC) / 4;

    split_bf16_kernel<<<(nx4 + 255) / 256, 256>>>(x, xhi, xlo, nx4);
    const float* Ws[4] = {W_Q, W_K, W_V, W_O};
    for (int i = 0; i < 4; i++)
        split_bf16_kernel<<<(nw4 + 255) / 256, 256>>>(Ws[i], whi + i * WSZ, wlo + i * WSZ, nw4);

    dim3 gemm_grid(CC / BN, MM / BM);   // (8, 64)
    gemm_tc_kernel<<<gemm_grid, 256, GEMM_SMEM>>>(
        xhi, xlo, whi + 0 * WSZ, wlo + 0 * WSZ, nullptr, qh, ql, 1);
    gemm_tc_kernel<<<gemm_grid, 256, GEMM_SMEM>>>(
        xhi, xlo, whi + 1 * WSZ, wlo + 1 * WSZ, nullptr, kh, kl, 1);
    gemm_tc_kernel<<<gemm_grid, 256, GEMM_SMEM>>>(
        xhi, xlo, whi + 2 * WSZ, wlo + 2 * WSZ, nullptr, vh, vl, 1);

    dim3 attn_grid(TT / 128, BB * HH);  // (16, 64)
    flash_attn_tc_kernel<<<attn_grid, 256, ATTN_SMEM>>>(
        qh, ql, kh, kl, vh, vl, ah, al);

    gemm_tc_kernel<<<gemm_grid, 256, GEMM_SMEM>>>(
        ah, al, whi + 3 * WSZ, wlo + 3 * WSZ, out, nullptr, nullptr, 0);
}

// round 5
// speedup vs baseline: 3.6810x; 1.2038x over previous
#include <cuda_runtime.h>
#include <cuda_fp16.h>
#include <cstdint>

// Problem constants
#define BB 4
#define TT 2048
#define HH 16
#define DH 64
#define CC 1024
#define MM (BB * TT)   // 8192 rows

// ---------------------------------------------------------------------------
// Scratch (device globals -- allocation-free per harness rules)
// ---------------------------------------------------------------------------
static __device__ __align__(16) __half g_xhi[(size_t)MM * CC];
static __device__ __align__(16) __half g_xlo[(size_t)MM * CC];
static __device__ __align__(16) __half g_wh[4][(size_t)CC * CC];
static __device__ __align__(16) __half g_qhi[(size_t)MM * CC];
static __device__ __align__(16) __half g_qlo[(size_t)MM * CC];
static __device__ __align__(16) __half g_khi[(size_t)MM * CC];
static __device__ __align__(16) __half g_klo[(size_t)MM * CC];
static __device__ __align__(16) __half g_vhi[(size_t)MM * CC];
static __device__ __align__(16) __half g_vlo[(size_t)MM * CC];
static __device__ __align__(16) __half g_ahi[(size_t)MM * CC];
static __device__ __align__(16) __half g_alo[(size_t)MM * CC];

// ---------------------------------------------------------------------------
// PTX helpers (sm_80+ portable -- compute_103 safe)
// ---------------------------------------------------------------------------
__device__ __forceinline__ uint32_t smem_u32(const void* p) {
    uint32_t a;
    asm("{ .reg .u64 t; cvta.to.shared.u64 t, %1; cvt.u32.u64 %0, t; }"
        : "=r"(a) : "l"(p));
    return a;
}

#define CP_ASYNC16(saddr, gaddr) \
    asm volatile("cp.async.cg.shared.global [%0], [%1], 16;" \
                 :: "r"(saddr), "l"(gaddr))
#define CP_COMMIT() asm volatile("cp.async.commit_group;" ::: "memory")
#define CP_WAIT0()  asm volatile("cp.async.wait_group 0;" ::: "memory")
#define CP_WAIT1()  asm volatile("cp.async.wait_group 1;" ::: "memory")

#define LDSM4(r, addr)                                                          \
    asm volatile("ldmatrix.sync.aligned.m8n8.x4.shared.b16 {%0,%1,%2,%3}, [%4];"\
                 : "=r"((r)[0]), "=r"((r)[1]), "=r"((r)[2]), "=r"((r)[3])       \
                 : "r"(addr))

#define LDSM4T(r, addr)                                                         \
    asm volatile("ldmatrix.sync.aligned.m8n8.x4.trans.shared.b16 {%0,%1,%2,%3}, [%4];" \
                 : "=r"((r)[0]), "=r"((r)[1]), "=r"((r)[2]), "=r"((r)[3])       \
                 : "r"(addr))

#define MMA16816(c, a, b)                                                       \
    asm volatile("mma.sync.aligned.m16n8k16.row.col.f32.f16.f16.f32 "           \
                 "{%0,%1,%2,%3}, {%4,%5,%6,%7}, {%8,%9}, {%0,%1,%2,%3};"        \
                 : "+f"((c)[0]), "+f"((c)[1]), "+f"((c)[2]), "+f"((c)[3])       \
                 : "r"((a)[0]), "r"((a)[1]), "r"((a)[2]), "r"((a)[3]),          \
                   "r"((b)[0]), "r"((b)[1]))

// exp2(y) for y <= 0, FMA/ALU pipes only (no MUFU). |rel err| ~2e-6.
__device__ __forceinline__ float fexp2(float y) {
    y = fmaxf(y, -126.0f);
    float t = __fadd_rn(y, 12582912.0f);
    int   e = __float_as_int(t) << 23;
    float f = __fsub_rn(y, __fsub_rn(t, 12582912.0f));
    float p =              1.3333558146e-3f;
    p = fmaf(p, f, 9.6181291077e-3f);
    p = fmaf(p, f, 5.5504108664e-2f);
    p = fmaf(p, f, 2.4022650696e-1f);
    p = fmaf(p, f, 6.9314718056e-1f);
    p = fmaf(p, f, 1.0f);
    return __uint_as_float((uint32_t)(__float_as_int(p) + e));
}

// fp32 pair -> packed fp16 hi pair (RN) + fp16 lo pair (residual, RN)
__device__ __forceinline__ void pack_split_h(float v0, float v1,
                                             uint32_t& hi, uint32_t& lo) {
    __half2 h = __floats2half2_rn(v0, v1);
    hi = *(uint32_t*)&h;
    float h0 = __half2float(__low2half(h));
    float h1 = __half2float(__high2half(h));
    __half2 l = __floats2half2_rn(v0 - h0, v1 - h1);
    lo = *(uint32_t*)&l;
}

// ---------------------------------------------------------------------------
// fp32 -> (hi, lo) fp16 split with optional prescale; lo write optional
// ---------------------------------------------------------------------------
__global__ void __launch_bounds__(256) split_h_kernel(
    const float* __restrict__ in, __half* __restrict__ hi,
    __half* __restrict__ lo, float prescale, int write_lo, int n4)
{
    int i = blockIdx.x * 256 + threadIdx.x;
    if (i >= n4) return;
    float4 v = ((const float4*)in)[i];
    v.x *= prescale; v.y *= prescale; v.z *= prescale; v.w *= prescale;
    uint32_t h01, l01, h23, l23;
    pack_split_h(v.x, v.y, h01, l01);
    pack_split_h(v.z, v.w, h23, l23);
    ((uint2*)hi)[i] = make_uint2(h01, h23);
    if (write_lo) ((uint2*)lo)[i] = make_uint2(l01, l23);
}

// ---------------------------------------------------------------------------
// 2-product fp16 tensor-core GEMM: Y[M,N] = (Ahi+Alo)[M,K] @ Bh[N,K]^T * 1/32
// A split (hi+lo fp16), B single fp16 (weights pre-scaled x32).
// mode 1: write (hi, lo) fp16 to Yhi/Ylo in [b, h, t, d] layout
// mode 0: write fp32 to Yf in [m, n] layout
// ---------------------------------------------------------------------------
#define BM 128
#define BN 128
#define BK 32
#define NK (CC / BK)
#define ROWB 80
#define SUBT (128 * ROWB)       // 10240
#define BUFB (3 * SUBT)         // 30720 (Ahi, Alo, Bh)
#define GEMM_SMEM 67584         // max(2*BUFB=61440, epilogue 128*132*4)
#define INV32 0.03125f

__device__ __forceinline__ void load_chunk_async(
    uint32_t sb, int buf, int tid,
    const __half* __restrict__ Ahi, const __half* __restrict__ Alo,
    const __half* __restrict__ Bh, int m0, int n0, int k0)
{
    const uint32_t base = sb + buf * BUFB;
    const __half* gps[3] = {Ahi, Alo, Bh};
    const int rb[3] = {m0, m0, n0};
    #pragma unroll
    for (int it = 0; it < 6; it++) {
        const int sub = it >> 1;
        const int j = (it & 1) * 256 + tid;
        const int row = j >> 2;
        const int c16 = j & 3;
        const uint32_t saddr = base + sub * SUBT + row * ROWB + c16 * 16;
        const void* gaddr = gps[sub] + (size_t)(rb[sub] + row) * CC + k0 + c16 * 8;
        CP_ASYNC16(saddr, gaddr);
    }
}

__global__ void __launch_bounds__(256) gemm_tc_kernel(
    const __half* __restrict__ Ahi, const __half* __restrict__ Alo,
    const __half* __restrict__ Bh,
    float* __restrict__ Yf, __half* __restrict__ Yhi,
    __half* __restrict__ Ylo, int to_heads)
{
    extern __shared__ char smem[];
    const uint32_t sb = smem_u32(smem);
    const int tid = threadIdx.x;
    const int lane = tid & 31;
    const int wid = tid >> 5;
    const int wm = (wid >> 2) * 64;
    const int wn = (wid & 3) * 32;
    const int n0 = blockIdx.x * BN;
    const int m0 = blockIdx.y * BM;

    float acc[4][4][4] = {};

    load_chunk_async(sb, 0, tid, Ahi, Alo, Bh, m0, n0, 0);
    CP_COMMIT();

    const int a_row = (lane & 15);
    const int a_koff = (lane >> 4) << 3;
    const int b_row = ((lane >> 4) << 3) + (lane & 7);
    const int b_koff = ((lane >> 3) & 1) << 3;

    for (int c = 0; c < NK; c++) {
        CP_WAIT0();
        __syncthreads();
        if (c + 1 < NK) {
            load_chunk_async(sb, (c + 1) & 1, tid, Ahi, Alo, Bh,
                             m0, n0, (c + 1) * BK);
            CP_COMMIT();
        }

        const uint32_t ab = sb + (c & 1) * BUFB;
        const uint32_t bb = ab + 2 * SUBT;

        #pragma unroll
        for (int ks = 0; ks < 2; ks++) {
            uint32_t ah[16], al[16], bh[8];
            #pragma unroll
            for (int mt = 0; mt < 4; mt++) {
                const uint32_t off =
                    (uint32_t)((wm + mt * 16 + a_row) * ROWB + (ks * 16 + a_koff) * 2);
                LDSM4(&ah[mt * 4], ab + off);
                LDSM4(&al[mt * 4], ab + SUBT + off);
            }
            #pragma unroll
            for (int nt2 = 0; nt2 < 2; nt2++) {
                const uint32_t off =
                    (uint32_t)((wn + nt2 * 16 + b_row) * ROWB + (ks * 16 + b_koff) * 2);
                LDSM4(&bh[nt2 * 4], bb + off);
            }
            #pragma unroll
            for (int mt = 0; mt < 4; mt++)
                #pragma unroll
                for (int nt = 0; nt < 4; nt++) {
                    float* cc = acc[mt][nt];
                    MMA16816(cc, &ah[mt * 4], &bh[nt * 2]);
                    MMA16816(cc, &al[mt * 4], &bh[nt * 2]);
                }
        }
        __syncthreads();
    }

    // epilogue: registers (x 1/32) -> smem staging -> coalesced global stores
    float* es = (float*)smem;   // [128][132]
    const int er = lane >> 2;
    const int ec = (lane & 3) * 2;
    #pragma unroll
    for (int mt = 0; mt < 4; mt++)
        #pragma unroll
        for (int nt = 0; nt < 4; nt++) {
            const int r = wm + mt * 16 + er;
            const int cl = wn + nt * 8 + ec;
            *(float2*)&es[r * 132 + cl] =
                make_float2(acc[mt][nt][0] * INV32, acc[mt][nt][1] * INV32);
            *(float2*)&es[(r + 8) * 132 + cl] =
                make_float2(acc[mt][nt][2] * INV32, acc[mt][nt][3] * INV32);
        }
    __syncthreads();

    #pragma unroll
    for (int it = 0; it < 16; it++) {
        const int i = tid + it * 256;
        const int r = i >> 5;
        const int c4 = (i & 31) * 4;
        float4 v = *(float4*)&es[r * 132 + c4];
        const int m = m0 + r;
        const int n = n0 + c4;
        if (to_heads) {
            const int b = m >> 11, t = m & 2047, h = n >> 6, d = n & 63;
            const size_t idx = (((size_t)(b * HH + h) * TT) + t) * DH + d;
            uint32_t h01, l01, h23, l23;
            pack_split_h(v.x, v.y, h01, l01);
            pack_split_h(v.z, v.w, h23, l23);
            *(uint2*)&Yhi[idx] = make_uint2(h01, h23);
            *(uint2*)&Ylo[idx] = make_uint2(l01, l23);
        } else {
            *(float4*)&Yf[(size_t)m * CC + n] = v;
        }
    }
}

// ---------------------------------------------------------------------------
// Tensor-core flash attention (causal), fp16 3-product (error ~2^-22).
// BM=128 Q rows, BKV=64, d=64. 256 threads = 8 warps, warp owns 16 Q rows.
// Softmax exp on the FMA pipe. Outputs (hi, lo) fp16 in [m, c] layout.
// ---------------------------------------------------------------------------
#define AROW 144
#define SMQH 0
#define SMQL (128 * AROW)            // 18432
#define SMKV (2 * 128 * AROW)        // 36864
#define STAGEB (4 * 64 * AROW)       // 36864
#define KO_KH 0
#define KO_KL (64 * AROW)            // 9216
#define KO_VH (2 * 64 * AROW)
#define KO_VL (3 * 64 * AROW)
#define ATTN_SMEM (SMKV + 2 * STAGEB)  // 110592
#define SCALE_L2E 0.1803368801111763f  // 0.125 * log2(e)

__device__ __forceinline__ void load_kv_stage(
    uint32_t sb, int stage, int tid, size_t gbase, int kv0,
    const __half* __restrict__ khi, const __half* __restrict__ klo,
    const __half* __restrict__ vhi, const __half* __restrict__ vlo)
{
    const uint32_t base = sb + SMKV + stage * STAGEB;
    const __half* gps[4] = {khi, klo, vhi, vlo};
    #pragma unroll
    for (int it = 0; it < 8; it++) {
        const int idx = tid + it * 256;         // 0..2047
        const int arr = idx >> 9;               // 0..3
        const int r = (idx >> 3) & 63;
        const int c = idx & 7;
        const uint32_t dst = base + arr * (64 * AROW) + r * AROW + c * 16;
        CP_ASYNC16(dst, gps[arr] + gbase + (size_t)(kv0 + r) * DH + c * 8);
    }
}

__global__ void __launch_bounds__(256, 1) flash_attn_tc_kernel(
    const __half* __restrict__ qhi, const __half* __restrict__ qlo,
    const __half* __restrict__ khi, const __half* __restrict__ klo,
    const __half* __restrict__ vhi, const __half* __restrict__ vlo,
    __half* __restrict__ Ohi, __half* __restrict__ Olo)
{
    extern __shared__ char smem[];
    const uint32_t sb = smem_u32(smem);
    const int tid = threadIdx.x;
    const int lane = tid & 31;
    const int wid = tid >> 5;
    const int wm = wid * 16;
    const int qi = 15 - (int)blockIdx.x;     // heavy tiles first
    const int bh = blockIdx.y;
    const int q0 = qi * 128;
    const size_t gbase = (size_t)bh * TT * DH;

    // ldmatrix lane offsets
    const int a_row = lane & 15;
    const int a_koff = (lane >> 4) << 3;
    const int b_row = ((lane >> 4) << 3) + (lane & 7);
    const int b_koff = ((lane >> 3) & 1) << 3;
    const int v_krow = (lane & 7) + (((lane >> 3) & 1) << 3);
    const int v_noff = (lane >> 4) << 3;

    // group 0: Q tile + KV stage 0
    #pragma unroll
    for (int it = 0; it < 8; it++) {
        const int idx = tid + it * 256;      // 0..2047
        const int r = (idx >> 3) & 127;
        const int c = idx & 7;
        const int isLo = idx >> 10;
        const uint32_t dst = sb + (isLo ? SMQL : SMQH) + r * AROW + c * 16;
        const __half* src = isLo ? qlo : qhi;
        CP_ASYNC16(dst, src + gbase + (size_t)(q0 + r) * DH + c * 8);
    }
    load_kv_stage(sb, 0, tid, gbase, 0, khi, klo, vhi, vlo);
    CP_COMMIT();

    const int nkv = 2 * qi + 2;
    float m0 = -1e30f, m1 = -1e30f, l0 = 0.0f, l1 = 0.0f;
    float oacc[8][4] = {};
    const int r0 = lane >> 2;
    const int cb = (lane & 3) * 2;

    for (int j = 0; j < nkv; j++) {
        if (j + 1 < nkv) {
            load_kv_stage(sb, (j + 1) & 1, tid, gbase, (j + 1) * 64,
                          khi, klo, vhi, vlo);
            CP_COMMIT();
            CP_WAIT1();
        } else {
            CP_WAIT0();
        }
        __syncthreads();

        const uint32_t kvb = sb + SMKV + (j & 1) * STAGEB;

        // ---- S = Q K^T (3-product) ----
        float sacc[8][4] = {};
        #pragma unroll
        for (int ks = 0; ks < 4; ks++) {
            uint32_t ah[4], al[4];
            const uint32_t aoff =
                (uint32_t)((wm + a_row) * AROW + (ks * 16 + a_koff) * 2);
            LDSM4(ah, sb + SMQH + aoff);
            LDSM4(al, sb + SMQL + aoff);
            #pragma unroll
            for (int ng = 0; ng < 4; ng++) {
                uint32_t bhf[4], blf[4];
                const uint32_t boff =
                    (uint32_t)((ng * 16 + b_row) * AROW + (ks * 16 + b_koff) * 2);
                LDSM4(bhf, kvb + KO_KH + boff);
                LDSM4(blf, kvb + KO_KL + boff);
                float* s0 = sacc[2 * ng];
                float* s1 = sacc[2 * ng + 1];
                MMA16816(s0, ah, &bhf[0]);
                MMA16816(s0, ah, &blf[0]);
                MMA16816(s0, al, &bhf[0]);
                MMA16816(s1, ah, &bhf[2]);
                MMA16816(s1, ah, &blf[2]);
                MMA16816(s1, al, &bhf[2]);
            }
        }

        // ---- scale (log2 domain) + causal mask ----
        const int kv0 = j * 64;
        const bool needmask = (kv0 + 63 > q0 + wm);
        const int tq0 = q0 + wm + r0;
        #pragma unroll
        for (int nt = 0; nt < 8; nt++) {
            #pragma unroll
            for (int e = 0; e < 4; e++) {
                float z = sacc[nt][e] * SCALE_L2E;
                if (needmask) {
                    const int tk = kv0 + nt * 8 + cb + (e & 1);
                    const int tq = tq0 + ((e >> 1) << 3);
                    if (tk > tq) z = -1e30f;
                }
                sacc[nt][e] = z;
            }
        }

        // ---- online softmax (quad-reduced row stats) ----
        float zm0 = -1e30f, zm1 = -1e30f;
        #pragma unroll
        for (int nt = 0; nt < 8; nt++) {
            zm0 = fmaxf(zm0, fmaxf(sacc[nt][0], sacc[nt][1]));
            zm1 = fmaxf(zm1, fmaxf(sacc[nt][2], sacc[nt][3]));
        }
        zm0 = fmaxf(zm0, __shfl_xor_sync(0xffffffffu, zm0, 1));
        zm0 = fmaxf(zm0, __shfl_xor_sync(0xffffffffu, zm0, 2));
        zm1 = fmaxf(zm1, __shfl_xor_sync(0xffffffffu, zm1, 1));
        zm1 = fmaxf(zm1, __shfl_xor_sync(0xffffffffu, zm1, 2));
        const float mn0 = fmaxf(m0, zm0);
        const float mn1 = fmaxf(m1, zm1);
        const float rs0 = fexp2(m0 - mn0);
        const float rs1 = fexp2(m1 - mn1);
        float sum0 = 0.0f, sum1 = 0.0f;
        #pragma unroll
        for (int nt = 0; nt < 8; nt++) {
            float p0 = fexp2(sacc[nt][0] - mn0);
            float p1 = fexp2(sacc[nt][1] - mn0);
            float p2 = fexp2(sacc[nt][2] - mn1);
            float p3 = fexp2(sacc[nt][3] - mn1);
            sacc[nt][0] = p0; sacc[nt][1] = p1;
            sacc[nt][2] = p2; sacc[nt][3] = p3;
            sum0 += p0 + p1;
            sum1 += p2 + p3;
        }
        sum0 += __shfl_xor_sync(0xffffffffu, sum0, 1);
        sum0 += __shfl_xor_sync(0xffffffffu, sum0, 2);
        sum1 += __shfl_xor_sync(0xffffffffu, sum1, 1);
        sum1 += __shfl_xor_sync(0xffffffffu, sum1, 2);
        l0 = l0 * rs0 + sum0;
        l1 = l1 * rs1 + sum1;
        m0 = mn0;
        m1 = mn1;

        // ---- rescale O ----
        #pragma unroll
        for (int nt = 0; nt < 8; nt++) {
            oacc[nt][0] *= rs0;
            oacc[nt][1] *= rs0;
            oacc[nt][2] *= rs1;
            oacc[nt][3] *= rs1;
        }

        // ---- pack P into split A-fragments ----
        uint32_t pah[4][4], pal[4][4];
        #pragma unroll
        for (int kt = 0; kt < 4; kt++) {
            pack_split_h(sacc[2 * kt][0],     sacc[2 * kt][1],     pah[kt][0], pal[kt][0]);
            pack_split_h(sacc[2 * kt][2],     sacc[2 * kt][3],     pah[kt][1], pal[kt][1]);
            pack_split_h(sacc[2 * kt + 1][0], sacc[2 * kt + 1][1], pah[kt][2], pal[kt][2]);
            pack_split_h(sacc[2 * kt + 1][2], sacc[2 * kt + 1][3], pah[kt][3], pal[kt][3]);
        }

        // ---- O += P V (3-product), V via ldmatrix.trans ----
        #pragma unroll
        for (int ks = 0; ks < 4; ks++) {
            #pragma unroll
            for (int ng = 0; ng < 4; ng++) {
                uint32_t vhf[4], vlf[4];
                const uint32_t voff =
                    (uint32_t)((ks * 16 + v_krow) * AROW + (ng * 16 + v_noff) * 2);
                LDSM4T(vhf, kvb + KO_VH + voff);
                LDSM4T(vlf, kvb + KO_VL + voff);
                float* o0 = oacc[2 * ng];
                float* o1 = oacc[2 * ng + 1];
                MMA16816(o0, pah[ks], &vhf[0]);
                MMA16816(o0, pah[ks], &vlf[0]);
                MMA16816(o0, pal[ks], &vhf[0]);
                MMA16816(o1, pah[ks], &vhf[2]);
                MMA16816(o1, pah[ks], &vlf[2]);
                MMA16816(o1, pal[ks], &vhf[2]);
            }
        }
        __syncthreads();
    }

    // ---- epilogue: normalize, split to (hi, lo) fp16, write [m, c] ----
    const float inv0 = 1.0f / l0;
    const float inv1 = 1.0f / l1;
    const int b = bh >> 4;
    const int h = bh & 15;
    const int trow0 = q0 + wm + r0;
    const int trow1 = trow0 + 8;
    #pragma unroll
    for (int nt = 0; nt < 8; nt++) {
        const int col = h * DH + nt * 8 + cb;
        uint32_t hp, lp;
        pack_split_h(oacc[nt][0] * inv0, oacc[nt][1] * inv0, hp, lp);
        const size_t idx0 = ((size_t)b * TT + trow0) * CC + col;
        *(uint32_t*)&Ohi[idx0] = hp;
        *(uint32_t*)&Olo[idx0] = lp;
        pack_split_h(oacc[nt][2] * inv1, oacc[nt][3] * inv1, hp, lp);
        const size_t idx1 = ((size_t)b * TT + trow1) * CC + col;
        *(uint32_t*)&Ohi[idx1] = hp;
        *(uint32_t*)&Olo[idx1] = lp;
    }
}

// ---------------------------------------------------------------------------
// Launch
// ---------------------------------------------------------------------------
extern "C" void kernel_launch(void* const* d_in, const int* in_sizes, int n_in,
                              void* d_out, int out_size)
{
    const float* x   = (const float*)d_in[0];
    const float* W_Q = (const float*)d_in[1];
    const float* W_K = (const float*)d_in[2];
    const float* W_V = (const float*)d_in[3];
    const float* W_O = (const float*)d_in[4];
    float* out = (float*)d_out;

    __half *xhi, *xlo, *wh;
    __half *qh, *ql, *kh, *kl, *vh, *vl, *ah, *al;
    cudaGetSymbolAddress((void**)&xhi, g_xhi);
    cudaGetSymbolAddress((void**)&xlo, g_xlo);
    cudaGetSymbolAddress((void**)&wh, g_wh);
    cudaGetSymbolAddress((void**)&qh, g_qhi);
    cudaGetSymbolAddress((void**)&ql, g_qlo);
    cudaGetSymbolAddress((void**)&kh, g_khi);
    cudaGetSymbolAddress((void**)&kl, g_klo);
    cudaGetSymbolAddress((void**)&vh, g_vhi);
    cudaGetSymbolAddress((void**)&vl, g_vlo);
    cudaGetSymbolAddress((void**)&ah, g_ahi);
    cudaGetSymbolAddress((void**)&al, g_alo);

    cudaFuncSetAttribute(gemm_tc_kernel,
                         cudaFuncAttributeMaxDynamicSharedMemorySize, GEMM_SMEM);
    cudaFuncSetAttribute(flash_attn_tc_kernel,
                         cudaFuncAttributeMaxDynamicSharedMemorySize, ATTN_SMEM);

    const size_t WSZ = (size_t)CC * CC;
    const int nx4 = (MM * CC) / 4;
    const int nw4 = (CC * CC) / 4;

    // x: split (hi+lo). Weights: hi only, pre-scaled by 32 (epilogue undoes).
    split_h_kernel<<<(nx4 + 255) / 256, 256>>>(x, xhi, xlo, 1.0f, 1, nx4);
    const float* Ws[4] = {W_Q, W_K, W_V, W_O};
    for (int i = 0; i < 4; i++)
        split_h_kernel<<<(nw4 + 255) / 256, 256>>>(Ws[i], wh + i * WSZ,
                                                   nullptr, 32.0f, 0, nw4);

    dim3 gemm_grid(CC / BN, MM / BM);   // (8, 64)
    gemm_tc_kernel<<<gemm_grid, 256, GEMM_SMEM>>>(
        xhi, xlo, wh + 0 * WSZ, nullptr, qh, ql, 1);
    gemm_tc_kernel<<<gemm_grid, 256, GEMM_SMEM>>>(
        xhi, xlo, wh + 1 * WSZ, nullptr, kh, kl, 1);
    gemm_tc_kernel<<<gemm_grid, 256, GEMM_SMEM>>>(
        xhi, xlo, wh + 2 * WSZ, nullptr, vh, vl, 1);

    dim3 attn_grid(TT / 128, BB * HH);  // (16, 64)
    flash_attn_tc_kernel<<<attn_grid, 256, ATTN_SMEM>>>(
        qh, ql, kh, kl, vh, vl, ah, al);

    gemm_tc_kernel<<<gemm_grid, 256, GEMM_SMEM>>>(
        ah, al, wh + 3 * WSZ, out, nullptr, nullptr, 0);
}

// round 6
// speedup vs baseline: 4.2751x; 1.1614x over previous
#include <cuda_runtime.h>
#include <cuda_fp16.h>
#include <cstdint>

// Problem constants
#define BB 4
#define TT 2048
#define HH 16
#define DH 64
#define CC 1024
#define MM (BB * TT)   // 8192 rows

// ---------------------------------------------------------------------------
// Scratch (device globals -- allocation-free per harness rules)
// ---------------------------------------------------------------------------
static __device__ __align__(16) __half g_xhi[(size_t)MM * CC];
static __device__ __align__(16) __half g_xlo[(size_t)MM * CC];
static __device__ __align__(16) __half g_wh[4][(size_t)CC * CC];
static __device__ __align__(16) __half g_qhi[(size_t)MM * CC];
static __device__ __align__(16) __half g_qlo[(size_t)MM * CC];
static __device__ __align__(16) __half g_khi[(size_t)MM * CC];
static __device__ __align__(16) __half g_vhi[(size_t)MM * CC];
static __device__ __align__(16) __half g_ahi[(size_t)MM * CC];
static __device__ __align__(16) __half g_alo[(size_t)MM * CC];

// ---------------------------------------------------------------------------
// PTX helpers (sm_80+ portable -- compute_103 safe)
// ---------------------------------------------------------------------------
__device__ __forceinline__ uint32_t smem_u32(const void* p) {
    uint32_t a;
    asm("{ .reg .u64 t; cvta.to.shared.u64 t, %1; cvt.u32.u64 %0, t; }"
        : "=r"(a) : "l"(p));
    return a;
}

#define CP_ASYNC16(saddr, gaddr) \
    asm volatile("cp.async.cg.shared.global [%0], [%1], 16;" \
                 :: "r"(saddr), "l"(gaddr))
#define CP_COMMIT() asm volatile("cp.async.commit_group;" ::: "memory")
#define CP_WAIT0()  asm volatile("cp.async.wait_group 0;" ::: "memory")
#define CP_WAIT1()  asm volatile("cp.async.wait_group 1;" ::: "memory")

#define LDSM4(r, addr)                                                          \
    asm volatile("ldmatrix.sync.aligned.m8n8.x4.shared.b16 {%0,%1,%2,%3}, [%4];"\
                 : "=r"((r)[0]), "=r"((r)[1]), "=r"((r)[2]), "=r"((r)[3])       \
                 : "r"(addr))

#define LDSM4T(r, addr)                                                         \
    asm volatile("ldmatrix.sync.aligned.m8n8.x4.trans.shared.b16 {%0,%1,%2,%3}, [%4];" \
                 : "=r"((r)[0]), "=r"((r)[1]), "=r"((r)[2]), "=r"((r)[3])       \
                 : "r"(addr))

#define MMA16816(c, a, b)                                                       \
    asm volatile("mma.sync.aligned.m16n8k16.row.col.f32.f16.f16.f32 "           \
                 "{%0,%1,%2,%3}, {%4,%5,%6,%7}, {%8,%9}, {%0,%1,%2,%3};"        \
                 : "+f"((c)[0]), "+f"((c)[1]), "+f"((c)[2]), "+f"((c)[3])       \
                 : "r"((a)[0]), "r"((a)[1]), "r"((a)[2]), "r"((a)[3]),          \
                   "r"((b)[0]), "r"((b)[1]))

// exp2(y) for y <= 0, FMA/ALU pipes only (no MUFU). |rel err| ~2e-6.
__device__ __forceinline__ float fexp2(float y) {
    y = fmaxf(y, -126.0f);
    float t = __fadd_rn(y, 12582912.0f);
    int   e = __float_as_int(t) << 23;
    float f = __fsub_rn(y, __fsub_rn(t, 12582912.0f));
    float p =              1.3333558146e-3f;
    p = fmaf(p, f, 9.6181291077e-3f);
    p = fmaf(p, f, 5.5504108664e-2f);
    p = fmaf(p, f, 2.4022650696e-1f);
    p = fmaf(p, f, 6.9314718056e-1f);
    p = fmaf(p, f, 1.0f);
    return __uint_as_float((uint32_t)(__float_as_int(p) + e));
}

// fp32 pair -> packed fp16 hi pair (RN) + fp16 lo pair (residual, RN)
__device__ __forceinline__ void pack_split_h(float v0, float v1,
                                             uint32_t& hi, uint32_t& lo) {
    __half2 h = __floats2half2_rn(v0, v1);
    hi = *(uint32_t*)&h;
    float h0 = __half2float(__low2half(h));
    float h1 = __half2float(__high2half(h));
    __half2 l = __floats2half2_rn(v0 - h0, v1 - h1);
    lo = *(uint32_t*)&l;
}

// ---------------------------------------------------------------------------
// fp32 -> (hi, lo) fp16 split with optional prescale; lo write optional
// ---------------------------------------------------------------------------
__global__ void __launch_bounds__(256) split_h_kernel(
    const float* __restrict__ in, __half* __restrict__ hi,
    __half* __restrict__ lo, float prescale, int write_lo, int n4)
{
    int i = blockIdx.x * 256 + threadIdx.x;
    if (i >= n4) return;
    float4 v = ((const float4*)in)[i];
    v.x *= prescale; v.y *= prescale; v.z *= prescale; v.w *= prescale;
    uint32_t h01, l01, h23, l23;
    pack_split_h(v.x, v.y, h01, l01);
    pack_split_h(v.z, v.w, h23, l23);
    ((uint2*)hi)[i] = make_uint2(h01, h23);
    if (write_lo) ((uint2*)lo)[i] = make_uint2(l01, l23);
}

// ---------------------------------------------------------------------------
// 2-product fp16 tensor-core GEMM: Y = (Ahi+Alo) @ Bh^T * 1/32
// mode 1 (fused QKV): grid.x = 24; gsel = blockIdx.x>>3 picks weight matrix
//   gsel 0 -> (Yq_hi, Yq_lo)  [b,h,t,d] layout, hi+lo
//   gsel 1 -> Yk_hi           [b,h,t,d] layout, hi only
//   gsel 2 -> Yv_hi           [b,h,t,d] layout, hi only
// mode 0: grid.x = 8; fp32 out to Yf in [m, n] layout
// ---------------------------------------------------------------------------
#define BM 128
#define BN 128
#define BK 32
#define NK (CC / BK)
#define ROWB 80
#define SUBT (128 * ROWB)       // 10240
#define BUFB (3 * SUBT)         // 30720 (Ahi, Alo, Bh)
#define GEMM_SMEM 67584         // max(2*BUFB=61440, epilogue 128*132*4)
#define INV32 0.03125f

__device__ __forceinline__ void load_chunk_async(
    uint32_t sb, int buf, int tid,
    const __half* __restrict__ Ahi, const __half* __restrict__ Alo,
    const __half* __restrict__ Bh, int m0, int n0, int k0)
{
    const uint32_t base = sb + buf * BUFB;
    const __half* gps[3] = {Ahi, Alo, Bh};
    const int rb[3] = {m0, m0, n0};
    #pragma unroll
    for (int it = 0; it < 6; it++) {
        const int sub = it >> 1;
        const int j = (it & 1) * 256 + tid;
        const int row = j >> 2;
        const int c16 = j & 3;
        const uint32_t saddr = base + sub * SUBT + row * ROWB + c16 * 16;
        const void* gaddr = gps[sub] + (size_t)(rb[sub] + row) * CC + k0 + c16 * 8;
        CP_ASYNC16(saddr, gaddr);
    }
}

__global__ void __launch_bounds__(256) gemm_tc_kernel(
    const __half* __restrict__ Ahi, const __half* __restrict__ Alo,
    const __half* __restrict__ Wbase,
    float* __restrict__ Yf,
    __half* __restrict__ Yq_hi, __half* __restrict__ Yq_lo,
    __half* __restrict__ Yk_hi, __half* __restrict__ Yv_hi,
    int mode)
{
    extern __shared__ char smem[];
    const uint32_t sb = smem_u32(smem);
    const int tid = threadIdx.x;
    const int lane = tid & 31;
    const int wid = tid >> 5;
    const int wm = (wid >> 2) * 64;
    const int wn = (wid & 3) * 32;

    int gsel = 0, nblk = blockIdx.x;
    if (mode == 1) { gsel = blockIdx.x >> 3; nblk = blockIdx.x & 7; }
    const int n0 = nblk * BN;
    const int m0 = blockIdx.y * BM;
    const __half* Bh = Wbase + (size_t)gsel * CC * CC;

    __half* Yhi = nullptr; __half* Ylo = nullptr;
    if (mode == 1) {
        if (gsel == 0)      { Yhi = Yq_hi; Ylo = Yq_lo; }
        else if (gsel == 1) { Yhi = Yk_hi; }
        else                { Yhi = Yv_hi; }
    }

    float acc[4][4][4] = {};

    load_chunk_async(sb, 0, tid, Ahi, Alo, Bh, m0, n0, 0);
    CP_COMMIT();

    const int a_row = (lane & 15);
    const int a_koff = (lane >> 4) << 3;
    const int b_row = ((lane >> 4) << 3) + (lane & 7);
    const int b_koff = ((lane >> 3) & 1) << 3;

    for (int c = 0; c < NK; c++) {
        CP_WAIT0();
        __syncthreads();
        if (c + 1 < NK) {
            load_chunk_async(sb, (c + 1) & 1, tid, Ahi, Alo, Bh,
                             m0, n0, (c + 1) * BK);
            CP_COMMIT();
        }

        const uint32_t ab = sb + (c & 1) * BUFB;
        const uint32_t bb = ab + 2 * SUBT;

        #pragma unroll
        for (int ks = 0; ks < 2; ks++) {
            uint32_t ah[16], al[16], bh[8];
            #pragma unroll
            for (int mt = 0; mt < 4; mt++) {
                const uint32_t off =
                    (uint32_t)((wm + mt * 16 + a_row) * ROWB + (ks * 16 + a_koff) * 2);
                LDSM4(&ah[mt * 4], ab + off);
                LDSM4(&al[mt * 4], ab + SUBT + off);
            }
            #pragma unroll
            for (int nt2 = 0; nt2 < 2; nt2++) {
                const uint32_t off =
                    (uint32_t)((wn + nt2 * 16 + b_row) * ROWB + (ks * 16 + b_koff) * 2);
                LDSM4(&bh[nt2 * 4], bb + off);
            }
            #pragma unroll
            for (int mt = 0; mt < 4; mt++)
                #pragma unroll
                for (int nt = 0; nt < 4; nt++) {
                    float* cc = acc[mt][nt];
                    MMA16816(cc, &ah[mt * 4], &bh[nt * 2]);
                    MMA16816(cc, &al[mt * 4], &bh[nt * 2]);
                }
        }
        __syncthreads();
    }

    // epilogue: registers (x 1/32) -> smem staging -> coalesced global stores
    float* es = (float*)smem;   // [128][132]
    const int er = lane >> 2;
    const int ec = (lane & 3) * 2;
    #pragma unroll
    for (int mt = 0; mt < 4; mt++)
        #pragma unroll
        for (int nt = 0; nt < 4; nt++) {
            const int r = wm + mt * 16 + er;
            const int cl = wn + nt * 8 + ec;
            *(float2*)&es[r * 132 + cl] =
                make_float2(acc[mt][nt][0] * INV32, acc[mt][nt][1] * INV32);
            *(float2*)&es[(r + 8) * 132 + cl] =
                make_float2(acc[mt][nt][2] * INV32, acc[mt][nt][3] * INV32);
        }
    __syncthreads();

    #pragma unroll
    for (int it = 0; it < 16; it++) {
        const int i = tid + it * 256;
        const int r = i >> 5;
        const int c4 = (i & 31) * 4;
        float4 v = *(float4*)&es[r * 132 + c4];
        const int m = m0 + r;
        const int n = n0 + c4;
        if (mode == 1) {
            const int b = m >> 11, t = m & 2047, h = n >> 6, d = n & 63;
            const size_t idx = (((size_t)(b * HH + h) * TT) + t) * DH + d;
            uint32_t h01, l01, h23, l23;
            pack_split_h(v.x, v.y, h01, l01);
            pack_split_h(v.z, v.w, h23, l23);
            *(uint2*)&Yhi[idx] = make_uint2(h01, h23);
            if (Ylo) *(uint2*)&Ylo[idx] = make_uint2(l01, l23);
        } else {
            *(float4*)&Yf[(size_t)m * CC + n] = v;
        }
    }
}

// ---------------------------------------------------------------------------
// Tensor-core flash attention (causal), 2-product fp16:
//   S = (Qhi + Qlo) K^T,  O = (Phi + Plo) V.   K, V single fp16.
// BM=128 Q rows, BKV=64, d=64. 256 threads = 8 warps, warp owns 16 Q rows.
// Softmax exp on the FMA pipe. Outputs (hi, lo) fp16 in [m, c] layout.
// ---------------------------------------------------------------------------
#define AROW 144
#define SMQH 0
#define SMQL (128 * AROW)            // 18432
#define SMKV (2 * 128 * AROW)        // 36864
#define STAGEB (2 * 64 * AROW)       // 18432
#define KO_KH 0
#define KO_VH (64 * AROW)            // 9216
#define ATTN_SMEM (SMKV + 2 * STAGEB)  // 73728
#define SCALE_L2E 0.1803368801111763f  // 0.125 * log2(e)

__device__ __forceinline__ void load_kv_stage(
    uint32_t sb, int stage, int tid, size_t gbase, int kv0,
    const __half* __restrict__ khi, const __half* __restrict__ vhi)
{
    const uint32_t base = sb + SMKV + stage * STAGEB;
    const __half* gps[2] = {khi, vhi};
    #pragma unroll
    for (int it = 0; it < 4; it++) {
        const int idx = tid + it * 256;         // 0..1023
        const int arr = idx >> 9;               // 0..1
        const int r = (idx >> 3) & 63;
        const int c = idx & 7;
        const uint32_t dst = base + arr * (64 * AROW) + r * AROW + c * 16;
        CP_ASYNC16(dst, gps[arr] + gbase + (size_t)(kv0 + r) * DH + c * 8);
    }
}

__global__ void __launch_bounds__(256, 1) flash_attn_tc_kernel(
    const __half* __restrict__ qhi, const __half* __restrict__ qlo,
    const __half* __restrict__ khi, const __half* __restrict__ vhi,
    __half* __restrict__ Ohi, __half* __restrict__ Olo)
{
    extern __shared__ char smem[];
    const uint32_t sb = smem_u32(smem);
    const int tid = threadIdx.x;
    const int lane = tid & 31;
    const int wid = tid >> 5;
    const int wm = wid * 16;
    const int qi = 15 - (int)blockIdx.x;     // heavy tiles first
    const int bh = blockIdx.y;
    const int q0 = qi * 128;
    const size_t gbase = (size_t)bh * TT * DH;

    // ldmatrix lane offsets
    const int a_row = lane & 15;
    const int a_koff = (lane >> 4) << 3;
    const int b_row = ((lane >> 4) << 3) + (lane & 7);
    const int b_koff = ((lane >> 3) & 1) << 3;
    const int v_krow = (lane & 7) + (((lane >> 3) & 1) << 3);
    const int v_noff = (lane >> 4) << 3;

    // group 0: Q tile (hi + lo) + KV stage 0
    #pragma unroll
    for (int it = 0; it < 8; it++) {
        const int idx = tid + it * 256;      // 0..2047
        const int r = (idx >> 3) & 127;
        const int c = idx & 7;
        const int isLo = idx >> 10;
        const uint32_t dst = sb + (isLo ? SMQL : SMQH) + r * AROW + c * 16;
        const __half* src = isLo ? qlo : qhi;
        CP_ASYNC16(dst, src + gbase + (size_t)(q0 + r) * DH + c * 8);
    }
    load_kv_stage(sb, 0, tid, gbase, 0, khi, vhi);
    CP_COMMIT();

    const int nkv = 2 * qi + 2;
    float m0 = -1e30f, m1 = -1e30f, l0 = 0.0f, l1 = 0.0f;
    float oacc[8][4] = {};
    const int r0 = lane >> 2;
    const int cb = (lane & 3) * 2;

    for (int j = 0; j < nkv; j++) {
        if (j + 1 < nkv) {
            load_kv_stage(sb, (j + 1) & 1, tid, gbase, (j + 1) * 64, khi, vhi);
            CP_COMMIT();
            CP_WAIT1();
        } else {
            CP_WAIT0();
        }
        __syncthreads();

        const uint32_t kvb = sb + SMKV + (j & 1) * STAGEB;

        // ---- S = Q K^T (2-product) ----
        float sacc[8][4] = {};
        #pragma unroll
        for (int ks = 0; ks < 4; ks++) {
            uint32_t ah[4], al[4];
            const uint32_t aoff =
                (uint32_t)((wm + a_row) * AROW + (ks * 16 + a_koff) * 2);
            LDSM4(ah, sb + SMQH + aoff);
            LDSM4(al, sb + SMQL + aoff);
            #pragma unroll
            for (int ng = 0; ng < 4; ng++) {
                uint32_t bhf[4];
                const uint32_t boff =
                    (uint32_t)((ng * 16 + b_row) * AROW + (ks * 16 + b_koff) * 2);
                LDSM4(bhf, kvb + KO_KH + boff);
                float* s0 = sacc[2 * ng];
                float* s1 = sacc[2 * ng + 1];
                MMA16816(s0, ah, &bhf[0]);
                MMA16816(s0, al, &bhf[0]);
                MMA16816(s1, ah, &bhf[2]);
                MMA16816(s1, al, &bhf[2]);
            }
        }

        // ---- scale (log2 domain) + causal mask ----
        const int kv0 = j * 64;
        const bool needmask = (kv0 + 63 > q0 + wm);
        const int tq0 = q0 + wm + r0;
        #pragma unroll
        for (int nt = 0; nt < 8; nt++) {
            #pragma unroll
            for (int e = 0; e < 4; e++) {
                float z = sacc[nt][e] * SCALE_L2E;
                if (needmask) {
                    const int tk = kv0 + nt * 8 + cb + (e & 1);
                    const int tq = tq0 + ((e >> 1) << 3);
                    if (tk > tq) z = -1e30f;
                }
                sacc[nt][e] = z;
            }
        }

        // ---- online softmax (quad-reduced row stats) ----
        float zm0 = -1e30f, zm1 = -1e30f;
        #pragma unroll
        for (int nt = 0; nt < 8; nt++) {
            zm0 = fmaxf(zm0, fmaxf(sacc[nt][0], sacc[nt][1]));
            zm1 = fmaxf(zm1, fmaxf(sacc[nt][2], sacc[nt][3]));
        }
        zm0 = fmaxf(zm0, __shfl_xor_sync(0xffffffffu, zm0, 1));
        zm0 = fmaxf(zm0, __shfl_xor_sync(0xffffffffu, zm0, 2));
        zm1 = fmaxf(zm1, __shfl_xor_sync(0xffffffffu, zm1, 1));
        zm1 = fmaxf(zm1, __shfl_xor_sync(0xffffffffu, zm1, 2));
        const float mn0 = fmaxf(m0, zm0);
        const float mn1 = fmaxf(m1, zm1);
        const float rs0 = fexp2(m0 - mn0);
        const float rs1 = fexp2(m1 - mn1);
        float sum0 = 0.0f, sum1 = 0.0f;
        #pragma unroll
        for (int nt = 0; nt < 8; nt++) {
            float p0 = fexp2(sacc[nt][0] - mn0);
            float p1 = fexp2(sacc[nt][1] - mn0);
            float p2 = fexp2(sacc[nt][2] - mn1);
            float p3 = fexp2(sacc[nt][3] - mn1);
            sacc[nt][0] = p0; sacc[nt][1] = p1;
            sacc[nt][2] = p2; sacc[nt][3] = p3;
            sum0 += p0 + p1;
            sum1 += p2 + p3;
        }
        sum0 += __shfl_xor_sync(0xffffffffu, sum0, 1);
        sum0 += __shfl_xor_sync(0xffffffffu, sum0, 2);
        sum1 += __shfl_xor_sync(0xffffffffu, sum1, 1);
        sum1 += __shfl_xor_sync(0xffffffffu, sum1, 2);
        l0 = l0 * rs0 + sum0;
        l1 = l1 * rs1 + sum1;
        m0 = mn0;
        m1 = mn1;

        // ---- rescale O ----
        #pragma unroll
        for (int nt = 0; nt < 8; nt++) {
            oacc[nt][0] *= rs0;
            oacc[nt][1] *= rs0;
            oacc[nt][2] *= rs1;
            oacc[nt][3] *= rs1;
        }

        // ---- pack P into split A-fragments ----
        uint32_t pah[4][4], pal[4][4];
        #pragma unroll
        for (int kt = 0; kt < 4; kt++) {
            pack_split_h(sacc[2 * kt][0],     sacc[2 * kt][1],     pah[kt][0], pal[kt][0]);
            pack_split_h(sacc[2 * kt][2],     sacc[2 * kt][3],     pah[kt][1], pal[kt][1]);
            pack_split_h(sacc[2 * kt + 1][0], sacc[2 * kt + 1][1], pah[kt][2], pal[kt][2]);
            pack_split_h(sacc[2 * kt + 1][2], sacc[2 * kt + 1][3], pah[kt][3], pal[kt][3]);
        }

        // ---- O += P V (2-product), V via ldmatrix.trans ----
        #pragma unroll
        for (int ks = 0; ks < 4; ks++) {
            #pragma unroll
            for (int ng = 0; ng < 4; ng++) {
                uint32_t vhf[4];
                const uint32_t voff =
                    (uint32_t)((ks * 16 + v_krow) * AROW + (ng * 16 + v_noff) * 2);
                LDSM4T(vhf, kvb + KO_VH + voff);
                float* o0 = oacc[2 * ng];
                float* o1 = oacc[2 * ng + 1];
                MMA16816(o0, pah[ks], &vhf[0]);
                MMA16816(o0, pal[ks], &vhf[0]);
                MMA16816(o1, pah[ks], &vhf[2]);
                MMA16816(o1, pal[ks], &vhf[2]);
            }
        }
        __syncthreads();
    }

    // ---- epilogue: normalize, split to (hi, lo) fp16, write [m, c] ----
    const float inv0 = 1.0f / l0;
    const float inv1 = 1.0f / l1;
    const int b = bh >> 4;
    const int h = bh & 15;
    const int trow0 = q0 + wm + r0;
    const int trow1 = trow0 + 8;
    #pragma unroll
    for (int nt = 0; nt < 8; nt++) {
        const int col = h * DH + nt * 8 + cb;
        uint32_t hp, lp;
        pack_split_h(oacc[nt][0] * inv0, oacc[nt][1] * inv0, hp, lp);
        const size_t idx0 = ((size_t)b * TT + trow0) * CC + col;
        *(uint32_t*)&Ohi[idx0] = hp;
        *(uint32_t*)&Olo[idx0] = lp;
        pack_split_h(oacc[nt][2] * inv1, oacc[nt][3] * inv1, hp, lp);
        const size_t idx1 = ((size_t)b * TT + trow1) * CC + col;
        *(uint32_t*)&Ohi[idx1] = hp;
        *(uint32_t*)&Olo[idx1] = lp;
    }
}

// ---------------------------------------------------------------------------
// Launch
// ---------------------------------------------------------------------------
extern "C" void kernel_launch(void* const* d_in, const int* in_sizes, int n_in,
                              void* d_out, int out_size)
{
    const float* x   = (const float*)d_in[0];
    const float* W_Q = (const float*)d_in[1];
    const float* W_K = (const float*)d_in[2];
    const float* W_V = (const float*)d_in[3];
    const float* W_O = (const float*)d_in[4];
    float* out = (float*)d_out;

    __half *xhi, *xlo, *wh;
    __half *qh, *ql, *kh, *vh, *ah, *al;
    cudaGetSymbolAddress((void**)&xhi, g_xhi);
    cudaGetSymbolAddress((void**)&xlo, g_xlo);
    cudaGetSymbolAddress((void**)&wh, g_wh);
    cudaGetSymbolAddress((void**)&qh, g_qhi);
    cudaGetSymbolAddress((void**)&ql, g_qlo);
    cudaGetSymbolAddress((void**)&kh, g_khi);
    cudaGetSymbolAddress((void**)&vh, g_vhi);
    cudaGetSymbolAddress((void**)&ah, g_ahi);
    cudaGetSymbolAddress((void**)&al, g_alo);

    cudaFuncSetAttribute(gemm_tc_kernel,
                         cudaFuncAttributeMaxDynamicSharedMemorySize, GEMM_SMEM);
    cudaFuncSetAttribute(flash_attn_tc_kernel,
                         cudaFuncAttributeMaxDynamicSharedMemorySize, ATTN_SMEM);

    const size_t WSZ = (size_t)CC * CC;
    const int nx4 = (MM * CC) / 4;
    const int nw4 = (CC * CC) / 4;

    // x: split (hi+lo). Weights: hi only, pre-scaled by 32 (epilogue undoes).
    split_h_kernel<<<(nx4 + 255) / 256, 256>>>(x, xhi, xlo, 1.0f, 1, nx4);
    const float* Ws[4] = {W_Q, W_K, W_V, W_O};
    for (int i = 0; i < 4; i++)
        split_h_kernel<<<(nw4 + 255) / 256, 256>>>(Ws[i], wh + i * WSZ,
                                                   nullptr, 32.0f, 0, nw4);

    // fused QKV projections: one launch, 1536 CTAs
    dim3 qkv_grid(3 * CC / BN, MM / BM);   // (24, 64)
    gemm_tc_kernel<<<qkv_grid, 256, GEMM_SMEM>>>(
        xhi, xlo, wh, nullptr, qh, ql, kh, vh, 1);

    dim3 attn_grid(TT / 128, BB * HH);     // (16, 64)
    flash_attn_tc_kernel<<<attn_grid, 256, ATTN_SMEM>>>(
        qh, ql, kh, vh, ah, al);

    dim3 out_grid(CC / BN, MM / BM);       // (8, 64)
    gemm_tc_kernel<<<out_grid, 256, GEMM_SMEM>>>(
        ah, al, wh + 3 * WSZ, out, nullptr, nullptr, nullptr, nullptr, 0);
}

// round 7
// speedup vs baseline: 4.4192x; 1.0337x over previous
#include <cuda_runtime.h>
#include <cuda_fp16.h>
#include <cstdint>

// Problem constants
#define BB 4
#define TT 2048
#define HH 16
#define DH 64
#define CC 1024
#define MM (BB * TT)   // 8192 rows

// ---------------------------------------------------------------------------
// Scratch (device globals -- allocation-free per harness rules)
// ---------------------------------------------------------------------------
static __device__ __align__(16) __half g_xhi[(size_t)MM * CC];
static __device__ __align__(16) __half g_xlo[(size_t)MM * CC];
static __device__ __align__(16) __half g_wh[4][(size_t)CC * CC];
static __device__ __align__(16) __half g_qhi[(size_t)MM * CC];
static __device__ __align__(16) __half g_qlo[(size_t)MM * CC];
static __device__ __align__(16) __half g_khi[(size_t)MM * CC];
static __device__ __align__(16) __half g_vhi[(size_t)MM * CC];
static __device__ __align__(16) __half g_ahi[(size_t)MM * CC];
static __device__ __align__(16) __half g_alo[(size_t)MM * CC];

// ---------------------------------------------------------------------------
// PTX helpers (sm_80+ portable -- compute_103 safe)
// ---------------------------------------------------------------------------
__device__ __forceinline__ uint32_t smem_u32(const void* p) {
    uint32_t a;
    asm("{ .reg .u64 t; cvta.to.shared.u64 t, %1; cvt.u32.u64 %0, t; }"
        : "=r"(a) : "l"(p));
    return a;
}

#define CP_ASYNC16(saddr, gaddr) \
    asm volatile("cp.async.cg.shared.global [%0], [%1], 16;" \
                 :: "r"(saddr), "l"(gaddr))
#define CP_COMMIT() asm volatile("cp.async.commit_group;" ::: "memory")
#define CP_WAIT0()  asm volatile("cp.async.wait_group 0;" ::: "memory")
#define CP_WAIT1()  asm volatile("cp.async.wait_group 1;" ::: "memory")

#define LDSM4(r, addr)                                                          \
    asm volatile("ldmatrix.sync.aligned.m8n8.x4.shared.b16 {%0,%1,%2,%3}, [%4];"\
                 : "=r"((r)[0]), "=r"((r)[1]), "=r"((r)[2]), "=r"((r)[3])       \
                 : "r"(addr))

#define LDSM4T(r, addr)                                                         \
    asm volatile("ldmatrix.sync.aligned.m8n8.x4.trans.shared.b16 {%0,%1,%2,%3}, [%4];" \
                 : "=r"((r)[0]), "=r"((r)[1]), "=r"((r)[2]), "=r"((r)[3])       \
                 : "r"(addr))

#define MMA16816(c, a, b)                                                       \
    asm volatile("mma.sync.aligned.m16n8k16.row.col.f32.f16.f16.f32 "           \
                 "{%0,%1,%2,%3}, {%4,%5,%6,%7}, {%8,%9}, {%0,%1,%2,%3};"        \
                 : "+f"((c)[0]), "+f"((c)[1]), "+f"((c)[2]), "+f"((c)[3])       \
                 : "r"((a)[0]), "r"((a)[1]), "r"((a)[2]), "r"((a)[3]),          \
                   "r"((b)[0]), "r"((b)[1]))

// exp2(y) for y <= 0, FMA/ALU pipes only (no MUFU). |rel err| ~2e-6.
__device__ __forceinline__ float fexp2(float y) {
    y = fmaxf(y, -126.0f);
    float t = __fadd_rn(y, 12582912.0f);
    int   e = __float_as_int(t) << 23;
    float f = __fsub_rn(y, __fsub_rn(t, 12582912.0f));
    float p =              1.3333558146e-3f;
    p = fmaf(p, f, 9.6181291077e-3f);
    p = fmaf(p, f, 5.5504108664e-2f);
    p = fmaf(p, f, 2.4022650696e-1f);
    p = fmaf(p, f, 6.9314718056e-1f);
    p = fmaf(p, f, 1.0f);
    return __uint_as_float((uint32_t)(__float_as_int(p) + e));
}

// fp32 pair -> packed fp16 hi pair (RN) + fp16 lo pair (residual, RN)
__device__ __forceinline__ void pack_split_h(float v0, float v1,
                                             uint32_t& hi, uint32_t& lo) {
    __half2 h = __floats2half2_rn(v0, v1);
    hi = *(uint32_t*)&h;
    float h0 = __half2float(__low2half(h));
    float h1 = __half2float(__high2half(h));
    __half2 l = __floats2half2_rn(v0 - h0, v1 - h1);
    lo = *(uint32_t*)&l;
}

__device__ __forceinline__ uint32_t pack_h(float v0, float v1) {
    __half2 h = __floats2half2_rn(v0, v1);
    return *(uint32_t*)&h;
}

// ---------------------------------------------------------------------------
// fp32 -> (hi, lo) fp16 split with optional prescale; lo write optional
// ---------------------------------------------------------------------------
__global__ void __launch_bounds__(256) split_h_kernel(
    const float* __restrict__ in, __half* __restrict__ hi,
    __half* __restrict__ lo, float prescale, int write_lo, int n4)
{
    int i = blockIdx.x * 256 + threadIdx.x;
    if (i >= n4) return;
    float4 v = ((const float4*)in)[i];
    v.x *= prescale; v.y *= prescale; v.z *= prescale; v.w *= prescale;
    uint32_t h01, l01, h23, l23;
    pack_split_h(v.x, v.y, h01, l01);
    pack_split_h(v.z, v.w, h23, l23);
    ((uint2*)hi)[i] = make_uint2(h01, h23);
    if (write_lo) ((uint2*)lo)[i] = make_uint2(l01, l23);
}

// ---------------------------------------------------------------------------
// 2-product fp16 tensor-core GEMM: Y = (Ahi+Alo) @ Bh^T * 1/32
// mode 1 (fused QKV): grid.x = 24; gsel picks W and destination.
// mode 0: grid.x = 8; fp32 out to Yf in [m, n] layout
// ---------------------------------------------------------------------------
#define BM 128
#define BN 128
#define BK 32
#define NK (CC / BK)
#define ROWB 80
#define SUBT (128 * ROWB)       // 10240
#define BUFB (3 * SUBT)         // 30720 (Ahi, Alo, Bh)
#define GEMM_SMEM 67584
#define INV32 0.03125f

__device__ __forceinline__ void load_chunk_async(
    uint32_t sb, int buf, int tid,
    const __half* __restrict__ Ahi, const __half* __restrict__ Alo,
    const __half* __restrict__ Bh, int m0, int n0, int k0)
{
    const uint32_t base = sb + buf * BUFB;
    const __half* gps[3] = {Ahi, Alo, Bh};
    const int rb[3] = {m0, m0, n0};
    #pragma unroll
    for (int it = 0; it < 6; it++) {
        const int sub = it >> 1;
        const int j = (it & 1) * 256 + tid;
        const int row = j >> 2;
        const int c16 = j & 3;
        const uint32_t saddr = base + sub * SUBT + row * ROWB + c16 * 16;
        const void* gaddr = gps[sub] + (size_t)(rb[sub] + row) * CC + k0 + c16 * 8;
        CP_ASYNC16(saddr, gaddr);
    }
}

__global__ void __launch_bounds__(256) gemm_tc_kernel(
    const __half* __restrict__ Ahi, const __half* __restrict__ Alo,
    const __half* __restrict__ Wbase,
    float* __restrict__ Yf,
    __half* __restrict__ Yq_hi, __half* __restrict__ Yq_lo,
    __half* __restrict__ Yk_hi, __half* __restrict__ Yv_hi,
    int mode)
{
    extern __shared__ char smem[];
    const uint32_t sb = smem_u32(smem);
    const int tid = threadIdx.x;
    const int lane = tid & 31;
    const int wid = tid >> 5;
    const int wm = (wid >> 2) * 64;
    const int wn = (wid & 3) * 32;

    int gsel = 0, nblk = blockIdx.x;
    if (mode == 1) { gsel = blockIdx.x >> 3; nblk = blockIdx.x & 7; }
    const int n0 = nblk * BN;
    const int m0 = blockIdx.y * BM;
    const __half* Bh = Wbase + (size_t)gsel * CC * CC;

    __half* Yhi = nullptr; __half* Ylo = nullptr;
    if (mode == 1) {
        if (gsel == 0)      { Yhi = Yq_hi; Ylo = Yq_lo; }
        else if (gsel == 1) { Yhi = Yk_hi; }
        else                { Yhi = Yv_hi; }
    }

    float acc[4][4][4] = {};

    load_chunk_async(sb, 0, tid, Ahi, Alo, Bh, m0, n0, 0);
    CP_COMMIT();

    const int a_row = (lane & 15);
    const int a_koff = (lane >> 4) << 3;
    const int b_row = ((lane >> 4) << 3) + (lane & 7);
    const int b_koff = ((lane >> 3) & 1) << 3;

    for (int c = 0; c < NK; c++) {
        CP_WAIT0();
        __syncthreads();
        if (c + 1 < NK) {
            load_chunk_async(sb, (c + 1) & 1, tid, Ahi, Alo, Bh,
                             m0, n0, (c + 1) * BK);
            CP_COMMIT();
        }

        const uint32_t ab = sb + (c & 1) * BUFB;
        const uint32_t bb = ab + 2 * SUBT;

        #pragma unroll
        for (int ks = 0; ks < 2; ks++) {
            uint32_t ah[16], al[16], bh[8];
            #pragma unroll
            for (int mt = 0; mt < 4; mt++) {
                const uint32_t off =
                    (uint32_t)((wm + mt * 16 + a_row) * ROWB + (ks * 16 + a_koff) * 2);
                LDSM4(&ah[mt * 4], ab + off);
                LDSM4(&al[mt * 4], ab + SUBT + off);
            }
            #pragma unroll
            for (int nt2 = 0; nt2 < 2; nt2++) {
                const uint32_t off =
                    (uint32_t)((wn + nt2 * 16 + b_row) * ROWB + (ks * 16 + b_koff) * 2);
                LDSM4(&bh[nt2 * 4], bb + off);
            }
            #pragma unroll
            for (int mt = 0; mt < 4; mt++)
                #pragma unroll
                for (int nt = 0; nt < 4; nt++) {
                    float* cc = acc[mt][nt];
                    MMA16816(cc, &ah[mt * 4], &bh[nt * 2]);
                    MMA16816(cc, &al[mt * 4], &bh[nt * 2]);
                }
        }
        __syncthreads();
    }

    // epilogue
    float* es = (float*)smem;   // [128][132]
    const int er = lane >> 2;
    const int ec = (lane & 3) * 2;
    #pragma unroll
    for (int mt = 0; mt < 4; mt++)
        #pragma unroll
        for (int nt = 0; nt < 4; nt++) {
            const int r = wm + mt * 16 + er;
            const int cl = wn + nt * 8 + ec;
            *(float2*)&es[r * 132 + cl] =
                make_float2(acc[mt][nt][0] * INV32, acc[mt][nt][1] * INV32);
            *(float2*)&es[(r + 8) * 132 + cl] =
                make_float2(acc[mt][nt][2] * INV32, acc[mt][nt][3] * INV32);
        }
    __syncthreads();

    #pragma unroll
    for (int it = 0; it < 16; it++) {
        const int i = tid + it * 256;
        const int r = i >> 5;
        const int c4 = (i & 31) * 4;
        float4 v = *(float4*)&es[r * 132 + c4];
        const int m = m0 + r;
        const int n = n0 + c4;
        if (mode == 1) {
            const int b = m >> 11, t = m & 2047, h = n >> 6, d = n & 63;
            const size_t idx = (((size_t)(b * HH + h) * TT) + t) * DH + d;
            uint32_t h01, l01, h23, l23;
            pack_split_h(v.x, v.y, h01, l01);
            pack_split_h(v.z, v.w, h23, l23);
            *(uint2*)&Yhi[idx] = make_uint2(h01, h23);
            if (Ylo) *(uint2*)&Ylo[idx] = make_uint2(l01, l23);
        } else {
            *(float4*)&Yf[(size_t)m * CC + n] = v;
        }
    }
}

// ---------------------------------------------------------------------------
// Pipelined tensor-core flash attention (causal).
//   S = (Qhi + Qlo) K^T  (2-product),  O = P_hi V  (1-product).
// Software pipeline: QK of tile j+1 overlaps softmax of tile j (independent
// tensor vs FMA streams in one barrier-free region). 3-stage KV smem.
// ---------------------------------------------------------------------------
#define AROW 144
#define SMQH 0
#define SMQL (128 * AROW)            // 18432
#define SMKV (2 * 128 * AROW)        // 36864
#define STAGEB (2 * 64 * AROW)       // 18432 (K + V)
#define KO_KH 0
#define KO_VH (64 * AROW)            // 9216
#define ATTN_SMEM (SMKV + 3 * STAGEB)  // 92160
#define SCALE_L2E 0.1803368801111763f  // 0.125 * log2(e)

__device__ __forceinline__ void load_kv_stage(
    uint32_t sb, int stage, int tid, size_t gbase, int kv0,
    const __half* __restrict__ khi, const __half* __restrict__ vhi)
{
    const uint32_t base = sb + SMKV + stage * STAGEB;
    const __half* gps[2] = {khi, vhi};
    #pragma unroll
    for (int it = 0; it < 4; it++) {
        const int idx = tid + it * 256;         // 0..1023
        const int arr = idx >> 9;               // 0..1
        const int r = (idx >> 3) & 63;
        const int c = idx & 7;
        const uint32_t dst = base + arr * (64 * AROW) + r * AROW + c * 16;
        CP_ASYNC16(dst, gps[arr] + gbase + (size_t)(kv0 + r) * DH + c * 8);
    }
}

__global__ void __launch_bounds__(256, 1) flash_attn_tc_kernel(
    const __half* __restrict__ qhi, const __half* __restrict__ qlo,
    const __half* __restrict__ khi, const __half* __restrict__ vhi,
    __half* __restrict__ Ohi, __half* __restrict__ Olo)
{
    extern __shared__ char smem[];
    const uint32_t sb = smem_u32(smem);
    const int tid = threadIdx.x;
    const int lane = tid & 31;
    const int wid = tid >> 5;
    const int wm = wid * 16;
    const int qi = 15 - (int)blockIdx.x;     // heavy tiles first
    const int bh = blockIdx.y;
    const int q0 = qi * 128;
    const size_t gbase = (size_t)bh * TT * DH;

    // ldmatrix lane offsets
    const int a_row = lane & 15;
    const int a_koff = (lane >> 4) << 3;
    const int b_row = ((lane >> 4) << 3) + (lane & 7);
    const int b_koff = ((lane >> 3) & 1) << 3;
    const int v_krow = (lane & 7) + (((lane >> 3) & 1) << 3);
    const int v_noff = (lane >> 4) << 3;

    const int nkv = 2 * qi + 2;              // always even

    // group 0: Q tile (hi + lo) + KV stage 0
    #pragma unroll
    for (int it = 0; it < 8; it++) {
        const int idx = tid + it * 256;      // 0..2047
        const int r = (idx >> 3) & 127;
        const int c = idx & 7;
        const int isLo = idx >> 10;
        const uint32_t dst = sb + (isLo ? SMQL : SMQH) + r * AROW + c * 16;
        const __half* src = isLo ? qlo : qhi;
        CP_ASYNC16(dst, src + gbase + (size_t)(q0 + r) * DH + c * 8);
    }
    load_kv_stage(sb, 0, tid, gbase, 0, khi, vhi);
    CP_COMMIT();
    // group 1: KV stage 1
    if (nkv > 1) {
        load_kv_stage(sb, 1, tid, gbase, 64, khi, vhi);
        CP_COMMIT();
        CP_WAIT1();
    } else {
        CP_WAIT0();
    }
    __syncthreads();

    float m0 = -1e30f, m1 = -1e30f, l0 = 0.0f, l1 = 0.0f;
    float oacc[8][4] = {};
    float sA[8][4], sB[8][4];
    const int r0 = lane >> 2;
    const int cb = (lane & 3) * 2;
    const int tq0 = q0 + wm + r0;

    // QK for tile jt -> s (2-product) with scale+mask
    auto qk_tile = [&](int jt, float (&s)[8][4]) {
        const uint32_t kb = sb + SMKV + (jt % 3) * STAGEB + KO_KH;
        #pragma unroll
        for (int nt = 0; nt < 8; nt++)
            #pragma unroll
            for (int e = 0; e < 4; e++) s[nt][e] = 0.0f;
        #pragma unroll
        for (int ks = 0; ks < 4; ks++) {
            uint32_t ah[4], al[4];
            const uint32_t aoff =
                (uint32_t)((wm + a_row) * AROW + (ks * 16 + a_koff) * 2);
            LDSM4(ah, sb + SMQH + aoff);
            LDSM4(al, sb + SMQL + aoff);
            #pragma unroll
            for (int ng = 0; ng < 4; ng++) {
                uint32_t bhf[4];
                const uint32_t boff =
                    (uint32_t)((ng * 16 + b_row) * AROW + (ks * 16 + b_koff) * 2);
                LDSM4(bhf, kb + boff);
                float* s0 = s[2 * ng];
                float* s1 = s[2 * ng + 1];
                MMA16816(s0, ah, &bhf[0]);
                MMA16816(s0, al, &bhf[0]);
                MMA16816(s1, ah, &bhf[2]);
                MMA16816(s1, al, &bhf[2]);
            }
        }
        const int kv0 = jt * 64;
        const bool needmask = (kv0 + 63 > q0 + wm);
        #pragma unroll
        for (int nt = 0; nt < 8; nt++)
            #pragma unroll
            for (int e = 0; e < 4; e++) {
                float z = s[nt][e] * SCALE_L2E;
                if (needmask) {
                    const int tk = kv0 + nt * 8 + cb + (e & 1);
                    const int tq = tq0 + ((e >> 1) << 3);
                    if (tk > tq) z = -1e30f;
                }
                s[nt][e] = z;
            }
    };

    // one pipelined iteration: QK_{j+1} -> nxt overlaps softmax(cur); PV_j
    auto body = [&](int j, float (&cur)[8][4], float (&nxt)[8][4]) {
        __syncthreads();                       // all warps done with stage (j-1)%3
        if (j + 2 < nkv) {
            load_kv_stage(sb, (j + 2) % 3, tid, gbase, (j + 2) * 64, khi, vhi);
            CP_COMMIT();
        }
        if (j + 1 < nkv) {
            if (j + 2 < nkv) { CP_WAIT1(); } else { CP_WAIT0(); }
        }
        __syncthreads();                       // KV_{j+1} visible

        // ---- tensor stream: QK_{j+1} ----
        if (j + 1 < nkv) qk_tile(j + 1, nxt);

        // ---- FMA stream: softmax(cur) ----
        float zm0 = -1e30f, zm1 = -1e30f;
        #pragma unroll
        for (int nt = 0; nt < 8; nt++) {
            zm0 = fmaxf(zm0, fmaxf(cur[nt][0], cur[nt][1]));
            zm1 = fmaxf(zm1, fmaxf(cur[nt][2], cur[nt][3]));
        }
        zm0 = fmaxf(zm0, __shfl_xor_sync(0xffffffffu, zm0, 1));
        zm0 = fmaxf(zm0, __shfl_xor_sync(0xffffffffu, zm0, 2));
        zm1 = fmaxf(zm1, __shfl_xor_sync(0xffffffffu, zm1, 1));
        zm1 = fmaxf(zm1, __shfl_xor_sync(0xffffffffu, zm1, 2));
        const float mn0 = fmaxf(m0, zm0);
        const float mn1 = fmaxf(m1, zm1);
        const float rs0 = fexp2(m0 - mn0);
        const float rs1 = fexp2(m1 - mn1);
        float sum0 = 0.0f, sum1 = 0.0f;
        uint32_t pah[4][4];
        #pragma unroll
        for (int nt = 0; nt < 8; nt++) {
            float p0 = fexp2(cur[nt][0] - mn0);
            float p1 = fexp2(cur[nt][1] - mn0);
            float p2 = fexp2(cur[nt][2] - mn1);
            float p3 = fexp2(cur[nt][3] - mn1);
            sum0 += p0 + p1;
            sum1 += p2 + p3;
            const int kt = nt >> 1;
            const int o = (nt & 1) << 1;
            pah[kt][o]     = pack_h(p0, p1);
            pah[kt][o + 1] = pack_h(p2, p3);
        }
        sum0 += __shfl_xor_sync(0xffffffffu, sum0, 1);
        sum0 += __shfl_xor_sync(0xffffffffu, sum0, 2);
        sum1 += __shfl_xor_sync(0xffffffffu, sum1, 1);
        sum1 += __shfl_xor_sync(0xffffffffu, sum1, 2);
        l0 = l0 * rs0 + sum0;
        l1 = l1 * rs1 + sum1;
        m0 = mn0;
        m1 = mn1;

        // rescale O (skip when max unchanged across the whole warp)
        if (!__all_sync(0xffffffffu, (rs0 == 1.0f) && (rs1 == 1.0f))) {
            #pragma unroll
            for (int nt = 0; nt < 8; nt++) {
                oacc[nt][0] *= rs0;
                oacc[nt][1] *= rs0;
                oacc[nt][2] *= rs1;
                oacc[nt][3] *= rs1;
            }
        }

        // ---- tensor stream: PV_j (1-product) ----
        const uint32_t vb = sb + SMKV + (j % 3) * STAGEB + KO_VH;
        #pragma unroll
        for (int ks = 0; ks < 4; ks++) {
            #pragma unroll
            for (int ng = 0; ng < 4; ng++) {
                uint32_t vhf[4];
                const uint32_t voff =
                    (uint32_t)((ks * 16 + v_krow) * AROW + (ng * 16 + v_noff) * 2);
                LDSM4T(vhf, vb + voff);
                MMA16816(oacc[2 * ng], pah[ks], &vhf[0]);
                MMA16816(oacc[2 * ng + 1], pah[ks], &vhf[2]);
            }
        }
    };

    // prologue QK_0, then pipelined pairs (nkv is even)
    qk_tile(0, sA);
    for (int jj = 0; jj < nkv; jj += 2) {
        body(jj, sA, sB);
        body(jj + 1, sB, sA);
    }

    // ---- epilogue: normalize, split to (hi, lo) fp16, write [m, c] ----
    const float inv0 = 1.0f / l0;
    const float inv1 = 1.0f / l1;
    const int b = bh >> 4;
    const int h = bh & 15;
    const int trow0 = q0 + wm + r0;
    const int trow1 = trow0 + 8;
    #pragma unroll
    for (int nt = 0; nt < 8; nt++) {
        const int col = h * DH + nt * 8 + cb;
        uint32_t hp, lp;
        pack_split_h(oacc[nt][0] * inv0, oacc[nt][1] * inv0, hp, lp);
        const size_t idx0 = ((size_t)b * TT + trow0) * CC + col;
        *(uint32_t*)&Ohi[idx0] = hp;
        *(uint32_t*)&Olo[idx0] = lp;
        pack_split_h(oacc[nt][2] * inv1, oacc[nt][3] * inv1, hp, lp);
        const size_t idx1 = ((size_t)b * TT + trow1) * CC + col;
        *(uint32_t*)&Ohi[idx1] = hp;
        *(uint32_t*)&Olo[idx1] = lp;
    }
}

// ---------------------------------------------------------------------------
// Launch
// ---------------------------------------------------------------------------
extern "C" void kernel_launch(void* const* d_in, const int* in_sizes, int n_in,
                              void* d_out, int out_size)
{
    const float* x   = (const float*)d_in[0];
    const float* W_Q = (const float*)d_in[1];
    const float* W_K = (const float*)d_in[2];
    const float* W_V = (const float*)d_in[3];
    const float* W_O = (const float*)d_in[4];
    float* out = (float*)d_out;

    __half *xhi, *xlo, *wh;
    __half *qh, *ql, *kh, *vh, *ah, *al;
    cudaGetSymbolAddress((void**)&xhi, g_xhi);
    cudaGetSymbolAddress((void**)&xlo, g_xlo);
    cudaGetSymbolAddress((void**)&wh, g_wh);
    cudaGetSymbolAddress((void**)&qh, g_qhi);
    cudaGetSymbolAddress((void**)&ql, g_qlo);
    cudaGetSymbolAddress((void**)&kh, g_khi);
    cudaGetSymbolAddress((void**)&vh, g_vhi);
    cudaGetSymbolAddress((void**)&ah, g_ahi);
    cudaGetSymbolAddress((void**)&al, g_alo);

    cudaFuncSetAttribute(gemm_tc_kernel,
                         cudaFuncAttributeMaxDynamicSharedMemorySize, GEMM_SMEM);
    cudaFuncSetAttribute(flash_attn_tc_kernel,
                         cudaFuncAttributeMaxDynamicSharedMemorySize, ATTN_SMEM);

    const size_t WSZ = (size_t)CC * CC;
    const int nx4 = (MM * CC) / 4;
    const int nw4 = (CC * CC) / 4;

    split_h_kernel<<<(nx4 + 255) / 256, 256>>>(x, xhi, xlo, 1.0f, 1, nx4);
    const float* Ws[4] = {W_Q, W_K, W_V, W_O};
    for (int i = 0; i < 4; i++)
        split_h_kernel<<<(nw4 + 255) / 256, 256>>>(Ws[i], wh + i * WSZ,
                                                   nullptr, 32.0f, 0, nw4);

    dim3 qkv_grid(3 * CC / BN, MM / BM);   // (24, 64)
    gemm_tc_kernel<<<qkv_grid, 256, GEMM_SMEM>>>(
        xhi, xlo, wh, nullptr, qh, ql, kh, vh, 1);

    dim3 attn_grid(TT / 128, BB * HH);     // (16, 64)
    flash_attn_tc_kernel<<<attn_grid, 256, ATTN_SMEM>>>(
        qh, ql, kh, vh, ah, al);

    dim3 out_grid(CC / BN, MM / BM);       // (8, 64)
    gemm_tc_kernel<<<out_grid, 256, GEMM_SMEM>>>(
        ah, al, wh + 3 * WSZ, out, nullptr, nullptr, nullptr, nullptr, 0);
}

// round 8
// speedup vs baseline: 4.5103x; 1.0206x over previous
#include <cuda_runtime.h>
#include <cuda_fp16.h>
#include <cstdint>

// Problem constants
#define BB 4
#define TT 2048
#define HH 16
#define DH 64
#define CC 1024
#define MM (BB * TT)   // 8192 rows

// ---------------------------------------------------------------------------
// Scratch (device globals -- allocation-free per harness rules)
// ---------------------------------------------------------------------------
static __device__ __align__(16) __half g_xhi[(size_t)MM * CC];
static __device__ __align__(16) __half g_xlo[(size_t)MM * CC];
static __device__ __align__(16) __half g_wh[4][(size_t)CC * CC];
static __device__ __align__(16) __half g_qhi[(size_t)MM * CC];
static __device__ __align__(16) __half g_qlo[(size_t)MM * CC];
static __device__ __align__(16) __half g_khi[(size_t)MM * CC];
static __device__ __align__(16) __half g_vhi[(size_t)MM * CC];
static __device__ __align__(16) __half g_ahi[(size_t)MM * CC];
static __device__ __align__(16) __half g_alo[(size_t)MM * CC];

// ---------------------------------------------------------------------------
// PTX helpers (sm_80+ portable -- compute_103 safe)
// ---------------------------------------------------------------------------
__device__ __forceinline__ uint32_t smem_u32(const void* p) {
    uint32_t a;
    asm("{ .reg .u64 t; cvta.to.shared.u64 t, %1; cvt.u32.u64 %0, t; }"
        : "=r"(a) : "l"(p));
    return a;
}

#define CP_ASYNC16(saddr, gaddr) \
    asm volatile("cp.async.cg.shared.global [%0], [%1], 16;" \
                 :: "r"(saddr), "l"(gaddr))
#define CP_COMMIT() asm volatile("cp.async.commit_group;" ::: "memory")
#define CP_WAIT0()  asm volatile("cp.async.wait_group 0;" ::: "memory")
#define CP_WAIT1()  asm volatile("cp.async.wait_group 1;" ::: "memory")

#define LDSM4(r, addr)                                                          \
    asm volatile("ldmatrix.sync.aligned.m8n8.x4.shared.b16 {%0,%1,%2,%3}, [%4];"\
                 : "=r"((r)[0]), "=r"((r)[1]), "=r"((r)[2]), "=r"((r)[3])       \
                 : "r"(addr))

#define LDSM4T(r, addr)                                                         \
    asm volatile("ldmatrix.sync.aligned.m8n8.x4.trans.shared.b16 {%0,%1,%2,%3}, [%4];" \
                 : "=r"((r)[0]), "=r"((r)[1]), "=r"((r)[2]), "=r"((r)[3])       \
                 : "r"(addr))

#define MMA16816(c, a, b)                                                       \
    asm volatile("mma.sync.aligned.m16n8k16.row.col.f32.f16.f16.f32 "           \
                 "{%0,%1,%2,%3}, {%4,%5,%6,%7}, {%8,%9}, {%0,%1,%2,%3};"        \
                 : "+f"((c)[0]), "+f"((c)[1]), "+f"((c)[2]), "+f"((c)[3])       \
                 : "r"((a)[0]), "r"((a)[1]), "r"((a)[2]), "r"((a)[3]),          \
                   "r"((b)[0]), "r"((b)[1]))

// exp2(y) for y <= 0, FMA/ALU pipes only (no MUFU). |rel err| ~2e-6.
__device__ __forceinline__ float fexp2(float y) {
    y = fmaxf(y, -126.0f);
    float t = __fadd_rn(y, 12582912.0f);
    int   e = __float_as_int(t) << 23;
    float f = __fsub_rn(y, __fsub_rn(t, 12582912.0f));
    float p =              1.3333558146e-3f;
    p = fmaf(p, f, 9.6181291077e-3f);
    p = fmaf(p, f, 5.5504108664e-2f);
    p = fmaf(p, f, 2.4022650696e-1f);
    p = fmaf(p, f, 6.9314718056e-1f);
    p = fmaf(p, f, 1.0f);
    return __uint_as_float((uint32_t)(__float_as_int(p) + e));
}

// fp32 pair -> packed fp16 hi pair (RN) + fp16 lo pair (residual, RN)
__device__ __forceinline__ void pack_split_h(float v0, float v1,
                                             uint32_t& hi, uint32_t& lo) {
    __half2 h = __floats2half2_rn(v0, v1);
    hi = *(uint32_t*)&h;
    float h0 = __half2float(__low2half(h));
    float h1 = __half2float(__high2half(h));
    __half2 l = __floats2half2_rn(v0 - h0, v1 - h1);
    lo = *(uint32_t*)&l;
}

__device__ __forceinline__ uint32_t pack_h(float v0, float v1) {
    __half2 h = __floats2half2_rn(v0, v1);
    return *(uint32_t*)&h;
}

// ---------------------------------------------------------------------------
// fp32 -> (hi, lo) fp16 split with optional prescale; lo write optional
// ---------------------------------------------------------------------------
__global__ void __launch_bounds__(256) split_h_kernel(
    const float* __restrict__ in, __half* __restrict__ hi,
    __half* __restrict__ lo, float prescale, int write_lo, int n4)
{
    int i = blockIdx.x * 256 + threadIdx.x;
    if (i >= n4) return;
    float4 v = ((const float4*)in)[i];
    v.x *= prescale; v.y *= prescale; v.z *= prescale; v.w *= prescale;
    uint32_t h01, l01, h23, l23;
    pack_split_h(v.x, v.y, h01, l01);
    pack_split_h(v.z, v.w, h23, l23);
    ((uint2*)hi)[i] = make_uint2(h01, h23);
    if (write_lo) ((uint2*)lo)[i] = make_uint2(l01, l23);
}

// ---------------------------------------------------------------------------
// 2-product fp16 tensor-core GEMM: Y = (Ahi+Alo) @ Bh^T * 1/32
// mode 1 (fused QKV): grid.x = 24; gsel picks W and destination.
// mode 0: grid.x = 8; fp32 out to Yf in [m, n] layout
// ---------------------------------------------------------------------------
#define BM 128
#define BN 128
#define BK 32
#define NK (CC / BK)
#define ROWB 80
#define SUBT (128 * ROWB)       // 10240
#define BUFB (3 * SUBT)         // 30720 (Ahi, Alo, Bh)
#define GEMM_SMEM 67584
#define INV32 0.03125f

__device__ __forceinline__ void load_chunk_async(
    uint32_t sb, int buf, int tid,
    const __half* __restrict__ Ahi, const __half* __restrict__ Alo,
    const __half* __restrict__ Bh, int m0, int n0, int k0)
{
    const uint32_t base = sb + buf * BUFB;
    const __half* gps[3] = {Ahi, Alo, Bh};
    const int rb[3] = {m0, m0, n0};
    #pragma unroll
    for (int it = 0; it < 6; it++) {
        const int sub = it >> 1;
        const int j = (it & 1) * 256 + tid;
        const int row = j >> 2;
        const int c16 = j & 3;
        const uint32_t saddr = base + sub * SUBT + row * ROWB + c16 * 16;
        const void* gaddr = gps[sub] + (size_t)(rb[sub] + row) * CC + k0 + c16 * 8;
        CP_ASYNC16(saddr, gaddr);
    }
}

__global__ void __launch_bounds__(256) gemm_tc_kernel(
    const __half* __restrict__ Ahi, const __half* __restrict__ Alo,
    const __half* __restrict__ Wbase,
    float* __restrict__ Yf,
    __half* __restrict__ Yq_hi, __half* __restrict__ Yq_lo,
    __half* __restrict__ Yk_hi, __half* __restrict__ Yv_hi,
    int mode)
{
    extern __shared__ char smem[];
    const uint32_t sb = smem_u32(smem);
    const int tid = threadIdx.x;
    const int lane = tid & 31;
    const int wid = tid >> 5;
    const int wm = (wid >> 2) * 64;
    const int wn = (wid & 3) * 32;

    int gsel = 0, nblk = blockIdx.x;
    if (mode == 1) { gsel = blockIdx.x >> 3; nblk = blockIdx.x & 7; }
    const int n0 = nblk * BN;
    const int m0 = blockIdx.y * BM;
    const __half* Bh = Wbase + (size_t)gsel * CC * CC;

    __half* Yhi = nullptr; __half* Ylo = nullptr;
    if (mode == 1) {
        if (gsel == 0)      { Yhi = Yq_hi; Ylo = Yq_lo; }
        else if (gsel == 1) { Yhi = Yk_hi; }
        else                { Yhi = Yv_hi; }
    }

    float acc[4][4][4] = {};

    load_chunk_async(sb, 0, tid, Ahi, Alo, Bh, m0, n0, 0);
    CP_COMMIT();

    const int a_row = (lane & 15);
    const int a_koff = (lane >> 4) << 3;
    const int b_row = ((lane >> 4) << 3) + (lane & 7);
    const int b_koff = ((lane >> 3) & 1) << 3;

    for (int c = 0; c < NK; c++) {
        CP_WAIT0();
        __syncthreads();
        if (c + 1 < NK) {
            load_chunk_async(sb, (c + 1) & 1, tid, Ahi, Alo, Bh,
                             m0, n0, (c + 1) * BK);
            CP_COMMIT();
        }

        const uint32_t ab = sb + (c & 1) * BUFB;
        const uint32_t bb = ab + 2 * SUBT;

        #pragma unroll
        for (int ks = 0; ks < 2; ks++) {
            uint32_t ah[16], al[16], bh[8];
            #pragma unroll
            for (int mt = 0; mt < 4; mt++) {
                const uint32_t off =
                    (uint32_t)((wm + mt * 16 + a_row) * ROWB + (ks * 16 + a_koff) * 2);
                LDSM4(&ah[mt * 4], ab + off);
                LDSM4(&al[mt * 4], ab + SUBT + off);
            }
            #pragma unroll
            for (int nt2 = 0; nt2 < 2; nt2++) {
                const uint32_t off =
                    (uint32_t)((wn + nt2 * 16 + b_row) * ROWB + (ks * 16 + b_koff) * 2);
                LDSM4(&bh[nt2 * 4], bb + off);
            }
            #pragma unroll
            for (int mt = 0; mt < 4; mt++)
                #pragma unroll
                for (int nt = 0; nt < 4; nt++) {
                    float* cc = acc[mt][nt];
                    MMA16816(cc, &ah[mt * 4], &bh[nt * 2]);
                    MMA16816(cc, &al[mt * 4], &bh[nt * 2]);
                }
        }
        __syncthreads();
    }

    // epilogue
    float* es = (float*)smem;   // [128][132]
    const int er = lane >> 2;
    const int ec = (lane & 3) * 2;
    #pragma unroll
    for (int mt = 0; mt < 4; mt++)
        #pragma unroll
        for (int nt = 0; nt < 4; nt++) {
            const int r = wm + mt * 16 + er;
            const int cl = wn + nt * 8 + ec;
            *(float2*)&es[r * 132 + cl] =
                make_float2(acc[mt][nt][0] * INV32, acc[mt][nt][1] * INV32);
            *(float2*)&es[(r + 8) * 132 + cl] =
                make_float2(acc[mt][nt][2] * INV32, acc[mt][nt][3] * INV32);
        }
    __syncthreads();

    #pragma unroll
    for (int it = 0; it < 16; it++) {
        const int i = tid + it * 256;
        const int r = i >> 5;
        const int c4 = (i & 31) * 4;
        float4 v = *(float4*)&es[r * 132 + c4];
        const int m = m0 + r;
        const int n = n0 + c4;
        if (mode == 1) {
            const int b = m >> 11, t = m & 2047, h = n >> 6, d = n & 63;
            const size_t idx = (((size_t)(b * HH + h) * TT) + t) * DH + d;
            uint32_t h01, l01, h23, l23;
            pack_split_h(v.x, v.y, h01, l01);
            pack_split_h(v.z, v.w, h23, l23);
            *(uint2*)&Yhi[idx] = make_uint2(h01, h23);
            if (Ylo) *(uint2*)&Ylo[idx] = make_uint2(l01, l23);
        } else {
            *(float4*)&Yf[(size_t)m * CC + n] = v;
        }
    }
}

// ---------------------------------------------------------------------------
// Tensor-core flash attention (causal), 2 CTAs/SM.
//   S = (Qhi + Qlo) K^T  (2-product),  O = P_hi V  (1-product).
// Q fragments live in registers (loaded once, MMA A-layout). 3-stage KV smem,
// ONE __syncthreads per KV tile. 55 KB smem + <=128 regs -> occupancy 2.
// ---------------------------------------------------------------------------
#define AROW 144
#define STAGEB (2 * 64 * AROW)       // 18432 (K + V)
#define KO_KH 0
#define KO_VH (64 * AROW)            // 9216
#define ATTN_SMEM (3 * STAGEB)       // 55296
#define SCALE_L2E 0.1803368801111763f  // 0.125 * log2(e)

__device__ __forceinline__ void load_kv_stage(
    uint32_t sb, int stage, int tid, size_t gbase, int kv0,
    const __half* __restrict__ khi, const __half* __restrict__ vhi)
{
    const uint32_t base = sb + stage * STAGEB;
    const __half* gps[2] = {khi, vhi};
    #pragma unroll
    for (int it = 0; it < 4; it++) {
        const int idx = tid + it * 256;         // 0..1023
        const int arr = idx >> 9;               // 0..1
        const int r = (idx >> 3) & 63;
        const int c = idx & 7;
        const uint32_t dst = base + arr * (64 * AROW) + r * AROW + c * 16;
        CP_ASYNC16(dst, gps[arr] + gbase + (size_t)(kv0 + r) * DH + c * 8);
    }
}

__global__ void __launch_bounds__(256, 2) flash_attn_tc_kernel(
    const __half* __restrict__ qhi, const __half* __restrict__ qlo,
    const __half* __restrict__ khi, const __half* __restrict__ vhi,
    __half* __restrict__ Ohi, __half* __restrict__ Olo)
{
    extern __shared__ char smem[];
    const uint32_t sb = smem_u32(smem);
    const int tid = threadIdx.x;
    const int lane = tid & 31;
    const int wid = tid >> 5;
    const int wm = wid * 16;
    const int qi = 15 - (int)blockIdx.x;     // heavy tiles first
    const int bh = blockIdx.y;
    const int q0 = qi * 128;
    const size_t gbase = (size_t)bh * TT * DH;

    // ldmatrix lane offsets (K, V)
    const int b_row = ((lane >> 4) << 3) + (lane & 7);
    const int b_koff = ((lane >> 3) & 1) << 3;
    const int v_krow = (lane & 7) + (((lane >> 3) & 1) << 3);
    const int v_noff = (lane >> 4) << 3;

    const int r0 = lane >> 2;
    const int cb = (lane & 3) * 2;
    const int tq0 = q0 + wm + r0;
    const int nkv = 2 * qi + 2;              // always even

    // ---- Q fragments in registers (MMA A-layout), loaded once ----
    uint32_t qfh[4][4], qfl[4][4];
    {
        const size_t rA = gbase + (size_t)(q0 + wm + r0) * DH;
        const size_t rB = gbase + (size_t)(q0 + wm + r0 + 8) * DH;
        #pragma unroll
        for (int ks = 0; ks < 4; ks++) {
            const int c0 = ks * 16 + cb;
            qfh[ks][0] = *(const uint32_t*)(qhi + rA + c0);
            qfh[ks][1] = *(const uint32_t*)(qhi + rB + c0);
            qfh[ks][2] = *(const uint32_t*)(qhi + rA + c0 + 8);
            qfh[ks][3] = *(const uint32_t*)(qhi + rB + c0 + 8);
            qfl[ks][0] = *(const uint32_t*)(qlo + rA + c0);
            qfl[ks][1] = *(const uint32_t*)(qlo + rB + c0);
            qfl[ks][2] = *(const uint32_t*)(qlo + rA + c0 + 8);
            qfl[ks][3] = *(const uint32_t*)(qlo + rB + c0 + 8);
        }
    }

    // prologue: stages 0, 1
    load_kv_stage(sb, 0, tid, gbase, 0, khi, vhi);
    CP_COMMIT();
    if (nkv > 1) {
        load_kv_stage(sb, 1, tid, gbase, 64, khi, vhi);
        CP_COMMIT();
        CP_WAIT1();
    } else {
        CP_WAIT0();
    }
    __syncthreads();

    float m0 = -1e30f, m1 = -1e30f, l0 = 0.0f, l1 = 0.0f;
    float oacc[8][4] = {};

    for (int j = 0; j < nkv; j++) {
        const uint32_t stb = sb + (j % 3) * STAGEB;
        const bool pre = (j + 2 < nkv);
        if (pre) {
            load_kv_stage(sb, (j + 2) % 3, tid, gbase, (j + 2) * 64, khi, vhi);
            CP_COMMIT();
        }

        // ---- S = Q K^T (2-product), Q from registers ----
        float s[8][4];
        #pragma unroll
        for (int nt = 0; nt < 8; nt++)
            #pragma unroll
            for (int e = 0; e < 4; e++) s[nt][e] = 0.0f;
        #pragma unroll
        for (int ks = 0; ks < 4; ks++) {
            #pragma unroll
            for (int ng = 0; ng < 4; ng++) {
                uint32_t bhf[4];
                const uint32_t boff =
                    (uint32_t)((ng * 16 + b_row) * AROW + (ks * 16 + b_koff) * 2);
                LDSM4(bhf, stb + KO_KH + boff);
                float* s0 = s[2 * ng];
                float* s1 = s[2 * ng + 1];
                MMA16816(s0, qfh[ks], &bhf[0]);
                MMA16816(s0, qfl[ks], &bhf[0]);
                MMA16816(s1, qfh[ks], &bhf[2]);
                MMA16816(s1, qfl[ks], &bhf[2]);
            }
        }

        // ---- scale (log2 domain) + causal mask ----
        const int kv0 = j * 64;
        const bool needmask = (kv0 + 63 > q0 + wm);
        #pragma unroll
        for (int nt = 0; nt < 8; nt++)
            #pragma unroll
            for (int e = 0; e < 4; e++) {
                float z = s[nt][e] * SCALE_L2E;
                if (needmask) {
                    const int tk = kv0 + nt * 8 + cb + (e & 1);
                    const int tq = tq0 + ((e >> 1) << 3);
                    if (tk > tq) z = -1e30f;
                }
                s[nt][e] = z;
            }

        // ---- online softmax ----
        float zm0 = -1e30f, zm1 = -1e30f;
        #pragma unroll
        for (int nt = 0; nt < 8; nt++) {
            zm0 = fmaxf(zm0, fmaxf(s[nt][0], s[nt][1]));
            zm1 = fmaxf(zm1, fmaxf(s[nt][2], s[nt][3]));
        }
        zm0 = fmaxf(zm0, __shfl_xor_sync(0xffffffffu, zm0, 1));
        zm0 = fmaxf(zm0, __shfl_xor_sync(0xffffffffu, zm0, 2));
        zm1 = fmaxf(zm1, __shfl_xor_sync(0xffffffffu, zm1, 1));
        zm1 = fmaxf(zm1, __shfl_xor_sync(0xffffffffu, zm1, 2));
        const float mn0 = fmaxf(m0, zm0);
        const float mn1 = fmaxf(m1, zm1);
        const float rs0 = fexp2(m0 - mn0);
        const float rs1 = fexp2(m1 - mn1);
        float sum0 = 0.0f, sum1 = 0.0f;
        uint32_t pah[4][4];
        #pragma unroll
        for (int nt = 0; nt < 8; nt++) {
            float p0 = fexp2(s[nt][0] - mn0);
            float p1 = fexp2(s[nt][1] - mn0);
            float p2 = fexp2(s[nt][2] - mn1);
            float p3 = fexp2(s[nt][3] - mn1);
            sum0 += p0 + p1;
            sum1 += p2 + p3;
            const int kt = nt >> 1;
            const int o = (nt & 1) << 1;
            pah[kt][o]     = pack_h(p0, p1);
            pah[kt][o + 1] = pack_h(p2, p3);
        }
        sum0 += __shfl_xor_sync(0xffffffffu, sum0, 1);
        sum0 += __shfl_xor_sync(0xffffffffu, sum0, 2);
        sum1 += __shfl_xor_sync(0xffffffffu, sum1, 1);
        sum1 += __shfl_xor_sync(0xffffffffu, sum1, 2);
        l0 = l0 * rs0 + sum0;
        l1 = l1 * rs1 + sum1;
        m0 = mn0;
        m1 = mn1;

        // rescale O (skip when max unchanged across the whole warp)
        if (!__all_sync(0xffffffffu, (rs0 == 1.0f) && (rs1 == 1.0f))) {
            #pragma unroll
            for (int nt = 0; nt < 8; nt++) {
                oacc[nt][0] *= rs0;
                oacc[nt][1] *= rs0;
                oacc[nt][2] *= rs1;
                oacc[nt][3] *= rs1;
            }
        }

        // ---- O += P V (1-product), V via ldmatrix.trans ----
        #pragma unroll
        for (int ks = 0; ks < 4; ks++) {
            #pragma unroll
            for (int ng = 0; ng < 4; ng++) {
                uint32_t vhf[4];
                const uint32_t voff =
                    (uint32_t)((ks * 16 + v_krow) * AROW + (ng * 16 + v_noff) * 2);
                LDSM4T(vhf, stb + KO_VH + voff);
                MMA16816(oacc[2 * ng], pah[ks], &vhf[0]);
                MMA16816(oacc[2 * ng + 1], pah[ks], &vhf[2]);
            }
        }

        // stage j+1 ready before next iteration; sync marks stage j reusable
        if (j + 1 < nkv) {
            if (pre) { CP_WAIT1(); } else { CP_WAIT0(); }
        }
        __syncthreads();
    }

    // ---- epilogue: normalize, split to (hi, lo) fp16, write [m, c] ----
    const float inv0 = 1.0f / l0;
    const float inv1 = 1.0f / l1;
    const int b = bh >> 4;
    const int h = bh & 15;
    const int trow0 = q0 + wm + r0;
    const int trow1 = trow0 + 8;
    #pragma unroll
    for (int nt = 0; nt < 8; nt++) {
        const int col = h * DH + nt * 8 + cb;
        uint32_t hp, lp;
        pack_split_h(oacc[nt][0] * inv0, oacc[nt][1] * inv0, hp, lp);
        const size_t idx0 = ((size_t)b * TT + trow0) * CC + col;
        *(uint32_t*)&Ohi[idx0] = hp;
        *(uint32_t*)&Olo[idx0] = lp;
        pack_split_h(oacc[nt][2] * inv1, oacc[nt][3] * inv1, hp, lp);
        const size_t idx1 = ((size_t)b * TT + trow1) * CC + col;
        *(uint32_t*)&Ohi[idx1] = hp;
        *(uint32_t*)&Olo[idx1] = lp;
    }
}

// ---------------------------------------------------------------------------
// Launch
// ---------------------------------------------------------------------------
extern "C" void kernel_launch(void* const* d_in, const int* in_sizes, int n_in,
                              void* d_out, int out_size)
{
    const float* x   = (const float*)d_in[0];
    const float* W_Q = (const float*)d_in[1];
    const float* W_K = (const float*)d_in[2];
    const float* W_V = (const float*)d_in[3];
    const float* W_O = (const float*)d_in[4];
    float* out = (float*)d_out;

    __half *xhi, *xlo, *wh;
    __half *qh, *ql, *kh, *vh, *ah, *al;
    cudaGetSymbolAddress((void**)&xhi, g_xhi);
    cudaGetSymbolAddress((void**)&xlo, g_xlo);
    cudaGetSymbolAddress((void**)&wh, g_wh);
    cudaGetSymbolAddress((void**)&qh, g_qhi);
    cudaGetSymbolAddress((void**)&ql, g_qlo);
    cudaGetSymbolAddress((void**)&kh, g_khi);
    cudaGetSymbolAddress((void**)&vh, g_vhi);
    cudaGetSymbolAddress((void**)&ah, g_ahi);
    cudaGetSymbolAddress((void**)&al, g_alo);

    cudaFuncSetAttribute(gemm_tc_kernel,
                         cudaFuncAttributeMaxDynamicSharedMemorySize, GEMM_SMEM);
    cudaFuncSetAttribute(flash_attn_tc_kernel,
                         cudaFuncAttributeMaxDynamicSharedMemorySize, ATTN_SMEM);

    const size_t WSZ = (size_t)CC * CC;
    const int nx4 = (MM * CC) / 4;
    const int nw4 = (CC * CC) / 4;

    split_h_kernel<<<(nx4 + 255) / 256, 256>>>(x, xhi, xlo, 1.0f, 1, nx4);
    const float* Ws[4] = {W_Q, W_K, W_V, W_O};
    for (int i = 0; i < 4; i++)
        split_h_kernel<<<(nw4 + 255) / 256, 256>>>(Ws[i], wh + i * WSZ,
                                                   nullptr, 32.0f, 0, nw4);

    dim3 qkv_grid(3 * CC / BN, MM / BM);   // (24, 64)
    gemm_tc_kernel<<<qkv_grid, 256, GEMM_SMEM>>>(
        xhi, xlo, wh, nullptr, qh, ql, kh, vh, 1);

    dim3 attn_grid(TT / 128, BB * HH);     // (16, 64)
    flash_attn_tc_kernel<<<attn_grid, 256, ATTN_SMEM>>>(
        qh, ql, kh, vh, ah, al);

    dim3 out_grid(CC / BN, MM / BM);       // (8, 64)
    gemm_tc_kernel<<<out_grid, 256, GEMM_SMEM>>>(
        ah, al, wh + 3 * WSZ, out, nullptr, nullptr, nullptr, nullptr, 0);
}

// round 9
// speedup vs baseline: 5.9543x; 1.3202x over previous
#include <cuda_runtime.h>
#include <cuda_fp16.h>
#include <cstdint>

// Problem constants
#define BB 4
#define TT 2048
#define HH 16
#define DH 64
#define CC 1024
#define MM (BB * TT)   // 8192 rows

// ---------------------------------------------------------------------------
// Scratch (device globals -- allocation-free per harness rules)
// ---------------------------------------------------------------------------
static __device__ __align__(16) __half g_xhi[(size_t)MM * CC];
static __device__ __align__(16) __half g_wh[4][(size_t)CC * CC];
static __device__ __align__(16) __half g_qhi[(size_t)MM * CC];
static __device__ __align__(16) __half g_khi[(size_t)MM * CC];
static __device__ __align__(16) __half g_vhi[(size_t)MM * CC];
static __device__ __align__(16) __half g_ahi[(size_t)MM * CC];
static __device__ __align__(16) __half g_alo[(size_t)MM * CC];

// ---------------------------------------------------------------------------
// PTX helpers (sm_80+ portable -- compute_103 safe)
// ---------------------------------------------------------------------------
__device__ __forceinline__ uint32_t smem_u32(const void* p) {
    uint32_t a;
    asm("{ .reg .u64 t; cvta.to.shared.u64 t, %1; cvt.u32.u64 %0, t; }"
        : "=r"(a) : "l"(p));
    return a;
}

#define CP_ASYNC16(saddr, gaddr) \
    asm volatile("cp.async.cg.shared.global [%0], [%1], 16;" \
                 :: "r"(saddr), "l"(gaddr))
#define CP_COMMIT() asm volatile("cp.async.commit_group;" ::: "memory")
#define CP_WAIT0()  asm volatile("cp.async.wait_group 0;" ::: "memory")
#define CP_WAIT1()  asm volatile("cp.async.wait_group 1;" ::: "memory")

#define LDSM4(r, addr)                                                          \
    asm volatile("ldmatrix.sync.aligned.m8n8.x4.shared.b16 {%0,%1,%2,%3}, [%4];"\
                 : "=r"((r)[0]), "=r"((r)[1]), "=r"((r)[2]), "=r"((r)[3])       \
                 : "r"(addr))

#define LDSM4T(r, addr)                                                         \
    asm volatile("ldmatrix.sync.aligned.m8n8.x4.trans.shared.b16 {%0,%1,%2,%3}, [%4];" \
                 : "=r"((r)[0]), "=r"((r)[1]), "=r"((r)[2]), "=r"((r)[3])       \
                 : "r"(addr))

#define MMA16816(c, a, b)                                                       \
    asm volatile("mma.sync.aligned.m16n8k16.row.col.f32.f16.f16.f32 "           \
                 "{%0,%1,%2,%3}, {%4,%5,%6,%7}, {%8,%9}, {%0,%1,%2,%3};"        \
                 : "+f"((c)[0]), "+f"((c)[1]), "+f"((c)[2]), "+f"((c)[3])       \
                 : "r"((a)[0]), "r"((a)[1]), "r"((a)[2]), "r"((a)[3]),          \
                   "r"((b)[0]), "r"((b)[1]))

// exp2(y) for y <= 0, FMA/ALU pipes only (no MUFU). |rel err| ~2e-6.
__device__ __forceinline__ float fexp2(float y) {
    y = fmaxf(y, -126.0f);
    float t = __fadd_rn(y, 12582912.0f);
    int   e = __float_as_int(t) << 23;
    float f = __fsub_rn(y, __fsub_rn(t, 12582912.0f));
    float p =              1.3333558146e-3f;
    p = fmaf(p, f, 9.6181291077e-3f);
    p = fmaf(p, f, 5.5504108664e-2f);
    p = fmaf(p, f, 2.4022650696e-1f);
    p = fmaf(p, f, 6.9314718056e-1f);
    p = fmaf(p, f, 1.0f);
    return __uint_as_float((uint32_t)(__float_as_int(p) + e));
}

// fp32 pair -> packed fp16 hi pair (RN) + fp16 lo pair (residual, RN)
__device__ __forceinline__ void pack_split_h(float v0, float v1,
                                             uint32_t& hi, uint32_t& lo) {
    __half2 h = __floats2half2_rn(v0, v1);
    hi = *(uint32_t*)&h;
    float h0 = __half2float(__low2half(h));
    float h1 = __half2float(__high2half(h));
    __half2 l = __floats2half2_rn(v0 - h0, v1 - h1);
    lo = *(uint32_t*)&l;
}

__device__ __forceinline__ uint32_t pack_h(float v0, float v1) {
    __half2 h = __floats2half2_rn(v0, v1);
    return *(uint32_t*)&h;
}

// ---------------------------------------------------------------------------
// fp32 -> fp16 (hi; optional lo) with prescale
// ---------------------------------------------------------------------------
__global__ void __launch_bounds__(256) split_h_kernel(
    const float* __restrict__ in, __half* __restrict__ hi,
    __half* __restrict__ lo, float prescale, int write_lo, int n4)
{
    int i = blockIdx.x * 256 + threadIdx.x;
    if (i >= n4) return;
    float4 v = ((const float4*)in)[i];
    v.x *= prescale; v.y *= prescale; v.z *= prescale; v.w *= prescale;
    uint32_t h01, l01, h23, l23;
    pack_split_h(v.x, v.y, h01, l01);
    pack_split_h(v.z, v.w, h23, l23);
    ((uint2*)hi)[i] = make_uint2(h01, h23);
    if (write_lo) ((uint2*)lo)[i] = make_uint2(l01, l23);
}

// ---------------------------------------------------------------------------
// fp16 tensor-core GEMM, NPROD in {1, 2}:
//   NPROD=2: Y = (Ahi + Alo) @ Bh^T * 1/32   (W_O path, fp32 out [m, n])
//   NPROD=1: Y = Ahi @ Bh^T * 1/32           (QKV path, fp16-hi out [b,h,t,d])
// QKV (mode 1): grid.x = 24, gsel = blockIdx.x>>3 picks W + destination.
// ---------------------------------------------------------------------------
#define BM 128
#define BN 128
#define BK 32
#define NK (CC / BK)
#define ROWB 80
#define SUBT (128 * ROWB)       // 10240
#define GEMM_SMEM 67584
#define INV32 0.03125f

template <int NPROD>
__device__ __forceinline__ void load_chunk_async(
    uint32_t sb, int buf, int tid,
    const __half* __restrict__ Ahi, const __half* __restrict__ Alo,
    const __half* __restrict__ Bh, int m0, int n0, int k0)
{
    const int nsub = NPROD + 1;
    const uint32_t base = sb + buf * (nsub * SUBT);
    const __half* gps[3];
    int rb[3];
    if (NPROD == 2) {
        gps[0] = Ahi; gps[1] = Alo; gps[2] = Bh;
        rb[0] = m0; rb[1] = m0; rb[2] = n0;
    } else {
        gps[0] = Ahi; gps[1] = Bh;
        rb[0] = m0; rb[1] = n0;
    }
    #pragma unroll
    for (int it = 0; it < 2 * (NPROD + 1); it++) {
        const int sub = it >> 1;
        const int j = (it & 1) * 256 + tid;
        const int row = j >> 2;
        const int c16 = j & 3;
        const uint32_t saddr = base + sub * SUBT + row * ROWB + c16 * 16;
        const void* gaddr = gps[sub] + (size_t)(rb[sub] + row) * CC + k0 + c16 * 8;
        CP_ASYNC16(saddr, gaddr);
    }
}

template <int NPROD>
__global__ void __launch_bounds__(256) gemm_tc_kernel(
    const __half* __restrict__ Ahi, const __half* __restrict__ Alo,
    const __half* __restrict__ Wbase,
    float* __restrict__ Yf,
    __half* __restrict__ Yq_hi, __half* __restrict__ Yk_hi,
    __half* __restrict__ Yv_hi, int mode)
{
    extern __shared__ char smem[];
    const uint32_t sb = smem_u32(smem);
    const int tid = threadIdx.x;
    const int lane = tid & 31;
    const int wid = tid >> 5;
    const int wm = (wid >> 2) * 64;
    const int wn = (wid & 3) * 32;
    const int nsub = NPROD + 1;

    int gsel = 0, nblk = blockIdx.x;
    if (mode == 1) { gsel = blockIdx.x >> 3; nblk = blockIdx.x & 7; }
    const int n0 = nblk * BN;
    const int m0 = blockIdx.y * BM;
    const __half* Bh = Wbase + (size_t)gsel * CC * CC;

    __half* Yhi = nullptr;
    if (mode == 1) {
        if (gsel == 0)      Yhi = Yq_hi;
        else if (gsel == 1) Yhi = Yk_hi;
        else                Yhi = Yv_hi;
    }

    float acc[4][4][4] = {};

    load_chunk_async<NPROD>(sb, 0, tid, Ahi, Alo, Bh, m0, n0, 0);
    CP_COMMIT();

    const int a_row = (lane & 15);
    const int a_koff = (lane >> 4) << 3;
    const int b_row = ((lane >> 4) << 3) + (lane & 7);
    const int b_koff = ((lane >> 3) & 1) << 3;

    for (int c = 0; c < NK; c++) {
        CP_WAIT0();
        __syncthreads();
        if (c + 1 < NK) {
            load_chunk_async<NPROD>(sb, (c + 1) & 1, tid, Ahi, Alo, Bh,
                                    m0, n0, (c + 1) * BK);
            CP_COMMIT();
        }

        const uint32_t ab = sb + (c & 1) * (nsub * SUBT);
        const uint32_t bb = ab + NPROD * SUBT;

        #pragma unroll
        for (int ks = 0; ks < 2; ks++) {
            uint32_t ah[16], al[16], bh[8];
            #pragma unroll
            for (int mt = 0; mt < 4; mt++) {
                const uint32_t off =
                    (uint32_t)((wm + mt * 16 + a_row) * ROWB + (ks * 16 + a_koff) * 2);
                LDSM4(&ah[mt * 4], ab + off);
                if (NPROD == 2) LDSM4(&al[mt * 4], ab + SUBT + off);
            }
            #pragma unroll
            for (int nt2 = 0; nt2 < 2; nt2++) {
                const uint32_t off =
                    (uint32_t)((wn + nt2 * 16 + b_row) * ROWB + (ks * 16 + b_koff) * 2);
                LDSM4(&bh[nt2 * 4], bb + off);
            }
            #pragma unroll
            for (int mt = 0; mt < 4; mt++)
                #pragma unroll
                for (int nt = 0; nt < 4; nt++) {
                    float* cc = acc[mt][nt];
                    MMA16816(cc, &ah[mt * 4], &bh[nt * 2]);
                    if (NPROD == 2) MMA16816(cc, &al[mt * 4], &bh[nt * 2]);
                }
        }
        __syncthreads();
    }

    // epilogue: registers (x 1/32) -> smem staging -> coalesced global stores
    float* es = (float*)smem;   // [128][132]
    const int er = lane >> 2;
    const int ec = (lane & 3) * 2;
    #pragma unroll
    for (int mt = 0; mt < 4; mt++)
        #pragma unroll
        for (int nt = 0; nt < 4; nt++) {
            const int r = wm + mt * 16 + er;
            const int cl = wn + nt * 8 + ec;
            *(float2*)&es[r * 132 + cl] =
                make_float2(acc[mt][nt][0] * INV32, acc[mt][nt][1] * INV32);
            *(float2*)&es[(r + 8) * 132 + cl] =
                make_float2(acc[mt][nt][2] * INV32, acc[mt][nt][3] * INV32);
        }
    __syncthreads();

    #pragma unroll
    for (int it = 0; it < 16; it++) {
        const int i = tid + it * 256;
        const int r = i >> 5;
        const int c4 = (i & 31) * 4;
        float4 v = *(float4*)&es[r * 132 + c4];
        const int m = m0 + r;
        const int n = n0 + c4;
        if (mode == 1) {
            const int b = m >> 11, t = m & 2047, h = n >> 6, d = n & 63;
            const size_t idx = (((size_t)(b * HH + h) * TT) + t) * DH + d;
            *(uint2*)&Yhi[idx] =
                make_uint2(pack_h(v.x, v.y), pack_h(v.z, v.w));
        } else {
            *(float4*)&Yf[(size_t)m * CC + n] = v;
        }
    }
}

// ---------------------------------------------------------------------------
// Tensor-core flash attention (causal), all 1-product fp16, 2 CTAs/SM.
//   S = Q_hi K_hi^T,  O = P_hi V_hi.
// Q fragments in registers (loaded once). 3-stage KV smem, one sync per tile.
// ---------------------------------------------------------------------------
#define AROW 144
#define STAGEB (2 * 64 * AROW)       // 18432 (K + V)
#define KO_KH 0
#define KO_VH (64 * AROW)            // 9216
#define ATTN_SMEM (3 * STAGEB)       // 55296
#define SCALE_L2E 0.1803368801111763f  // 0.125 * log2(e)

__device__ __forceinline__ void load_kv_stage(
    uint32_t sb, int stage, int tid, size_t gbase, int kv0,
    const __half* __restrict__ khi, const __half* __restrict__ vhi)
{
    const uint32_t base = sb + stage * STAGEB;
    const __half* gps[2] = {khi, vhi};
    #pragma unroll
    for (int it = 0; it < 4; it++) {
        const int idx = tid + it * 256;         // 0..1023
        const int arr = idx >> 9;               // 0..1
        const int r = (idx >> 3) & 63;
        const int c = idx & 7;
        const uint32_t dst = base + arr * (64 * AROW) + r * AROW + c * 16;
        CP_ASYNC16(dst, gps[arr] + gbase + (size_t)(kv0 + r) * DH + c * 8);
    }
}

__global__ void __launch_bounds__(256, 2) flash_attn_tc_kernel(
    const __half* __restrict__ qhi,
    const __half* __restrict__ khi, const __half* __restrict__ vhi,
    __half* __restrict__ Ohi, __half* __restrict__ Olo)
{
    extern __shared__ char smem[];
    const uint32_t sb = smem_u32(smem);
    const int tid = threadIdx.x;
    const int lane = tid & 31;
    const int wid = tid >> 5;
    const int wm = wid * 16;
    const int qi = 15 - (int)blockIdx.x;     // heavy tiles first
    const int bh = blockIdx.y;
    const int q0 = qi * 128;
    const size_t gbase = (size_t)bh * TT * DH;

    // ldmatrix lane offsets (K, V)
    const int b_row = ((lane >> 4) << 3) + (lane & 7);
    const int b_koff = ((lane >> 3) & 1) << 3;
    const int v_krow = (lane & 7) + (((lane >> 3) & 1) << 3);
    const int v_noff = (lane >> 4) << 3;

    const int r0 = lane >> 2;
    const int cb = (lane & 3) * 2;
    const int tq0 = q0 + wm + r0;
    const int nkv = 2 * qi + 2;              // always even

    // ---- Q fragments in registers (MMA A-layout), loaded once ----
    uint32_t qfh[4][4];
    {
        const size_t rA = gbase + (size_t)(q0 + wm + r0) * DH;
        const size_t rB = gbase + (size_t)(q0 + wm + r0 + 8) * DH;
        #pragma unroll
        for (int ks = 0; ks < 4; ks++) {
            const int c0 = ks * 16 + cb;
            qfh[ks][0] = *(const uint32_t*)(qhi + rA + c0);
            qfh[ks][1] = *(const uint32_t*)(qhi + rB + c0);
            qfh[ks][2] = *(const uint32_t*)(qhi + rA + c0 + 8);
            qfh[ks][3] = *(const uint32_t*)(qhi + rB + c0 + 8);
        }
    }

    // prologue: stages 0, 1
    load_kv_stage(sb, 0, tid, gbase, 0, khi, vhi);
    CP_COMMIT();
    if (nkv > 1) {
        load_kv_stage(sb, 1, tid, gbase, 64, khi, vhi);
        CP_COMMIT();
        CP_WAIT1();
    } else {
        CP_WAIT0();
    }
    __syncthreads();

    float m0 = -1e30f, m1 = -1e30f, l0 = 0.0f, l1 = 0.0f;
    float oacc[8][4] = {};

    for (int j = 0; j < nkv; j++) {
        const uint32_t stb = sb + (j % 3) * STAGEB;
        const bool pre = (j + 2 < nkv);
        if (pre) {
            load_kv_stage(sb, (j + 2) % 3, tid, gbase, (j + 2) * 64, khi, vhi);
            CP_COMMIT();
        }

        // ---- S = Q K^T (1-product), Q from registers ----
        float s[8][4];
        #pragma unroll
        for (int nt = 0; nt < 8; nt++)
            #pragma unroll
            for (int e = 0; e < 4; e++) s[nt][e] = 0.0f;
        #pragma unroll
        for (int ks = 0; ks < 4; ks++) {
            #pragma unroll
            for (int ng = 0; ng < 4; ng++) {
                uint32_t bhf[4];
                const uint32_t boff =
                    (uint32_t)((ng * 16 + b_row) * AROW + (ks * 16 + b_koff) * 2);
                LDSM4(bhf, stb + KO_KH + boff);
                MMA16816(s[2 * ng], qfh[ks], &bhf[0]);
                MMA16816(s[2 * ng + 1], qfh[ks], &bhf[2]);
            }
        }

        // ---- scale (log2 domain) + causal mask ----
        const int kv0 = j * 64;
        const bool needmask = (kv0 + 63 > q0 + wm);
        #pragma unroll
        for (int nt = 0; nt < 8; nt++)
            #pragma unroll
            for (int e = 0; e < 4; e++) {
                float z = s[nt][e] * SCALE_L2E;
                if (needmask) {
                    const int tk = kv0 + nt * 8 + cb + (e & 1);
                    const int tq = tq0 + ((e >> 1) << 3);
                    if (tk > tq) z = -1e30f;
                }
                s[nt][e] = z;
            }

        // ---- online softmax ----
        float zm0 = -1e30f, zm1 = -1e30f;
        #pragma unroll
        for (int nt = 0; nt < 8; nt++) {
            zm0 = fmaxf(zm0, fmaxf(s[nt][0], s[nt][1]));
            zm1 = fmaxf(zm1, fmaxf(s[nt][2], s[nt][3]));
        }
        zm0 = fmaxf(zm0, __shfl_xor_sync(0xffffffffu, zm0, 1));
        zm0 = fmaxf(zm0, __shfl_xor_sync(0xffffffffu, zm0, 2));
        zm1 = fmaxf(zm1, __shfl_xor_sync(0xffffffffu, zm1, 1));
        zm1 = fmaxf(zm1, __shfl_xor_sync(0xffffffffu, zm1, 2));
        const float mn0 = fmaxf(m0, zm0);
        const float mn1 = fmaxf(m1, zm1);
        const float rs0 = fexp2(m0 - mn0);
        const float rs1 = fexp2(m1 - mn1);
        float sum0 = 0.0f, sum1 = 0.0f;
        uint32_t pah[4][4];
        #pragma unroll
        for (int nt = 0; nt < 8; nt++) {
            float p0 = fexp2(s[nt][0] - mn0);
            float p1 = fexp2(s[nt][1] - mn0);
            float p2 = fexp2(s[nt][2] - mn1);
            float p3 = fexp2(s[nt][3] - mn1);
            sum0 += p0 + p1;
            sum1 += p2 + p3;
            const int kt = nt >> 1;
            const int o = (nt & 1) << 1;
            pah[kt][o]     = pack_h(p0, p1);
            pah[kt][o + 1] = pack_h(p2, p3);
        }
        sum0 += __shfl_xor_sync(0xffffffffu, sum0, 1);
        sum0 += __shfl_xor_sync(0xffffffffu, sum0, 2);
        sum1 += __shfl_xor_sync(0xffffffffu, sum1, 1);
        sum1 += __shfl_xor_sync(0xffffffffu, sum1, 2);
        l0 = l0 * rs0 + sum0;
        l1 = l1 * rs1 + sum1;
        m0 = mn0;
        m1 = mn1;

        // rescale O (skip when max unchanged across the whole warp)
        if (!__all_sync(0xffffffffu, (rs0 == 1.0f) && (rs1 == 1.0f))) {
            #pragma unroll
            for (int nt = 0; nt < 8; nt++) {
                oacc[nt][0] *= rs0;
                oacc[nt][1] *= rs0;
                oacc[nt][2] *= rs1;
                oacc[nt][3] *= rs1;
            }
        }

        // ---- O += P V (1-product), V via ldmatrix.trans ----
        #pragma unroll
        for (int ks = 0; ks < 4; ks++) {
            #pragma unroll
            for (int ng = 0; ng < 4; ng++) {
                uint32_t vhf[4];
                const uint32_t voff =
                    (uint32_t)((ks * 16 + v_krow) * AROW + (ng * 16 + v_noff) * 2);
                LDSM4T(vhf, stb + KO_VH + voff);
                MMA16816(oacc[2 * ng], pah[ks], &vhf[0]);
                MMA16816(oacc[2 * ng + 1], pah[ks], &vhf[2]);
            }
        }

        if (j + 1 < nkv) {
            if (pre) { CP_WAIT1(); } else { CP_WAIT0(); }
        }
        __syncthreads();
    }

    // ---- epilogue: normalize, split to (hi, lo) fp16, write [m, c] ----
    const float inv0 = 1.0f / l0;
    const float inv1 = 1.0f / l1;
    const int b = bh >> 4;
    const int h = bh & 15;
    const int trow0 = q0 + wm + r0;
    const int trow1 = trow0 + 8;
    #pragma unroll
    for (int nt = 0; nt < 8; nt++) {
        const int col = h * DH + nt * 8 + cb;
        uint32_t hp, lp;
        pack_split_h(oacc[nt][0] * inv0, oacc[nt][1] * inv0, hp, lp);
        const size_t idx0 = ((size_t)b * TT + trow0) * CC + col;
        *(uint32_t*)&Ohi[idx0] = hp;
        *(uint32_t*)&Olo[idx0] = lp;
        pack_split_h(oacc[nt][2] * inv1, oacc[nt][3] * inv1, hp, lp);
        const size_t idx1 = ((size_t)b * TT + trow1) * CC + col;
        *(uint32_t*)&Ohi[idx1] = hp;
        *(uint32_t*)&Olo[idx1] = lp;
    }
}

// ---------------------------------------------------------------------------
// Launch
// ---------------------------------------------------------------------------
extern "C" void kernel_launch(void* const* d_in, const int* in_sizes, int n_in,
                              void* d_out, int out_size)
{
    const float* x   = (const float*)d_in[0];
    const float* W_Q = (const float*)d_in[1];
    const float* W_K = (const float*)d_in[2];
    const float* W_V = (const float*)d_in[3];
    const float* W_O = (const float*)d_in[4];
    float* out = (float*)d_out;

    __half *xhi, *wh, *qh, *kh, *vh, *ah, *al;
    cudaGetSymbolAddress((void**)&xhi, g_xhi);
    cudaGetSymbolAddress((void**)&wh, g_wh);
    cudaGetSymbolAddress((void**)&qh, g_qhi);
    cudaGetSymbolAddress((void**)&kh, g_khi);
    cudaGetSymbolAddress((void**)&vh, g_vhi);
    cudaGetSymbolAddress((void**)&ah, g_ahi);
    cudaGetSymbolAddress((void**)&al, g_alo);

    cudaFuncSetAttribute(gemm_tc_kernel<1>,
                         cudaFuncAttributeMaxDynamicSharedMemorySize, GEMM_SMEM);
    cudaFuncSetAttribute(gemm_tc_kernel<2>,
                         cudaFuncAttributeMaxDynamicSharedMemorySize, GEMM_SMEM);
    cudaFuncSetAttribute(flash_attn_tc_kernel,
                         cudaFuncAttributeMaxDynamicSharedMemorySize, ATTN_SMEM);

    const size_t WSZ = (size_t)CC * CC;
    const int nx4 = (MM * CC) / 4;
    const int nw4 = (CC * CC) / 4;

    // x: hi only. Weights: hi only, pre-scaled by 32 (epilogue undoes).
    split_h_kernel<<<(nx4 + 255) / 256, 256>>>(x, xhi, nullptr, 1.0f, 0, nx4);
    const float* Ws[4] = {W_Q, W_K, W_V, W_O};
    for (int i = 0; i < 4; i++)
        split_h_kernel<<<(nw4 + 255) / 256, 256>>>(Ws[i], wh + i * WSZ,
                                                   nullptr, 32.0f, 0, nw4);

    // fused QKV projections (1-product): one launch, 1536 CTAs
    dim3 qkv_grid(3 * CC / BN, MM / BM);   // (24, 64)
    gemm_tc_kernel<1><<<qkv_grid, 256, GEMM_SMEM>>>(
        xhi, nullptr, wh, nullptr, qh, kh, vh, 1);

    dim3 attn_grid(TT / 128, BB * HH);     // (16, 64)
    flash_attn_tc_kernel<<<attn_grid, 256, ATTN_SMEM>>>(
        qh, kh, vh, ah, al);

    // output projection (2-product, protects final accuracy)
    dim3 out_grid(CC / BN, MM / BM);       // (8, 64)
    gemm_tc_kernel<2><<<out_grid, 256, GEMM_SMEM>>>(
        ah, al, wh + 3 * WSZ, out, nullptr, nullptr, nullptr, 0);
}

// round 10
// speedup vs baseline: 6.7855x; 1.1396x over previous
#include <cuda_runtime.h>
#include <cuda_fp16.h>
#include <cstdint>

// Problem constants
#define BB 4
#define TT 2048
#define HH 16
#define DH 64
#define CC 1024
#define MM (BB * TT)   // 8192 rows

// ---------------------------------------------------------------------------
// Scratch (device globals -- allocation-free per harness rules)
// ---------------------------------------------------------------------------
static __device__ __align__(16) __half g_xhi[(size_t)MM * CC];
static __device__ __align__(16) __half g_wh[4][(size_t)CC * CC];
static __device__ __align__(16) __half g_qhi[(size_t)MM * CC];
static __device__ __align__(16) __half g_khi[(size_t)MM * CC];
static __device__ __align__(16) __half g_vhi[(size_t)MM * CC];
static __device__ __align__(16) __half g_ahi[(size_t)MM * CC];

// ---------------------------------------------------------------------------
// PTX helpers (sm_80+ portable -- compute_103 safe)
// ---------------------------------------------------------------------------
__device__ __forceinline__ uint32_t smem_u32(const void* p) {
    uint32_t a;
    asm("{ .reg .u64 t; cvta.to.shared.u64 t, %1; cvt.u32.u64 %0, t; }"
        : "=r"(a) : "l"(p));
    return a;
}

#define CP_ASYNC16(saddr, gaddr) \
    asm volatile("cp.async.cg.shared.global [%0], [%1], 16;" \
                 :: "r"(saddr), "l"(gaddr))
#define CP_COMMIT() asm volatile("cp.async.commit_group;" ::: "memory")
#define CP_WAIT0()  asm volatile("cp.async.wait_group 0;" ::: "memory")
#define CP_WAIT1()  asm volatile("cp.async.wait_group 1;" ::: "memory")

#define LDSM4(r, addr)                                                          \
    asm volatile("ldmatrix.sync.aligned.m8n8.x4.shared.b16 {%0,%1,%2,%3}, [%4];"\
                 : "=r"((r)[0]), "=r"((r)[1]), "=r"((r)[2]), "=r"((r)[3])       \
                 : "r"(addr))

#define LDSM4T(r, addr)                                                         \
    asm volatile("ldmatrix.sync.aligned.m8n8.x4.trans.shared.b16 {%0,%1,%2,%3}, [%4];" \
                 : "=r"((r)[0]), "=r"((r)[1]), "=r"((r)[2]), "=r"((r)[3])       \
                 : "r"(addr))

#define MMA16816(c, a, b)                                                       \
    asm volatile("mma.sync.aligned.m16n8k16.row.col.f32.f16.f16.f32 "           \
                 "{%0,%1,%2,%3}, {%4,%5,%6,%7}, {%8,%9}, {%0,%1,%2,%3};"        \
                 : "+f"((c)[0]), "+f"((c)[1]), "+f"((c)[2]), "+f"((c)[3])       \
                 : "r"((a)[0]), "r"((a)[1]), "r"((a)[2]), "r"((a)[3]),          \
                   "r"((b)[0]), "r"((b)[1]))

// exp2(y) for y <= 0, FMA/ALU pipes only. Deg-4 poly, |rel err| ~5e-5.
__device__ __forceinline__ float fexp2(float y) {
    y = fmaxf(y, -126.0f);
    float t = __fadd_rn(y, 12582912.0f);
    int   e = __float_as_int(t) << 23;
    float f = __fsub_rn(y, __fsub_rn(t, 12582912.0f));
    float p =              9.6181291077e-3f;
    p = fmaf(p, f, 5.5504108664e-2f);
    p = fmaf(p, f, 2.4022650696e-1f);
    p = fmaf(p, f, 6.9314718056e-1f);
    p = fmaf(p, f, 1.0f);
    return __uint_as_float((uint32_t)(__float_as_int(p) + e));
}

// fp32 pair -> packed fp16 hi pair (RN) + fp16 lo pair (residual, RN)
__device__ __forceinline__ void pack_split_h(float v0, float v1,
                                             uint32_t& hi, uint32_t& lo) {
    __half2 h = __floats2half2_rn(v0, v1);
    hi = *(uint32_t*)&h;
    float h0 = __half2float(__low2half(h));
    float h1 = __half2float(__high2half(h));
    __half2 l = __floats2half2_rn(v0 - h0, v1 - h1);
    lo = *(uint32_t*)&l;
}

__device__ __forceinline__ uint32_t pack_h(float v0, float v1) {
    __half2 h = __floats2half2_rn(v0, v1);
    return *(uint32_t*)&h;
}

// ---------------------------------------------------------------------------
// fp32 -> fp16 (hi; optional lo) with prescale
// ---------------------------------------------------------------------------
__global__ void __launch_bounds__(256) split_h_kernel(
    const float* __restrict__ in, __half* __restrict__ hi,
    __half* __restrict__ lo, float prescale, int write_lo, int n4)
{
    int i = blockIdx.x * 256 + threadIdx.x;
    if (i >= n4) return;
    float4 v = ((const float4*)in)[i];
    v.x *= prescale; v.y *= prescale; v.z *= prescale; v.w *= prescale;
    uint32_t h01, l01, h23, l23;
    pack_split_h(v.x, v.y, h01, l01);
    pack_split_h(v.z, v.w, h23, l23);
    ((uint2*)hi)[i] = make_uint2(h01, h23);
    if (write_lo) ((uint2*)lo)[i] = make_uint2(l01, l23);
}

// ---------------------------------------------------------------------------
// fp16 tensor-core GEMM, NPROD in {1, 2}:
//   NPROD=2: Y = (Ahi + Alo) @ Bh^T * 1/32
//   NPROD=1: Y = Ahi @ Bh^T * 1/32
// QKV (mode 1): grid.x = 24, gsel = blockIdx.x>>3 picks W + destination.
//   Q output additionally pre-scaled by 0.125*log2(e) (folded into epilogue).
// mode 0: fp32 out [m, n].
// ---------------------------------------------------------------------------
#define BM 128
#define BN 128
#define BK 32
#define NK (CC / BK)
#define ROWB 80
#define SUBT (128 * ROWB)       // 10240
#define GEMM_SMEM 67584
#define INV32 0.03125f
#define SCALE_L2E 0.1803368801111763f  // 0.125 * log2(e)

template <int NPROD>
__device__ __forceinline__ void load_chunk_async(
    uint32_t sb, int buf, int tid,
    const __half* __restrict__ Ahi, const __half* __restrict__ Alo,
    const __half* __restrict__ Bh, int m0, int n0, int k0)
{
    const int nsub = NPROD + 1;
    const uint32_t base = sb + buf * (nsub * SUBT);
    const __half* gps[3];
    int rb[3];
    if (NPROD == 2) {
        gps[0] = Ahi; gps[1] = Alo; gps[2] = Bh;
        rb[0] = m0; rb[1] = m0; rb[2] = n0;
    } else {
        gps[0] = Ahi; gps[1] = Bh;
        rb[0] = m0; rb[1] = n0;
    }
    #pragma unroll
    for (int it = 0; it < 2 * (NPROD + 1); it++) {
        const int sub = it >> 1;
        const int j = (it & 1) * 256 + tid;
        const int row = j >> 2;
        const int c16 = j & 3;
        const uint32_t saddr = base + sub * SUBT + row * ROWB + c16 * 16;
        const void* gaddr = gps[sub] + (size_t)(rb[sub] + row) * CC + k0 + c16 * 8;
        CP_ASYNC16(saddr, gaddr);
    }
}

template <int NPROD>
__global__ void __launch_bounds__(256) gemm_tc_kernel(
    const __half* __restrict__ Ahi, const __half* __restrict__ Alo,
    const __half* __restrict__ Wbase,
    float* __restrict__ Yf,
    __half* __restrict__ Yq_hi, __half* __restrict__ Yk_hi,
    __half* __restrict__ Yv_hi, int mode)
{
    extern __shared__ char smem[];
    const uint32_t sb = smem_u32(smem);
    const int tid = threadIdx.x;
    const int lane = tid & 31;
    const int wid = tid >> 5;
    const int wm = (wid >> 2) * 64;
    const int wn = (wid & 3) * 32;
    const int nsub = NPROD + 1;

    int gsel = 0, nblk = blockIdx.x;
    if (mode == 1) { gsel = blockIdx.x >> 3; nblk = blockIdx.x & 7; }
    const int n0 = nblk * BN;
    const int m0 = blockIdx.y * BM;
    const __half* Bh = Wbase + (size_t)gsel * CC * CC;

    __half* Yhi = nullptr;
    float esc = INV32;
    if (mode == 1) {
        if (gsel == 0)      { Yhi = Yq_hi; esc = INV32 * SCALE_L2E; }
        else if (gsel == 1) Yhi = Yk_hi;
        else                Yhi = Yv_hi;
    }

    float acc[4][4][4] = {};

    load_chunk_async<NPROD>(sb, 0, tid, Ahi, Alo, Bh, m0, n0, 0);
    CP_COMMIT();

    const int a_row = (lane & 15);
    const int a_koff = (lane >> 4) << 3;
    const int b_row = ((lane >> 4) << 3) + (lane & 7);
    const int b_koff = ((lane >> 3) & 1) << 3;

    for (int c = 0; c < NK; c++) {
        CP_WAIT0();
        __syncthreads();
        if (c + 1 < NK) {
            load_chunk_async<NPROD>(sb, (c + 1) & 1, tid, Ahi, Alo, Bh,
                                    m0, n0, (c + 1) * BK);
            CP_COMMIT();
        }

        const uint32_t ab = sb + (c & 1) * (nsub * SUBT);
        const uint32_t bb = ab + NPROD * SUBT;

        #pragma unroll
        for (int ks = 0; ks < 2; ks++) {
            uint32_t ah[16], al[16], bh[8];
            #pragma unroll
            for (int mt = 0; mt < 4; mt++) {
                const uint32_t off =
                    (uint32_t)((wm + mt * 16 + a_row) * ROWB + (ks * 16 + a_koff) * 2);
                LDSM4(&ah[mt * 4], ab + off);
                if (NPROD == 2) LDSM4(&al[mt * 4], ab + SUBT + off);
            }
            #pragma unroll
            for (int nt2 = 0; nt2 < 2; nt2++) {
                const uint32_t off =
                    (uint32_t)((wn + nt2 * 16 + b_row) * ROWB + (ks * 16 + b_koff) * 2);
                LDSM4(&bh[nt2 * 4], bb + off);
            }
            #pragma unroll
            for (int mt = 0; mt < 4; mt++)
                #pragma unroll
                for (int nt = 0; nt < 4; nt++) {
                    float* cc = acc[mt][nt];
                    MMA16816(cc, &ah[mt * 4], &bh[nt * 2]);
                    if (NPROD == 2) MMA16816(cc, &al[mt * 4], &bh[nt * 2]);
                }
        }
        __syncthreads();
    }

    // epilogue: registers (x esc) -> smem staging -> coalesced global stores
    float* es = (float*)smem;   // [128][132]
    const int er = lane >> 2;
    const int ec = (lane & 3) * 2;
    #pragma unroll
    for (int mt = 0; mt < 4; mt++)
        #pragma unroll
        for (int nt = 0; nt < 4; nt++) {
            const int r = wm + mt * 16 + er;
            const int cl = wn + nt * 8 + ec;
            *(float2*)&es[r * 132 + cl] =
                make_float2(acc[mt][nt][0] * esc, acc[mt][nt][1] * esc);
            *(float2*)&es[(r + 8) * 132 + cl] =
                make_float2(acc[mt][nt][2] * esc, acc[mt][nt][3] * esc);
        }
    __syncthreads();

    #pragma unroll
    for (int it = 0; it < 16; it++) {
        const int i = tid + it * 256;
        const int r = i >> 5;
        const int c4 = (i & 31) * 4;
        float4 v = *(float4*)&es[r * 132 + c4];
        const int m = m0 + r;
        const int n = n0 + c4;
        if (mode == 1) {
            const int b = m >> 11, t = m & 2047, h = n >> 6, d = n & 63;
            const size_t idx = (((size_t)(b * HH + h) * TT) + t) * DH + d;
            *(uint2*)&Yhi[idx] =
                make_uint2(pack_h(v.x, v.y), pack_h(v.z, v.w));
        } else {
            *(float4*)&Yf[(size_t)m * CC + n] = v;
        }
    }
}

// ---------------------------------------------------------------------------
// Tensor-core flash attention (causal), all 1-product fp16, 2 CTAs/SM.
//   S = Q_hi K_hi^T (Q pre-scaled -> S already in log2 domain),  O = P_hi V_hi.
// Q fragments in registers. 3-stage KV smem, one sync per tile.
// Output: fp16-hi only, [m, c] layout.
// ---------------------------------------------------------------------------
#define AROW 144
#define STAGEB (2 * 64 * AROW)       // 18432 (K + V)
#define KO_KH 0
#define KO_VH (64 * AROW)            // 9216
#define ATTN_SMEM (3 * STAGEB)       // 55296

__device__ __forceinline__ void load_kv_stage(
    uint32_t sb, int stage, int tid, size_t gbase, int kv0,
    const __half* __restrict__ khi, const __half* __restrict__ vhi)
{
    const uint32_t base = sb + stage * STAGEB;
    const __half* gps[2] = {khi, vhi};
    #pragma unroll
    for (int it = 0; it < 4; it++) {
        const int idx = tid + it * 256;         // 0..1023
        const int arr = idx >> 9;               // 0..1
        const int r = (idx >> 3) & 63;
        const int c = idx & 7;
        const uint32_t dst = base + arr * (64 * AROW) + r * AROW + c * 16;
        CP_ASYNC16(dst, gps[arr] + gbase + (size_t)(kv0 + r) * DH + c * 8);
    }
}

__global__ void __launch_bounds__(256, 2) flash_attn_tc_kernel(
    const __half* __restrict__ qhi,
    const __half* __restrict__ khi, const __half* __restrict__ vhi,
    __half* __restrict__ Ohi)
{
    extern __shared__ char smem[];
    const uint32_t sb = smem_u32(smem);
    const int tid = threadIdx.x;
    const int lane = tid & 31;
    const int wid = tid >> 5;
    const int wm = wid * 16;
    const int qi = 15 - (int)blockIdx.x;     // heavy tiles first
    const int bh = blockIdx.y;
    const int q0 = qi * 128;
    const size_t gbase = (size_t)bh * TT * DH;

    // ldmatrix lane offsets (K, V)
    const int b_row = ((lane >> 4) << 3) + (lane & 7);
    const int b_koff = ((lane >> 3) & 1) << 3;
    const int v_krow = (lane & 7) + (((lane >> 3) & 1) << 3);
    const int v_noff = (lane >> 4) << 3;

    const int r0 = lane >> 2;
    const int cb = (lane & 3) * 2;
    const int tq0 = q0 + wm + r0;
    const int nkv = 2 * qi + 2;              // always even

    // ---- Q fragments in registers (MMA A-layout), loaded once ----
    uint32_t qfh[4][4];
    {
        const size_t rA = gbase + (size_t)(q0 + wm + r0) * DH;
        const size_t rB = gbase + (size_t)(q0 + wm + r0 + 8) * DH;
        #pragma unroll
        for (int ks = 0; ks < 4; ks++) {
            const int c0 = ks * 16 + cb;
            qfh[ks][0] = *(const uint32_t*)(qhi + rA + c0);
            qfh[ks][1] = *(const uint32_t*)(qhi + rB + c0);
            qfh[ks][2] = *(const uint32_t*)(qhi + rA + c0 + 8);
            qfh[ks][3] = *(const uint32_t*)(qhi + rB + c0 + 8);
        }
    }

    // prologue: stages 0, 1
    load_kv_stage(sb, 0, tid, gbase, 0, khi, vhi);
    CP_COMMIT();
    if (nkv > 1) {
        load_kv_stage(sb, 1, tid, gbase, 64, khi, vhi);
        CP_COMMIT();
        CP_WAIT1();
    } else {
        CP_WAIT0();
    }
    __syncthreads();

    float m0 = -1e30f, m1 = -1e30f, l0 = 0.0f, l1 = 0.0f;
    float oacc[8][4] = {};

    for (int j = 0; j < nkv; j++) {
        const uint32_t stb = sb + (j % 3) * STAGEB;
        const bool pre = (j + 2 < nkv);
        if (pre) {
            load_kv_stage(sb, (j + 2) % 3, tid, gbase, (j + 2) * 64, khi, vhi);
            CP_COMMIT();
        }

        // ---- S = Q K^T (1-product, pre-scaled Q) ----
        float s[8][4];
        #pragma unroll
        for (int nt = 0; nt < 8; nt++)
            #pragma unroll
            for (int e = 0; e < 4; e++) s[nt][e] = 0.0f;
        #pragma unroll
        for (int ks = 0; ks < 4; ks++) {
            #pragma unroll
            for (int ng = 0; ng < 4; ng++) {
                uint32_t bhf[4];
                const uint32_t boff =
                    (uint32_t)((ng * 16 + b_row) * AROW + (ks * 16 + b_koff) * 2);
                LDSM4(bhf, stb + KO_KH + boff);
                MMA16816(s[2 * ng], qfh[ks], &bhf[0]);
                MMA16816(s[2 * ng + 1], qfh[ks], &bhf[2]);
            }
        }

        // ---- causal mask (diagonal tiles only; S already log2-scaled) ----
        const int kv0 = j * 64;
        if (kv0 + 63 > q0 + wm) {
            #pragma unroll
            for (int nt = 0; nt < 8; nt++)
                #pragma unroll
                for (int e = 0; e < 4; e++) {
                    const int tk = kv0 + nt * 8 + cb + (e & 1);
                    const int tq = tq0 + ((e >> 1) << 3);
                    if (tk > tq) s[nt][e] = -1e30f;
                }
        }

        // ---- online softmax ----
        float zm0 = -1e30f, zm1 = -1e30f;
        #pragma unroll
        for (int nt = 0; nt < 8; nt++) {
            zm0 = fmaxf(zm0, fmaxf(s[nt][0], s[nt][1]));
            zm1 = fmaxf(zm1, fmaxf(s[nt][2], s[nt][3]));
        }
        zm0 = fmaxf(zm0, __shfl_xor_sync(0xffffffffu, zm0, 1));
        zm0 = fmaxf(zm0, __shfl_xor_sync(0xffffffffu, zm0, 2));
        zm1 = fmaxf(zm1, __shfl_xor_sync(0xffffffffu, zm1, 1));
        zm1 = fmaxf(zm1, __shfl_xor_sync(0xffffffffu, zm1, 2));
        const float mn0 = fmaxf(m0, zm0);
        const float mn1 = fmaxf(m1, zm1);
        const float rs0 = fexp2(m0 - mn0);
        const float rs1 = fexp2(m1 - mn1);
        float sum0 = 0.0f, sum1 = 0.0f;
        uint32_t pah[4][4];
        #pragma unroll
        for (int nt = 0; nt < 8; nt++) {
            float p0 = fexp2(s[nt][0] - mn0);
            float p1 = fexp2(s[nt][1] - mn0);
            float p2 = fexp2(s[nt][2] - mn1);
            float p3 = fexp2(s[nt][3] - mn1);
            sum0 += p0 + p1;
            sum1 += p2 + p3;
            const int kt = nt >> 1;
            const int o = (nt & 1) << 1;
            pah[kt][o]     = pack_h(p0, p1);
            pah[kt][o + 1] = pack_h(p2, p3);
        }
        sum0 += __shfl_xor_sync(0xffffffffu, sum0, 1);
        sum0 += __shfl_xor_sync(0xffffffffu, sum0, 2);
        sum1 += __shfl_xor_sync(0xffffffffu, sum1, 1);
        sum1 += __shfl_xor_sync(0xffffffffu, sum1, 2);
        l0 = l0 * rs0 + sum0;
        l1 = l1 * rs1 + sum1;
        m0 = mn0;
        m1 = mn1;

        // rescale O (skip when max unchanged across the whole warp)
        if (!__all_sync(0xffffffffu, (rs0 == 1.0f) && (rs1 == 1.0f))) {
            #pragma unroll
            for (int nt = 0; nt < 8; nt++) {
                oacc[nt][0] *= rs0;
                oacc[nt][1] *= rs0;
                oacc[nt][2] *= rs1;
                oacc[nt][3] *= rs1;
            }
        }

        // ---- O += P V (1-product), V via ldmatrix.trans ----
        #pragma unroll
        for (int ks = 0; ks < 4; ks++) {
            #pragma unroll
            for (int ng = 0; ng < 4; ng++) {
                uint32_t vhf[4];
                const uint32_t voff =
                    (uint32_t)((ks * 16 + v_krow) * AROW + (ng * 16 + v_noff) * 2);
                LDSM4T(vhf, stb + KO_VH + voff);
                MMA16816(oacc[2 * ng], pah[ks], &vhf[0]);
                MMA16816(oacc[2 * ng + 1], pah[ks], &vhf[2]);
            }
        }

        if (j + 1 < nkv) {
            if (pre) { CP_WAIT1(); } else { CP_WAIT0(); }
        }
        __syncthreads();
    }

    // ---- epilogue: normalize, fp16-hi, write [m, c] ----
    const float inv0 = 1.0f / l0;
    const float inv1 = 1.0f / l1;
    const int b = bh >> 4;
    const int h = bh & 15;
    const int trow0 = q0 + wm + r0;
    const int trow1 = trow0 + 8;
    #pragma unroll
    for (int nt = 0; nt < 8; nt++) {
        const int col = h * DH + nt * 8 + cb;
        *(uint32_t*)&Ohi[((size_t)b * TT + trow0) * CC + col] =
            pack_h(oacc[nt][0] * inv0, oacc[nt][1] * inv0);
        *(uint32_t*)&Ohi[((size_t)b * TT + trow1) * CC + col] =
            pack_h(oacc[nt][2] * inv1, oacc[nt][3] * inv1);
    }
}

// ---------------------------------------------------------------------------
// Launch
// ---------------------------------------------------------------------------
extern "C" void kernel_launch(void* const* d_in, const int* in_sizes, int n_in,
                              void* d_out, int out_size)
{
    const float* x   = (const float*)d_in[0];
    const float* W_Q = (const float*)d_in[1];
    const float* W_K = (const float*)d_in[2];
    const float* W_V = (const float*)d_in[3];
    const float* W_O = (const float*)d_in[4];
    float* out = (float*)d_out;

    __half *xhi, *wh, *qh, *kh, *vh, *ah;
    cudaGetSymbolAddress((void**)&xhi, g_xhi);
    cudaGetSymbolAddress((void**)&wh, g_wh);
    cudaGetSymbolAddress((void**)&qh, g_qhi);
    cudaGetSymbolAddress((void**)&kh, g_khi);
    cudaGetSymbolAddress((void**)&vh, g_vhi);
    cudaGetSymbolAddress((void**)&ah, g_ahi);

    cudaFuncSetAttribute(gemm_tc_kernel<1>,
                         cudaFuncAttributeMaxDynamicSharedMemorySize, GEMM_SMEM);
    cudaFuncSetAttribute(flash_attn_tc_kernel,
                         cudaFuncAttributeMaxDynamicSharedMemorySize, ATTN_SMEM);

    const size_t WSZ = (size_t)CC * CC;
    const int nx4 = (MM * CC) / 4;
    const int nw4 = (CC * CC) / 4;

    // x: hi only. Weights: hi only, pre-scaled by 32 (epilogue undoes).
    split_h_kernel<<<(nx4 + 255) / 256, 256>>>(x, xhi, nullptr, 1.0f, 0, nx4);
    const float* Ws[4] = {W_Q, W_K, W_V, W_O};
    for (int i = 0; i < 4; i++)
        split_h_kernel<<<(nw4 + 255) / 256, 256>>>(Ws[i], wh + i * WSZ,
                                                   nullptr, 32.0f, 0, nw4);

    // fused QKV projections (1-product): one launch, 1536 CTAs
    dim3 qkv_grid(3 * CC / BN, MM / BM);   // (24, 64)
    gemm_tc_kernel<1><<<qkv_grid, 256, GEMM_SMEM>>>(
        xhi, nullptr, wh, nullptr, qh, kh, vh, 1);

    dim3 attn_grid(TT / 128, BB * HH);     // (16, 64)
    flash_attn_tc_kernel<<<attn_grid, 256, ATTN_SMEM>>>(qh, kh, vh, ah);

    // output projection (1-product)
    dim3 out_grid(CC / BN, MM / BM);       // (8, 64)
    gemm_tc_kernel<1><<<out_grid, 256, GEMM_SMEM>>>(
        ah, nullptr, wh + 3 * WSZ, out, nullptr, nullptr, nullptr, 0);
}

// round 11
// speedup vs baseline: 7.1008x; 1.0465x over previous
#include <cuda_runtime.h>
#include <cuda_fp16.h>
#include <cstdint>

// Problem constants
#define BB 4
#define TT 2048
#define HH 16
#define DH 64
#define CC 1024
#define MM (BB * TT)   // 8192 rows

// ---------------------------------------------------------------------------
// Scratch (device globals -- allocation-free per harness rules)
// ---------------------------------------------------------------------------
static __device__ __align__(16) __half g_xhi[(size_t)MM * CC];
static __device__ __align__(16) __half g_wh[4][(size_t)CC * CC];
static __device__ __align__(16) __half g_qhi[(size_t)MM * CC];
static __device__ __align__(16) __half g_khi[(size_t)MM * CC];
static __device__ __align__(16) __half g_vhi[(size_t)MM * CC];
static __device__ __align__(16) __half g_ahi[(size_t)MM * CC];

// ---------------------------------------------------------------------------
// PTX helpers (sm_80+ portable -- compute_103 safe)
// ---------------------------------------------------------------------------
__device__ __forceinline__ uint32_t smem_u32(const void* p) {
    uint32_t a;
    asm("{ .reg .u64 t; cvta.to.shared.u64 t, %1; cvt.u32.u64 %0, t; }"
        : "=r"(a) : "l"(p));
    return a;
}

#define CP_ASYNC16(saddr, gaddr) \
    asm volatile("cp.async.cg.shared.global [%0], [%1], 16;" \
                 :: "r"(saddr), "l"(gaddr))
#define CP_COMMIT() asm volatile("cp.async.commit_group;" ::: "memory")
#define CP_WAIT0()  asm volatile("cp.async.wait_group 0;" ::: "memory")
#define CP_WAIT1()  asm volatile("cp.async.wait_group 1;" ::: "memory")

#define LDSM4(r, addr)                                                          \
    asm volatile("ldmatrix.sync.aligned.m8n8.x4.shared.b16 {%0,%1,%2,%3}, [%4];"\
                 : "=r"((r)[0]), "=r"((r)[1]), "=r"((r)[2]), "=r"((r)[3])       \
                 : "r"(addr))

#define LDSM4T(r, addr)                                                         \
    asm volatile("ldmatrix.sync.aligned.m8n8.x4.trans.shared.b16 {%0,%1,%2,%3}, [%4];" \
                 : "=r"((r)[0]), "=r"((r)[1]), "=r"((r)[2]), "=r"((r)[3])       \
                 : "r"(addr))

#define MMA16816(c, a, b)                                                       \
    asm volatile("mma.sync.aligned.m16n8k16.row.col.f32.f16.f16.f32 "           \
                 "{%0,%1,%2,%3}, {%4,%5,%6,%7}, {%8,%9}, {%0,%1,%2,%3};"        \
                 : "+f"((c)[0]), "+f"((c)[1]), "+f"((c)[2]), "+f"((c)[3])       \
                 : "r"((a)[0]), "r"((a)[1]), "r"((a)[2]), "r"((a)[3]),          \
                   "r"((b)[0]), "r"((b)[1]))

// exp2(y) for y in [-126, 0], FMA/ALU pipes only. Deg-4 poly, no clamp
// (all call sites guarantee y > -126 via the -60 mask floor).
__device__ __forceinline__ float fexp2(float y) {
    float t = __fadd_rn(y, 12582912.0f);
    int   e = __float_as_int(t) << 23;
    float f = __fsub_rn(y, __fsub_rn(t, 12582912.0f));
    float p =              9.6181291077e-3f;
    p = fmaf(p, f, 5.5504108664e-2f);
    p = fmaf(p, f, 2.4022650696e-1f);
    p = fmaf(p, f, 6.9314718056e-1f);
    p = fmaf(p, f, 1.0f);
    return __uint_as_float((uint32_t)(__float_as_int(p) + e));
}

// fp32 pair -> packed fp16 hi pair (RN) + fp16 lo pair (residual, RN)
__device__ __forceinline__ void pack_split_h(float v0, float v1,
                                             uint32_t& hi, uint32_t& lo) {
    __half2 h = __floats2half2_rn(v0, v1);
    hi = *(uint32_t*)&h;
    float h0 = __half2float(__low2half(h));
    float h1 = __half2float(__high2half(h));
    __half2 l = __floats2half2_rn(v0 - h0, v1 - h1);
    lo = *(uint32_t*)&l;
}

__device__ __forceinline__ uint32_t pack_h(float v0, float v1) {
    __half2 h = __floats2half2_rn(v0, v1);
    return *(uint32_t*)&h;
}

// ---------------------------------------------------------------------------
// fp32 -> fp16 conversions
// ---------------------------------------------------------------------------
__global__ void __launch_bounds__(256) split_x_kernel(
    const float* __restrict__ in, __half* __restrict__ hi, int n4)
{
    int i = blockIdx.x * 256 + threadIdx.x;
    if (i >= n4) return;
    float4 v = ((const float4*)in)[i];
    ((uint2*)hi)[i] = make_uint2(pack_h(v.x, v.y), pack_h(v.z, v.w));
}

// all 4 weight matrices in one launch; pre-scaled by 32
__global__ void __launch_bounds__(256) split_w_kernel(
    const float* __restrict__ w0, const float* __restrict__ w1,
    const float* __restrict__ w2, const float* __restrict__ w3,
    __half* __restrict__ dst, int n4each)
{
    const int sel = blockIdx.x >> 10;            // n4each/256 = 1024 blocks each
    const int i = (blockIdx.x & 1023) * 256 + threadIdx.x;
    if (i >= n4each) return;
    const float* src = (sel == 0) ? w0 : (sel == 1) ? w1 : (sel == 2) ? w2 : w3;
    float4 v = ((const float4*)src)[i];
    v.x *= 32.0f; v.y *= 32.0f; v.z *= 32.0f; v.w *= 32.0f;
    ((uint2*)(dst + (size_t)sel * CC * CC))[i] =
        make_uint2(pack_h(v.x, v.y), pack_h(v.z, v.w));
}

// ---------------------------------------------------------------------------
// 1-product fp16 tensor-core GEMM: Y = Ahi @ Bh^T * 1/32
// QKV (mode 1): grid.x = 24, gsel = blockIdx.x>>3 picks W + destination.
//   Q output additionally pre-scaled by 0.125*log2(e).
// mode 0: fp32 out [m, n].
// ---------------------------------------------------------------------------
#define BMG 128
#define BNG 128
#define BKG 32
#define NKG (CC / BKG)
#define ROWB 80
#define SUBT (128 * ROWB)       // 10240
#define GEMM_SMEM 67584
#define INV32 0.03125f
#define SCALE_L2E 0.1803368801111763f  // 0.125 * log2(e)

__device__ __forceinline__ void load_chunk_async(
    uint32_t sb, int buf, int tid,
    const __half* __restrict__ Ahi, const __half* __restrict__ Bh,
    int m0, int n0, int k0)
{
    const uint32_t base = sb + buf * (2 * SUBT);
    const __half* gps[2] = {Ahi, Bh};
    const int rb[2] = {m0, n0};
    #pragma unroll
    for (int it = 0; it < 4; it++) {
        const int sub = it >> 1;
        const int j = (it & 1) * 256 + tid;
        const int row = j >> 2;
        const int c16 = j & 3;
        const uint32_t saddr = base + sub * SUBT + row * ROWB + c16 * 16;
        const void* gaddr = gps[sub] + (size_t)(rb[sub] + row) * CC + k0 + c16 * 8;
        CP_ASYNC16(saddr, gaddr);
    }
}

__global__ void __launch_bounds__(256) gemm_tc_kernel(
    const __half* __restrict__ Ahi, const __half* __restrict__ Wbase,
    float* __restrict__ Yf,
    __half* __restrict__ Yq_hi, __half* __restrict__ Yk_hi,
    __half* __restrict__ Yv_hi, int mode)
{
    extern __shared__ char smem[];
    const uint32_t sb = smem_u32(smem);
    const int tid = threadIdx.x;
    const int lane = tid & 31;
    const int wid = tid >> 5;
    const int wm = (wid >> 2) * 64;
    const int wn = (wid & 3) * 32;

    int gsel = 0, nblk = blockIdx.x;
    if (mode == 1) { gsel = blockIdx.x >> 3; nblk = blockIdx.x & 7; }
    const int n0 = nblk * BNG;
    const int m0 = blockIdx.y * BMG;
    const __half* Bh = Wbase + (size_t)gsel * CC * CC;

    __half* Yhi = nullptr;
    float esc = INV32;
    if (mode == 1) {
        if (gsel == 0)      { Yhi = Yq_hi; esc = INV32 * SCALE_L2E; }
        else if (gsel == 1) Yhi = Yk_hi;
        else                Yhi = Yv_hi;
    }

    float acc[4][4][4] = {};

    load_chunk_async(sb, 0, tid, Ahi, Bh, m0, n0, 0);
    CP_COMMIT();

    const int a_row = (lane & 15);
    const int a_koff = (lane >> 4) << 3;
    const int b_row = ((lane >> 4) << 3) + (lane & 7);
    const int b_koff = ((lane >> 3) & 1) << 3;

    for (int c = 0; c < NKG; c++) {
        CP_WAIT0();
        __syncthreads();
        if (c + 1 < NKG) {
            load_chunk_async(sb, (c + 1) & 1, tid, Ahi, Bh, m0, n0, (c + 1) * BKG);
            CP_COMMIT();
        }

        const uint32_t ab = sb + (c & 1) * (2 * SUBT);
        const uint32_t bb = ab + SUBT;

        #pragma unroll
        for (int ks = 0; ks < 2; ks++) {
            uint32_t ah[16], bh[8];
            #pragma unroll
            for (int mt = 0; mt < 4; mt++) {
                const uint32_t off =
                    (uint32_t)((wm + mt * 16 + a_row) * ROWB + (ks * 16 + a_koff) * 2);
                LDSM4(&ah[mt * 4], ab + off);
            }
            #pragma unroll
            for (int nt2 = 0; nt2 < 2; nt2++) {
                const uint32_t off =
                    (uint32_t)((wn + nt2 * 16 + b_row) * ROWB + (ks * 16 + b_koff) * 2);
                LDSM4(&bh[nt2 * 4], bb + off);
            }
            #pragma unroll
            for (int mt = 0; mt < 4; mt++)
                #pragma unroll
                for (int nt = 0; nt < 4; nt++)
                    MMA16816(acc[mt][nt], &ah[mt * 4], &bh[nt * 2]);
        }
        __syncthreads();
    }

    // epilogue: registers (x esc) -> smem staging -> coalesced global stores
    float* es = (float*)smem;   // [128][132]
    const int er = lane >> 2;
    const int ec = (lane & 3) * 2;
    #pragma unroll
    for (int mt = 0; mt < 4; mt++)
        #pragma unroll
        for (int nt = 0; nt < 4; nt++) {
            const int r = wm + mt * 16 + er;
            const int cl = wn + nt * 8 + ec;
            *(float2*)&es[r * 132 + cl] =
                make_float2(acc[mt][nt][0] * esc, acc[mt][nt][1] * esc);
            *(float2*)&es[(r + 8) * 132 + cl] =
                make_float2(acc[mt][nt][2] * esc, acc[mt][nt][3] * esc);
        }
    __syncthreads();

    #pragma unroll
    for (int it = 0; it < 16; it++) {
        const int i = tid + it * 256;
        const int r = i >> 5;
        const int c4 = (i & 31) * 4;
        float4 v = *(float4*)&es[r * 132 + c4];
        const int m = m0 + r;
        const int n = n0 + c4;
        if (mode == 1) {
            const int b = m >> 11, t = m & 2047, h = n >> 6, d = n & 63;
            const size_t idx = (((size_t)(b * HH + h) * TT) + t) * DH + d;
            *(uint2*)&Yhi[idx] =
                make_uint2(pack_h(v.x, v.y), pack_h(v.z, v.w));
        } else {
            *(float4*)&Yf[(size_t)m * CC + n] = v;
        }
    }
}

// ---------------------------------------------------------------------------
// Tensor-core flash attention (causal), 1-product fp16, 128 threads (4 warps),
// BM=64 Q rows per CTA, up to 4 CTAs/SM.
//   S = Q_hi K_hi^T (Q pre-scaled -> log2 domain),  O = P_hi V_hi.
// Q fragments in registers. 3-stage KV smem, one sync per tile.
// Mask floor -60 (not -inf) keeps all exp2 args > -126 (clamp-free fexp2).
// ---------------------------------------------------------------------------
#define AROW 144
#define STAGEB (2 * 64 * AROW)       // 18432 (K + V)
#define KO_KH 0
#define KO_VH (64 * AROW)            // 9216
#define ATTN_SMEM (3 * STAGEB)       // 55296
#define MASKF (-60.0f)

__device__ __forceinline__ void load_kv_stage(
    uint32_t sb, int stage, int tid, size_t gbase, int kv0,
    const __half* __restrict__ khi, const __half* __restrict__ vhi)
{
    const uint32_t base = sb + stage * STAGEB;
    const __half* gps[2] = {khi, vhi};
    #pragma unroll
    for (int it = 0; it < 8; it++) {
        const int idx = tid + it * 128;         // 0..1023
        const int arr = idx >> 9;               // 0..1
        const int r = (idx >> 3) & 63;
        const int c = idx & 7;
        const uint32_t dst = base + arr * (64 * AROW) + r * AROW + c * 16;
        CP_ASYNC16(dst, gps[arr] + gbase + (size_t)(kv0 + r) * DH + c * 8);
    }
}

__global__ void __launch_bounds__(128, 4) flash_attn_tc_kernel(
    const __half* __restrict__ qhi,
    const __half* __restrict__ khi, const __half* __restrict__ vhi,
    __half* __restrict__ Ohi)
{
    extern __shared__ char smem[];
    const uint32_t sb = smem_u32(smem);
    const int tid = threadIdx.x;
    const int lane = tid & 31;
    const int wid = tid >> 5;               // 0..3
    const int wm = wid * 16;
    const int qi = 31 - (int)blockIdx.x;    // heavy tiles first
    const int bh = blockIdx.y;
    const int q0 = qi * 64;
    const size_t gbase = (size_t)bh * TT * DH;

    // ldmatrix lane offsets (K, V)
    const int b_row = ((lane >> 4) << 3) + (lane & 7);
    const int b_koff = ((lane >> 3) & 1) << 3;
    const int v_krow = (lane & 7) + (((lane >> 3) & 1) << 3);
    const int v_noff = (lane >> 4) << 3;

    const int r0 = lane >> 2;
    const int cb = (lane & 3) * 2;
    const int tq0 = q0 + wm + r0;
    const int nkv = qi + 1;

    // ---- Q fragments in registers (MMA A-layout), loaded once ----
    uint32_t qfh[4][4];
    {
        const size_t rA = gbase + (size_t)(q0 + wm + r0) * DH;
        const size_t rB = gbase + (size_t)(q0 + wm + r0 + 8) * DH;
        #pragma unroll
        for (int ks = 0; ks < 4; ks++) {
            const int c0 = ks * 16 + cb;
            qfh[ks][0] = *(const uint32_t*)(qhi + rA + c0);
            qfh[ks][1] = *(const uint32_t*)(qhi + rB + c0);
            qfh[ks][2] = *(const uint32_t*)(qhi + rA + c0 + 8);
            qfh[ks][3] = *(const uint32_t*)(qhi + rB + c0 + 8);
        }
    }

    // prologue: stages 0, 1
    load_kv_stage(sb, 0, tid, gbase, 0, khi, vhi);
    CP_COMMIT();
    if (nkv > 1) {
        load_kv_stage(sb, 1, tid, gbase, 64, khi, vhi);
        CP_COMMIT();
        CP_WAIT1();
    } else {
        CP_WAIT0();
    }
    __syncthreads();

    float m0 = MASKF, m1 = MASKF, l0 = 0.0f, l1 = 0.0f;
    float oacc[8][4] = {};

    for (int j = 0; j < nkv; j++) {
        const uint32_t stb = sb + (j % 3) * STAGEB;
        const bool pre = (j + 2 < nkv);
        if (pre) {
            load_kv_stage(sb, (j + 2) % 3, tid, gbase, (j + 2) * 64, khi, vhi);
            CP_COMMIT();
        }

        // ---- S = Q K^T (1-product, pre-scaled Q -> log2 domain) ----
        float s[8][4];
        #pragma unroll
        for (int nt = 0; nt < 8; nt++)
            #pragma unroll
            for (int e = 0; e < 4; e++) s[nt][e] = 0.0f;
        #pragma unroll
        for (int ks = 0; ks < 4; ks++) {
            #pragma unroll
            for (int ng = 0; ng < 4; ng++) {
                uint32_t bhf[4];
                const uint32_t boff =
                    (uint32_t)((ng * 16 + b_row) * AROW + (ks * 16 + b_koff) * 2);
                LDSM4(bhf, stb + KO_KH + boff);
                MMA16816(s[2 * ng], qfh[ks], &bhf[0]);
                MMA16816(s[2 * ng + 1], qfh[ks], &bhf[2]);
            }
        }

        // ---- causal mask (diagonal tiles only) ----
        const int kv0 = j * 64;
        if (kv0 + 63 > q0 + wm) {
            #pragma unroll
            for (int nt = 0; nt < 8; nt++)
                #pragma unroll
                for (int e = 0; e < 4; e++) {
                    const int tk = kv0 + nt * 8 + cb + (e & 1);
                    const int tq = tq0 + ((e >> 1) << 3);
                    if (tk > tq) s[nt][e] = MASKF;
                }
        }

        // ---- online softmax ----
        float zm0 = MASKF, zm1 = MASKF;
        #pragma unroll
        for (int nt = 0; nt < 8; nt++) {
            zm0 = fmaxf(zm0, fmaxf(s[nt][0], s[nt][1]));
            zm1 = fmaxf(zm1, fmaxf(s[nt][2], s[nt][3]));
        }
        zm0 = fmaxf(zm0, __shfl_xor_sync(0xffffffffu, zm0, 1));
        zm0 = fmaxf(zm0, __shfl_xor_sync(0xffffffffu, zm0, 2));
        zm1 = fmaxf(zm1, __shfl_xor_sync(0xffffffffu, zm1, 1));
        zm1 = fmaxf(zm1, __shfl_xor_sync(0xffffffffu, zm1, 2));
        const float mn0 = fmaxf(m0, zm0);
        const float mn1 = fmaxf(m1, zm1);
        const float rs0 = fexp2(m0 - mn0);
        const float rs1 = fexp2(m1 - mn1);
        float sum0 = 0.0f, sum1 = 0.0f;
        uint32_t pah[4][4];
        #pragma unroll
        for (int nt = 0; nt < 8; nt++) {
            float p0 = fexp2(s[nt][0] - mn0);
            float p1 = fexp2(s[nt][1] - mn0);
            float p2 = fexp2(s[nt][2] - mn1);
            float p3 = fexp2(s[nt][3] - mn1);
            sum0 += p0 + p1;
            sum1 += p2 + p3;
            const int kt = nt >> 1;
            const int o = (nt & 1) << 1;
            pah[kt][o]     = pack_h(p0, p1);
            pah[kt][o + 1] = pack_h(p2, p3);
        }
        sum0 += __shfl_xor_sync(0xffffffffu, sum0, 1);
        sum0 += __shfl_xor_sync(0xffffffffu, sum0, 2);
        sum1 += __shfl_xor_sync(0xffffffffu, sum1, 1);
        sum1 += __shfl_xor_sync(0xffffffffu, sum1, 2);
        l0 = l0 * rs0 + sum0;
        l1 = l1 * rs1 + sum1;
        m0 = mn0;
        m1 = mn1;

        // rescale O (skip when max unchanged across the whole warp)
        if (!__all_sync(0xffffffffu, (rs0 == 1.0f) && (rs1 == 1.0f))) {
            #pragma unroll
            for (int nt = 0; nt < 8; nt++) {
                oacc[nt][0] *= rs0;
                oacc[nt][1] *= rs0;
                oacc[nt][2] *= rs1;
                oacc[nt][3] *= rs1;
            }
        }

        // ---- O += P V (1-product), V via ldmatrix.trans ----
        #pragma unroll
        for (int ks = 0; ks < 4; ks++) {
            #pragma unroll
            for (int ng = 0; ng < 4; ng++) {
                uint32_t vhf[4];
                const uint32_t voff =
                    (uint32_t)((ks * 16 + v_krow) * AROW + (ng * 16 + v_noff) * 2);
                LDSM4T(vhf, stb + KO_VH + voff);
                MMA16816(oacc[2 * ng], pah[ks], &vhf[0]);
                MMA16816(oacc[2 * ng + 1], pah[ks], &vhf[2]);
            }
        }

        if (j + 1 < nkv) {
            if (pre) { CP_WAIT1(); } else { CP_WAIT0(); }
        }
        __syncthreads();
    }

    // ---- epilogue: normalize, fp16-hi, write [m, c] ----
    const float inv0 = 1.0f / l0;
    const float inv1 = 1.0f / l1;
    const int b = bh >> 4;
    const int h = bh & 15;
    const int trow0 = q0 + wm + r0;
    const int trow1 = trow0 + 8;
    #pragma unroll
    for (int nt = 0; nt < 8; nt++) {
        const int col = h * DH + nt * 8 + cb;
        *(uint32_t*)&Ohi[((size_t)b * TT + trow0) * CC + col] =
            pack_h(oacc[nt][0] * inv0, oacc[nt][1] * inv0);
        *(uint32_t*)&Ohi[((size_t)b * TT + trow1) * CC + col] =
            pack_h(oacc[nt][2] * inv1, oacc[nt][3] * inv1);
    }
}

// ---------------------------------------------------------------------------
// Launch
// ---------------------------------------------------------------------------
extern "C" void kernel_launch(void* const* d_in, const int* in_sizes, int n_in,
                              void* d_out, int out_size)
{
    const float* x   = (const float*)d_in[0];
    const float* W_Q = (const float*)d_in[1];
    const float* W_K = (const float*)d_in[2];
    const float* W_V = (const float*)d_in[3];
    const float* W_O = (const float*)d_in[4];
    float* out = (float*)d_out;

    __half *xhi, *wh, *qh, *kh, *vh, *ah;
    cudaGetSymbolAddress((void**)&xhi, g_xhi);
    cudaGetSymbolAddress((void**)&wh, g_wh);
    cudaGetSymbolAddress((void**)&qh, g_qhi);
    cudaGetSymbolAddress((void**)&kh, g_khi);
    cudaGetSymbolAddress((void**)&vh, g_vhi);
    cudaGetSymbolAddress((void**)&ah, g_ahi);

    cudaFuncSetAttribute(gemm_tc_kernel,
                         cudaFuncAttributeMaxDynamicSharedMemorySize, GEMM_SMEM);
    cudaFuncSetAttribute(flash_attn_tc_kernel,
                         cudaFuncAttributeMaxDynamicSharedMemorySize, ATTN_SMEM);

    const size_t WSZ = (size_t)CC * CC;
    const int nx4 = (MM * CC) / 4;       // 2097152
    const int nw4 = (CC * CC) / 4;       // 262144 -> 1024 blocks per matrix

    split_x_kernel<<<(nx4 + 255) / 256, 256>>>(x, xhi, nx4);
    split_w_kernel<<<4 * 1024, 256>>>(W_Q, W_K, W_V, W_O, wh, nw4);

    // fused QKV projections (1-product): one launch, 1536 CTAs
    dim3 qkv_grid(3 * CC / BNG, MM / BMG);   // (24, 64)
    gemm_tc_kernel<<<qkv_grid, 256, GEMM_SMEM>>>(
        xhi, wh, nullptr, qh, kh, vh, 1);

    dim3 attn_grid(TT / 64, BB * HH);        // (32, 64)
    flash_attn_tc_kernel<<<attn_grid, 128, ATTN_SMEM>>>(qh, kh, vh, ah);

    // output projection (1-product)
    dim3 out_grid(CC / BNG, MM / BMG);       // (8, 64)
    gemm_tc_kernel<<<out_grid, 256, GEMM_SMEM>>>(
        ah, wh + 3 * WSZ, out, nullptr, nullptr, nullptr, 0);
}

// round 12
// speedup vs baseline: 7.1054x; 1.0007x over previous
#include <cuda_runtime.h>
#include <cuda_fp16.h>
#include <cstdint>

// Problem constants
#define BB 4
#define TT 2048
#define HH 16
#define DH 64
#define CC 1024
#define MM (BB * TT)   // 8192 rows

// ---------------------------------------------------------------------------
// Scratch (device globals -- allocation-free per harness rules)
// ---------------------------------------------------------------------------
static __device__ __align__(16) __half g_xhi[(size_t)MM * CC];
static __device__ __align__(16) __half g_wh[4][(size_t)CC * CC];
static __device__ __align__(16) __half g_qhi[(size_t)MM * CC];
static __device__ __align__(16) __half g_khi[(size_t)MM * CC];
static __device__ __align__(16) __half g_vhi[(size_t)MM * CC];
static __device__ __align__(16) __half g_ahi[(size_t)MM * CC];

// ---------------------------------------------------------------------------
// PTX helpers (sm_80+ portable -- compute_103 safe)
// ---------------------------------------------------------------------------
__device__ __forceinline__ uint32_t smem_u32(const void* p) {
    uint32_t a;
    asm("{ .reg .u64 t; cvta.to.shared.u64 t, %1; cvt.u32.u64 %0, t; }"
        : "=r"(a) : "l"(p));
    return a;
}

#define CP_ASYNC16(saddr, gaddr) \
    asm volatile("cp.async.cg.shared.global [%0], [%1], 16;" \
                 :: "r"(saddr), "l"(gaddr))
#define CP_COMMIT() asm volatile("cp.async.commit_group;" ::: "memory")
#define CP_WAIT0()  asm volatile("cp.async.wait_group 0;" ::: "memory")
#define CP_WAIT1()  asm volatile("cp.async.wait_group 1;" ::: "memory")

#define LDSM4(r, addr)                                                          \
    asm volatile("ldmatrix.sync.aligned.m8n8.x4.shared.b16 {%0,%1,%2,%3}, [%4];"\
                 : "=r"((r)[0]), "=r"((r)[1]), "=r"((r)[2]), "=r"((r)[3])       \
                 : "r"(addr))

#define LDSM4T(r, addr)                                                         \
    asm volatile("ldmatrix.sync.aligned.m8n8.x4.trans.shared.b16 {%0,%1,%2,%3}, [%4];" \
                 : "=r"((r)[0]), "=r"((r)[1]), "=r"((r)[2]), "=r"((r)[3])       \
                 : "r"(addr))

#define MMA16816(c, a, b)                                                       \
    asm volatile("mma.sync.aligned.m16n8k16.row.col.f32.f16.f16.f32 "           \
                 "{%0,%1,%2,%3}, {%4,%5,%6,%7}, {%8,%9}, {%0,%1,%2,%3};"        \
                 : "+f"((c)[0]), "+f"((c)[1]), "+f"((c)[2]), "+f"((c)[3])       \
                 : "r"((a)[0]), "r"((a)[1]), "r"((a)[2]), "r"((a)[3]),          \
                   "r"((b)[0]), "r"((b)[1]))

// exp2(y) for y in [-126, 0], FMA/ALU pipes only. Deg-4 poly, no clamp
// (all call sites guarantee y > -126 via the -60 mask floor).
__device__ __forceinline__ float fexp2(float y) {
    float t = __fadd_rn(y, 12582912.0f);
    int   e = __float_as_int(t) << 23;
    float f = __fsub_rn(y, __fsub_rn(t, 12582912.0f));
    float p =              9.6181291077e-3f;
    p = fmaf(p, f, 5.5504108664e-2f);
    p = fmaf(p, f, 2.4022650696e-1f);
    p = fmaf(p, f, 6.9314718056e-1f);
    p = fmaf(p, f, 1.0f);
    return __uint_as_float((uint32_t)(__float_as_int(p) + e));
}

__device__ __forceinline__ uint32_t pack_h(float v0, float v1) {
    __half2 h = __floats2half2_rn(v0, v1);
    return *(uint32_t*)&h;
}

// ---------------------------------------------------------------------------
// fused fp32 -> fp16 conversion: x (8192x1024) + 4 weights (1024x1024, x32)
// grid: 8192 blocks for x, then 4*1024 for weights
// ---------------------------------------------------------------------------
__global__ void __launch_bounds__(256) convert_all_kernel(
    const float* __restrict__ x, __half* __restrict__ xhi,
    const float* __restrict__ w0, const float* __restrict__ w1,
    const float* __restrict__ w2, const float* __restrict__ w3,
    __half* __restrict__ wdst)
{
    const int bid = blockIdx.x;
    if (bid < 8192) {
        const int i = bid * 256 + threadIdx.x;
        float4 v = ((const float4*)x)[i];
        ((uint2*)xhi)[i] = make_uint2(pack_h(v.x, v.y), pack_h(v.z, v.w));
    } else {
        const int wb = bid - 8192;
        const int sel = wb >> 10;
        const int i = (wb & 1023) * 256 + threadIdx.x;
        const float* src = (sel == 0) ? w0 : (sel == 1) ? w1 : (sel == 2) ? w2 : w3;
        float4 v = ((const float4*)src)[i];
        v.x *= 32.0f; v.y *= 32.0f; v.z *= 32.0f; v.w *= 32.0f;
        ((uint2*)(wdst + (size_t)sel * CC * CC))[i] =
            make_uint2(pack_h(v.x, v.y), pack_h(v.z, v.w));
    }
}

// ---------------------------------------------------------------------------
// 1-product fp16 tensor-core GEMM: Y = Ahi @ Bh^T * 1/32
// QKV (mode 1): grid.x = 24, gsel = blockIdx.x>>3 picks W + destination.
//   Q output additionally pre-scaled by 0.125*log2(e).
// mode 0: fp32 out [m, n].
// ---------------------------------------------------------------------------
#define BMG 128
#define BNG 128
#define BKG 32
#define NKG (CC / BKG)
#define ROWB 80
#define SUBT (128 * ROWB)       // 10240
#define GEMM_SMEM 67584
#define INV32 0.03125f
#define SCALE_L2E 0.1803368801111763f  // 0.125 * log2(e)

__device__ __forceinline__ void load_chunk_async(
    uint32_t sb, int buf, int tid,
    const __half* __restrict__ Ahi, const __half* __restrict__ Bh,
    int m0, int n0, int k0)
{
    const uint32_t base = sb + buf * (2 * SUBT);
    const __half* gps[2] = {Ahi, Bh};
    const int rb[2] = {m0, n0};
    #pragma unroll
    for (int it = 0; it < 4; it++) {
        const int sub = it >> 1;
        const int j = (it & 1) * 256 + tid;
        const int row = j >> 2;
        const int c16 = j & 3;
        const uint32_t saddr = base + sub * SUBT + row * ROWB + c16 * 16;
        const void* gaddr = gps[sub] + (size_t)(rb[sub] + row) * CC + k0 + c16 * 8;
        CP_ASYNC16(saddr, gaddr);
    }
}

__global__ void __launch_bounds__(256) gemm_tc_kernel(
    const __half* __restrict__ Ahi, const __half* __restrict__ Wbase,
    float* __restrict__ Yf,
    __half* __restrict__ Yq_hi, __half* __restrict__ Yk_hi,
    __half* __restrict__ Yv_hi, int mode)
{
    extern __shared__ char smem[];
    const uint32_t sb = smem_u32(smem);
    const int tid = threadIdx.x;
    const int lane = tid & 31;
    const int wid = tid >> 5;
    const int wm = (wid >> 2) * 64;
    const int wn = (wid & 3) * 32;

    int gsel = 0, nblk = blockIdx.x;
    if (mode == 1) { gsel = blockIdx.x >> 3; nblk = blockIdx.x & 7; }
    const int n0 = nblk * BNG;
    const int m0 = blockIdx.y * BMG;
    const __half* Bh = Wbase + (size_t)gsel * CC * CC;

    __half* Yhi = nullptr;
    float esc = INV32;
    if (mode == 1) {
        if (gsel == 0)      { Yhi = Yq_hi; esc = INV32 * SCALE_L2E; }
        else if (gsel == 1) Yhi = Yk_hi;
        else                Yhi = Yv_hi;
    }

    float acc[4][4][4] = {};

    load_chunk_async(sb, 0, tid, Ahi, Bh, m0, n0, 0);
    CP_COMMIT();

    const int a_row = (lane & 15);
    const int a_koff = (lane >> 4) << 3;
    const int b_row = ((lane >> 4) << 3) + (lane & 7);
    const int b_koff = ((lane >> 3) & 1) << 3;

    for (int c = 0; c < NKG; c++) {
        CP_WAIT0();
        __syncthreads();
        if (c + 1 < NKG) {
            load_chunk_async(sb, (c + 1) & 1, tid, Ahi, Bh, m0, n0, (c + 1) * BKG);
            CP_COMMIT();
        }

        const uint32_t ab = sb + (c & 1) * (2 * SUBT);
        const uint32_t bb = ab + SUBT;

        #pragma unroll
        for (int ks = 0; ks < 2; ks++) {
            uint32_t ah[16], bh[8];
            #pragma unroll
            for (int mt = 0; mt < 4; mt++) {
                const uint32_t off =
                    (uint32_t)((wm + mt * 16 + a_row) * ROWB + (ks * 16 + a_koff) * 2);
                LDSM4(&ah[mt * 4], ab + off);
            }
            #pragma unroll
            for (int nt2 = 0; nt2 < 2; nt2++) {
                const uint32_t off =
                    (uint32_t)((wn + nt2 * 16 + b_row) * ROWB + (ks * 16 + b_koff) * 2);
                LDSM4(&bh[nt2 * 4], bb + off);
            }
            #pragma unroll
            for (int mt = 0; mt < 4; mt++)
                #pragma unroll
                for (int nt = 0; nt < 4; nt++)
                    MMA16816(acc[mt][nt], &ah[mt * 4], &bh[nt * 2]);
        }
        __syncthreads();
    }

    // epilogue: registers (x esc) -> smem staging -> coalesced global stores
    float* es = (float*)smem;   // [128][132]
    const int er = lane >> 2;
    const int ec = (lane & 3) * 2;
    #pragma unroll
    for (int mt = 0; mt < 4; mt++)
        #pragma unroll
        for (int nt = 0; nt < 4; nt++) {
            const int r = wm + mt * 16 + er;
            const int cl = wn + nt * 8 + ec;
            *(float2*)&es[r * 132 + cl] =
                make_float2(acc[mt][nt][0] * esc, acc[mt][nt][1] * esc);
            *(float2*)&es[(r + 8) * 132 + cl] =
                make_float2(acc[mt][nt][2] * esc, acc[mt][nt][3] * esc);
        }
    __syncthreads();

    #pragma unroll
    for (int it = 0; it < 16; it++) {
        const int i = tid + it * 256;
        const int r = i >> 5;
        const int c4 = (i & 31) * 4;
        float4 v = *(float4*)&es[r * 132 + c4];
        const int m = m0 + r;
        const int n = n0 + c4;
        if (mode == 1) {
            const int b = m >> 11, t = m & 2047, h = n >> 6, d = n & 63;
            const size_t idx = (((size_t)(b * HH + h) * TT) + t) * DH + d;
            *(uint2*)&Yhi[idx] =
                make_uint2(pack_h(v.x, v.y), pack_h(v.z, v.w));
        } else {
            *(float4*)&Yf[(size_t)m * CC + n] = v;
        }
    }
}

// ---------------------------------------------------------------------------
// Tensor-core flash attention (causal), 1-product fp16, 128 threads (4 warps),
// BM=64 Q rows per CTA, 4 CTAs/SM.
//   S = Q_hi K_hi^T (Q pre-scaled -> log2 domain),  O = P_hi V_hi.
// l (row-sum) kept as PER-THREAD partials; quad-reduced once in the epilogue
// (rs is row-uniform so partials rescale identically) -- removes 4 SHFLs+2
// FADDs from every iteration's critical path.
// ---------------------------------------------------------------------------
#define AROW 144
#define STAGEB (2 * 64 * AROW)       // 18432 (K + V)
#define KO_KH 0
#define KO_VH (64 * AROW)            // 9216
#define ATTN_SMEM (3 * STAGEB)       // 55296
#define MASKF (-60.0f)

__device__ __forceinline__ void load_kv_stage(
    uint32_t sb, int stage, int tid, size_t gbase, int kv0,
    const __half* __restrict__ khi, const __half* __restrict__ vhi)
{
    const uint32_t base = sb + stage * STAGEB;
    const __half* gps[2] = {khi, vhi};
    #pragma unroll
    for (int it = 0; it < 8; it++) {
        const int idx = tid + it * 128;         // 0..1023
        const int arr = idx >> 9;               // 0..1
        const int r = (idx >> 3) & 63;
        const int c = idx & 7;
        const uint32_t dst = base + arr * (64 * AROW) + r * AROW + c * 16;
        CP_ASYNC16(dst, gps[arr] + gbase + (size_t)(kv0 + r) * DH + c * 8);
    }
}

__global__ void __launch_bounds__(128, 4) flash_attn_tc_kernel(
    const __half* __restrict__ qhi,
    const __half* __restrict__ khi, const __half* __restrict__ vhi,
    __half* __restrict__ Ohi)
{
    extern __shared__ char smem[];
    const uint32_t sb = smem_u32(smem);
    const int tid = threadIdx.x;
    const int lane = tid & 31;
    const int wid = tid >> 5;               // 0..3
    const int wm = wid * 16;
    const int qi = 31 - (int)blockIdx.x;    // heavy tiles first
    const int bh = blockIdx.y;
    const int q0 = qi * 64;
    const size_t gbase = (size_t)bh * TT * DH;

    // ldmatrix lane offsets (K, V)
    const int b_row = ((lane >> 4) << 3) + (lane & 7);
    const int b_koff = ((lane >> 3) & 1) << 3;
    const int v_krow = (lane & 7) + (((lane >> 3) & 1) << 3);
    const int v_noff = (lane >> 4) << 3;

    const int r0 = lane >> 2;
    const int cb = (lane & 3) * 2;
    const int tq0 = q0 + wm + r0;
    const int nkv = qi + 1;

    // ---- Q fragments in registers (MMA A-layout), loaded once ----
    uint32_t qfh[4][4];
    {
        const size_t rA = gbase + (size_t)(q0 + wm + r0) * DH;
        const size_t rB = gbase + (size_t)(q0 + wm + r0 + 8) * DH;
        #pragma unroll
        for (int ks = 0; ks < 4; ks++) {
            const int c0 = ks * 16 + cb;
            qfh[ks][0] = *(const uint32_t*)(qhi + rA + c0);
            qfh[ks][1] = *(const uint32_t*)(qhi + rB + c0);
            qfh[ks][2] = *(const uint32_t*)(qhi + rA + c0 + 8);
            qfh[ks][3] = *(const uint32_t*)(qhi + rB + c0 + 8);
        }
    }

    // prologue: stages 0, 1
    load_kv_stage(sb, 0, tid, gbase, 0, khi, vhi);
    CP_COMMIT();
    if (nkv > 1) {
        load_kv_stage(sb, 1, tid, gbase, 64, khi, vhi);
        CP_COMMIT();
        CP_WAIT1();
    } else {
        CP_WAIT0();
    }
    __syncthreads();

    float m0 = MASKF, m1 = MASKF;
    float l0 = 0.0f, l1 = 0.0f;             // per-thread partial row sums
    float oacc[8][4] = {};

    for (int j = 0; j < nkv; j++) {
        const uint32_t stb = sb + (j % 3) * STAGEB;
        const bool pre = (j + 2 < nkv);
        if (pre) {
            load_kv_stage(sb, (j + 2) % 3, tid, gbase, (j + 2) * 64, khi, vhi);
            CP_COMMIT();
        }

        // ---- S = Q K^T (1-product, pre-scaled Q -> log2 domain) ----
        float s[8][4];
        #pragma unroll
        for (int nt = 0; nt < 8; nt++)
            #pragma unroll
            for (int e = 0; e < 4; e++) s[nt][e] = 0.0f;
        #pragma unroll
        for (int ks = 0; ks < 4; ks++) {
            #pragma unroll
            for (int ng = 0; ng < 4; ng++) {
                uint32_t bhf[4];
                const uint32_t boff =
                    (uint32_t)((ng * 16 + b_row) * AROW + (ks * 16 + b_koff) * 2);
                LDSM4(bhf, stb + KO_KH + boff);
                MMA16816(s[2 * ng], qfh[ks], &bhf[0]);
                MMA16816(s[2 * ng + 1], qfh[ks], &bhf[2]);
            }
        }

        // ---- causal mask (diagonal tiles only) ----
        const int kv0 = j * 64;
        if (kv0 + 63 > q0 + wm) {
            #pragma unroll
            for (int nt = 0; nt < 8; nt++)
                #pragma unroll
                for (int e = 0; e < 4; e++) {
                    const int tk = kv0 + nt * 8 + cb + (e & 1);
                    const int tq = tq0 + ((e >> 1) << 3);
                    if (tk > tq) s[nt][e] = MASKF;
                }
        }

        // ---- online softmax (max reduced across quad; l stays per-thread) ----
        float zm0 = MASKF, zm1 = MASKF;
        #pragma unroll
        for (int nt = 0; nt < 8; nt++) {
            zm0 = fmaxf(zm0, fmaxf(s[nt][0], s[nt][1]));
            zm1 = fmaxf(zm1, fmaxf(s[nt][2], s[nt][3]));
        }
        zm0 = fmaxf(zm0, __shfl_xor_sync(0xffffffffu, zm0, 1));
        zm0 = fmaxf(zm0, __shfl_xor_sync(0xffffffffu, zm0, 2));
        zm1 = fmaxf(zm1, __shfl_xor_sync(0xffffffffu, zm1, 1));
        zm1 = fmaxf(zm1, __shfl_xor_sync(0xffffffffu, zm1, 2));
        const float mn0 = fmaxf(m0, zm0);
        const float mn1 = fmaxf(m1, zm1);
        const float rs0 = fexp2(m0 - mn0);
        const float rs1 = fexp2(m1 - mn1);
        float sum0 = 0.0f, sum1 = 0.0f;
        uint32_t pah[4][4];
        #pragma unroll
        for (int nt = 0; nt < 8; nt++) {
            float p0 = fexp2(s[nt][0] - mn0);
            float p1 = fexp2(s[nt][1] - mn0);
            float p2 = fexp2(s[nt][2] - mn1);
            float p3 = fexp2(s[nt][3] - mn1);
            sum0 += p0 + p1;
            sum1 += p2 + p3;
            const int kt = nt >> 1;
            const int o = (nt & 1) << 1;
            pah[kt][o]     = pack_h(p0, p1);
            pah[kt][o + 1] = pack_h(p2, p3);
        }
        l0 = l0 * rs0 + sum0;      // per-thread partial; no cross-thread reduce
        l1 = l1 * rs1 + sum1;
        m0 = mn0;
        m1 = mn1;

        // rescale O (skip when max unchanged across the whole warp)
        if (!__all_sync(0xffffffffu, (rs0 == 1.0f) && (rs1 == 1.0f))) {
            #pragma unroll
            for (int nt = 0; nt < 8; nt++) {
                oacc[nt][0] *= rs0;
                oacc[nt][1] *= rs0;
                oacc[nt][2] *= rs1;
                oacc[nt][3] *= rs1;
            }
        }

        // ---- O += P V (1-product), V via ldmatrix.trans ----
        #pragma unroll
        for (int ks = 0; ks < 4; ks++) {
            #pragma unroll
            for (int ng = 0; ng < 4; ng++) {
                uint32_t vhf[4];
                const uint32_t voff =
                    (uint32_t)((ks * 16 + v_krow) * AROW + (ng * 16 + v_noff) * 2);
                LDSM4T(vhf, stb + KO_VH + voff);
                MMA16816(oacc[2 * ng], pah[ks], &vhf[0]);
                MMA16816(oacc[2 * ng + 1], pah[ks], &vhf[2]);
            }
        }

        if (j + 1 < nkv) {
            if (pre) { CP_WAIT1(); } else { CP_WAIT0(); }
        }
        __syncthreads();
    }

    // ---- epilogue: quad-reduce l, normalize, fp16-hi, write [m, c] ----
    l0 += __shfl_xor_sync(0xffffffffu, l0, 1);
    l0 += __shfl_xor_sync(0xffffffffu, l0, 2);
    l1 += __shfl_xor_sync(0xffffffffu, l1, 1);
    l1 += __shfl_xor_sync(0xffffffffu, l1, 2);
    const float inv0 = 1.0f / l0;
    const float inv1 = 1.0f / l1;
    const int b = bh >> 4;
    const int h = bh & 15;
    const int trow0 = q0 + wm + r0;
    const int trow1 = trow0 + 8;
    #pragma unroll
    for (int nt = 0; nt < 8; nt++) {
        const int col = h * DH + nt * 8 + cb;
        *(uint32_t*)&Ohi[((size_t)b * TT + trow0) * CC + col] =
            pack_h(oacc[nt][0] * inv0, oacc[nt][1] * inv0);
        *(uint32_t*)&Ohi[((size_t)b * TT + trow1) * CC + col] =
            pack_h(oacc[nt][2] * inv1, oacc[nt][3] * inv1);
    }
}

// ---------------------------------------------------------------------------
// Launch
// ---------------------------------------------------------------------------
extern "C" void kernel_launch(void* const* d_in, const int* in_sizes, int n_in,
                              void* d_out, int out_size)
{
    const float* x   = (const float*)d_in[0];
    const float* W_Q = (const float*)d_in[1];
    const float* W_K = (const float*)d_in[2];
    const float* W_V = (const float*)d_in[3];
    const float* W_O = (const float*)d_in[4];
    float* out = (float*)d_out;

    __half *xhi, *wh, *qh, *kh, *vh, *ah;
    cudaGetSymbolAddress((void**)&xhi, g_xhi);
    cudaGetSymbolAddress((void**)&wh, g_wh);
    cudaGetSymbolAddress((void**)&qh, g_qhi);
    cudaGetSymbolAddress((void**)&kh, g_khi);
    cudaGetSymbolAddress((void**)&vh, g_vhi);
    cudaGetSymbolAddress((void**)&ah, g_ahi);

    cudaFuncSetAttribute(gemm_tc_kernel,
                         cudaFuncAttributeMaxDynamicSharedMemorySize, GEMM_SMEM);
    cudaFuncSetAttribute(flash_attn_tc_kernel,
                         cudaFuncAttributeMaxDynamicSharedMemorySize, ATTN_SMEM);

    const size_t WSZ = (size_t)CC * CC;

    // one fused conversion launch: x + all 4 weights
    convert_all_kernel<<<8192 + 4 * 1024, 256>>>(x, xhi, W_Q, W_K, W_V, W_O, wh);

    // fused QKV projections (1-product): one launch, 1536 CTAs
    dim3 qkv_grid(3 * CC / BNG, MM / BMG);   // (24, 64)
    gemm_tc_kernel<<<qkv_grid, 256, GEMM_SMEM>>>(
        xhi, wh, nullptr, qh, kh, vh, 1);

    dim3 attn_grid(TT / 64, BB * HH);        // (32, 64)
    flash_attn_tc_kernel<<<attn_grid, 128, ATTN_SMEM>>>(qh, kh, vh, ah);

    // output projection (1-product)
    dim3 out_grid(CC / BNG, MM / BMG);       // (8, 64)
    gemm_tc_kernel<<<out_grid, 256, GEMM_SMEM>>>(
        ah, wh + 3 * WSZ, out, nullptr, nullptr, nullptr, 0);
}

// round 13
// speedup vs baseline: 7.9028x; 1.1122x over previous
#include <cuda_runtime.h>
#include <cuda_fp16.h>
#include <cstdint>

// Problem constants
#define BB 4
#define TT 2048
#define HH 16
#define DH 64
#define CC 1024
#define MM (BB * TT)   // 8192 rows

// ---------------------------------------------------------------------------
// Scratch (device globals -- allocation-free per harness rules)
// ---------------------------------------------------------------------------
static __device__ __align__(16) __half g_xhi[(size_t)MM * CC];
static __device__ __align__(16) __half g_wh[4][(size_t)CC * CC];
static __device__ __align__(16) __half g_qhi[(size_t)MM * CC];
static __device__ __align__(16) __half g_khi[(size_t)MM * CC];
static __device__ __align__(16) __half g_vhi[(size_t)MM * CC];
static __device__ __align__(16) __half g_ahi[(size_t)MM * CC];

// ---------------------------------------------------------------------------
// PTX helpers (sm_80+ portable -- compute_103 safe)
// ---------------------------------------------------------------------------
__device__ __forceinline__ uint32_t smem_u32(const void* p) {
    uint32_t a;
    asm("{ .reg .u64 t; cvta.to.shared.u64 t, %1; cvt.u32.u64 %0, t; }"
        : "=r"(a) : "l"(p));
    return a;
}

#define CP_ASYNC16(saddr, gaddr) \
    asm volatile("cp.async.cg.shared.global [%0], [%1], 16;" \
                 :: "r"(saddr), "l"(gaddr))
#define CP_COMMIT() asm volatile("cp.async.commit_group;" ::: "memory")
#define CP_WAIT0()  asm volatile("cp.async.wait_group 0;" ::: "memory")
#define CP_WAIT1()  asm volatile("cp.async.wait_group 1;" ::: "memory")

#define LDSM4(r, addr)                                                          \
    asm volatile("ldmatrix.sync.aligned.m8n8.x4.shared.b16 {%0,%1,%2,%3}, [%4];"\
                 : "=r"((r)[0]), "=r"((r)[1]), "=r"((r)[2]), "=r"((r)[3])       \
                 : "r"(addr))

#define LDSM4T(r, addr)                                                         \
    asm volatile("ldmatrix.sync.aligned.m8n8.x4.trans.shared.b16 {%0,%1,%2,%3}, [%4];" \
                 : "=r"((r)[0]), "=r"((r)[1]), "=r"((r)[2]), "=r"((r)[3])       \
                 : "r"(addr))

#define MMA16816(c, a, b)                                                       \
    asm volatile("mma.sync.aligned.m16n8k16.row.col.f32.f16.f16.f32 "           \
                 "{%0,%1,%2,%3}, {%4,%5,%6,%7}, {%8,%9}, {%0,%1,%2,%3};"        \
                 : "+f"((c)[0]), "+f"((c)[1]), "+f"((c)[2]), "+f"((c)[3])       \
                 : "r"((a)[0]), "r"((a)[1]), "r"((a)[2]), "r"((a)[3]),          \
                   "r"((b)[0]), "r"((b)[1]))

// exp2(y) for y in [-126, 0], FMA/ALU pipes only. Deg-4 poly, no clamp
// (all call sites guarantee y > -126 via the -60 mask floor).
__device__ __forceinline__ float fexp2(float y) {
    float t = __fadd_rn(y, 12582912.0f);
    int   e = __float_as_int(t) << 23;
    float f = __fsub_rn(y, __fsub_rn(t, 12582912.0f));
    float p =              9.6181291077e-3f;
    p = fmaf(p, f, 5.5504108664e-2f);
    p = fmaf(p, f, 2.4022650696e-1f);
    p = fmaf(p, f, 6.9314718056e-1f);
    p = fmaf(p, f, 1.0f);
    return __uint_as_float((uint32_t)(__float_as_int(p) + e));
}

__device__ __forceinline__ uint32_t pack_h(float v0, float v1) {
    __half2 h = __floats2half2_rn(v0, v1);
    return *(uint32_t*)&h;
}

// ---------------------------------------------------------------------------
// fused fp32 -> fp16 conversion: x (8192x1024) + 4 weights (1024x1024, x32)
// ---------------------------------------------------------------------------
__global__ void __launch_bounds__(256) convert_all_kernel(
    const float* __restrict__ x, __half* __restrict__ xhi,
    const float* __restrict__ w0, const float* __restrict__ w1,
    const float* __restrict__ w2, const float* __restrict__ w3,
    __half* __restrict__ wdst)
{
    const int bid = blockIdx.x;
    if (bid < 8192) {
        const int i = bid * 256 + threadIdx.x;
        float4 v = ((const float4*)x)[i];
        ((uint2*)xhi)[i] = make_uint2(pack_h(v.x, v.y), pack_h(v.z, v.w));
    } else {
        const int wb = bid - 8192;
        const int sel = wb >> 10;
        const int i = (wb & 1023) * 256 + threadIdx.x;
        const float* src = (sel == 0) ? w0 : (sel == 1) ? w1 : (sel == 2) ? w2 : w3;
        float4 v = ((const float4*)src)[i];
        v.x *= 32.0f; v.y *= 32.0f; v.z *= 32.0f; v.w *= 32.0f;
        ((uint2*)(wdst + (size_t)sel * CC * CC))[i] =
            make_uint2(pack_h(v.x, v.y), pack_h(v.z, v.w));
    }
}

// ---------------------------------------------------------------------------
// 1-product fp16 tensor-core GEMM: Y = Ahi @ Bh^T * 1/32
// BK=64 per chunk (one sync per 64 K-columns) to amortize barrier costs.
// QKV (mode 1): grid.x = 24, gsel = blockIdx.x>>3 picks W + destination.
//   Q output additionally pre-scaled by 0.125*log2(e).
// mode 0: fp32 out [m, n].
// ---------------------------------------------------------------------------
#define BMG 128
#define BNG 128
#define BKG 64
#define NKG (CC / BKG)          // 16 chunks
#define GROWB 144               // 64 halves (128 B) + 16 B pad
#define GSUBT (128 * GROWB)     // 18432
#define GBUF (2 * GSUBT)        // 36864 (A + B)
#define GEMM_SMEM (2 * GBUF)    // 73728
#define INV32 0.03125f
#define SCALE_L2E 0.1803368801111763f  // 0.125 * log2(e)

__device__ __forceinline__ void load_chunk_async(
    uint32_t sb, int buf, int tid,
    const __half* __restrict__ Ahi, const __half* __restrict__ Bh,
    int m0, int n0, int k0)
{
    const uint32_t base = sb + buf * GBUF;
    const __half* gps[2] = {Ahi, Bh};
    const int rb[2] = {m0, n0};
    #pragma unroll
    for (int it = 0; it < 8; it++) {
        const int idx = it * 256 + tid;         // 0..2047
        const int sub = idx >> 10;              // 0..1
        const int rg = idx & 1023;
        const int row = rg >> 3;
        const int c16 = rg & 7;
        const uint32_t saddr = base + sub * GSUBT + row * GROWB + c16 * 16;
        const void* gaddr = gps[sub] + (size_t)(rb[sub] + row) * CC + k0 + c16 * 8;
        CP_ASYNC16(saddr, gaddr);
    }
}

__global__ void __launch_bounds__(256, 2) gemm_tc_kernel(
    const __half* __restrict__ Ahi, const __half* __restrict__ Wbase,
    float* __restrict__ Yf,
    __half* __restrict__ Yq_hi, __half* __restrict__ Yk_hi,
    __half* __restrict__ Yv_hi, int mode)
{
    extern __shared__ char smem[];
    const uint32_t sb = smem_u32(smem);
    const int tid = threadIdx.x;
    const int lane = tid & 31;
    const int wid = tid >> 5;
    const int wm = (wid >> 2) * 64;
    const int wn = (wid & 3) * 32;

    int gsel = 0, nblk = blockIdx.x;
    if (mode == 1) { gsel = blockIdx.x >> 3; nblk = blockIdx.x & 7; }
    const int n0 = nblk * BNG;
    const int m0 = blockIdx.y * BMG;
    const __half* Bh = Wbase + (size_t)gsel * CC * CC;

    __half* Yhi = nullptr;
    float esc = INV32;
    if (mode == 1) {
        if (gsel == 0)      { Yhi = Yq_hi; esc = INV32 * SCALE_L2E; }
        else if (gsel == 1) Yhi = Yk_hi;
        else                Yhi = Yv_hi;
    }

    float acc[4][4][4] = {};

    load_chunk_async(sb, 0, tid, Ahi, Bh, m0, n0, 0);
    CP_COMMIT();

    const int a_row = (lane & 15);
    const int a_koff = (lane >> 4) << 3;
    const int b_row = ((lane >> 4) << 3) + (lane & 7);
    const int b_koff = ((lane >> 3) & 1) << 3;

    for (int c = 0; c < NKG; c++) {
        CP_WAIT0();
        __syncthreads();
        if (c + 1 < NKG) {
            load_chunk_async(sb, (c + 1) & 1, tid, Ahi, Bh, m0, n0, (c + 1) * BKG);
            CP_COMMIT();
        }

        const uint32_t ab = sb + (c & 1) * GBUF;
        const uint32_t bb = ab + GSUBT;

        #pragma unroll
        for (int ks = 0; ks < 4; ks++) {
            uint32_t ah[16], bh[8];
            #pragma unroll
            for (int mt = 0; mt < 4; mt++) {
                const uint32_t off =
                    (uint32_t)((wm + mt * 16 + a_row) * GROWB + (ks * 16 + a_koff) * 2);
                LDSM4(&ah[mt * 4], ab + off);
            }
            #pragma unroll
            for (int nt2 = 0; nt2 < 2; nt2++) {
                const uint32_t off =
                    (uint32_t)((wn + nt2 * 16 + b_row) * GROWB + (ks * 16 + b_koff) * 2);
                LDSM4(&bh[nt2 * 4], bb + off);
            }
            #pragma unroll
            for (int mt = 0; mt < 4; mt++)
                #pragma unroll
                for (int nt = 0; nt < 4; nt++)
                    MMA16816(acc[mt][nt], &ah[mt * 4], &bh[nt * 2]);
        }
        __syncthreads();
    }

    // epilogue: registers (x esc) -> smem staging -> coalesced global stores
    float* es = (float*)smem;   // [128][132] = 67584 B (fits in GEMM_SMEM)
    const int er = lane >> 2;
    const int ec = (lane & 3) * 2;
    #pragma unroll
    for (int mt = 0; mt < 4; mt++)
        #pragma unroll
        for (int nt = 0; nt < 4; nt++) {
            const int r = wm + mt * 16 + er;
            const int cl = wn + nt * 8 + ec;
            *(float2*)&es[r * 132 + cl] =
                make_float2(acc[mt][nt][0] * esc, acc[mt][nt][1] * esc);
            *(float2*)&es[(r + 8) * 132 + cl] =
                make_float2(acc[mt][nt][2] * esc, acc[mt][nt][3] * esc);
        }
    __syncthreads();

    #pragma unroll
    for (int it = 0; it < 16; it++) {
        const int i = tid + it * 256;
        const int r = i >> 5;
        const int c4 = (i & 31) * 4;
        float4 v = *(float4*)&es[r * 132 + c4];
        const int m = m0 + r;
        const int n = n0 + c4;
        if (mode == 1) {
            const int b = m >> 11, t = m & 2047, h = n >> 6, d = n & 63;
            const size_t idx = (((size_t)(b * HH + h) * TT) + t) * DH + d;
            *(uint2*)&Yhi[idx] =
                make_uint2(pack_h(v.x, v.y), pack_h(v.z, v.w));
        } else {
            *(float4*)&Yf[(size_t)m * CC + n] = v;
        }
    }
}

// ---------------------------------------------------------------------------
// Tensor-core flash attention (causal), 1-product fp16, 128 threads (4 warps),
// BM=64 Q rows per CTA, 4 CTAs/SM. Unchanged from R12 (170 us).
// ---------------------------------------------------------------------------
#define AROW 144
#define STAGEB (2 * 64 * AROW)       // 18432 (K + V)
#define KO_KH 0
#define KO_VH (64 * AROW)            // 9216
#define ATTN_SMEM (3 * STAGEB)       // 55296
#define MASKF (-60.0f)

__device__ __forceinline__ void load_kv_stage(
    uint32_t sb, int stage, int tid, size_t gbase, int kv0,
    const __half* __restrict__ khi, const __half* __restrict__ vhi)
{
    const uint32_t base = sb + stage * STAGEB;
    const __half* gps[2] = {khi, vhi};
    #pragma unroll
    for (int it = 0; it < 8; it++) {
        const int idx = tid + it * 128;         // 0..1023
        const int arr = idx >> 9;               // 0..1
        const int r = (idx >> 3) & 63;
        const int c = idx & 7;
        const uint32_t dst = base + arr * (64 * AROW) + r * AROW + c * 16;
        CP_ASYNC16(dst, gps[arr] + gbase + (size_t)(kv0 + r) * DH + c * 8);
    }
}

__global__ void __launch_bounds__(128, 4) flash_attn_tc_kernel(
    const __half* __restrict__ qhi,
    const __half* __restrict__ khi, const __half* __restrict__ vhi,
    __half* __restrict__ Ohi)
{
    extern __shared__ char smem[];
    const uint32_t sb = smem_u32(smem);
    const int tid = threadIdx.x;
    const int lane = tid & 31;
    const int wid = tid >> 5;               // 0..3
    const int wm = wid * 16;
    const int qi = 31 - (int)blockIdx.x;    // heavy tiles first
    const int bh = blockIdx.y;
    const int q0 = qi * 64;
    const size_t gbase = (size_t)bh * TT * DH;

    const int b_row = ((lane >> 4) << 3) + (lane & 7);
    const int b_koff = ((lane >> 3) & 1) << 3;
    const int v_krow = (lane & 7) + (((lane >> 3) & 1) << 3);
    const int v_noff = (lane >> 4) << 3;

    const int r0 = lane >> 2;
    const int cb = (lane & 3) * 2;
    const int tq0 = q0 + wm + r0;
    const int nkv = qi + 1;

    uint32_t qfh[4][4];
    {
        const size_t rA = gbase + (size_t)(q0 + wm + r0) * DH;
        const size_t rB = gbase + (size_t)(q0 + wm + r0 + 8) * DH;
        #pragma unroll
        for (int ks = 0; ks < 4; ks++) {
            const int c0 = ks * 16 + cb;
            qfh[ks][0] = *(const uint32_t*)(qhi + rA + c0);
            qfh[ks][1] = *(const uint32_t*)(qhi + rB + c0);
            qfh[ks][2] = *(const uint32_t*)(qhi + rA + c0 + 8);
            qfh[ks][3] = *(const uint32_t*)(qhi + rB + c0 + 8);
        }
    }

    load_kv_stage(sb, 0, tid, gbase, 0, khi, vhi);
    CP_COMMIT();
    if (nkv > 1) {
        load_kv_stage(sb, 1, tid, gbase, 64, khi, vhi);
        CP_COMMIT();
        CP_WAIT1();
    } else {
        CP_WAIT0();
    }
    __syncthreads();

    float m0 = MASKF, m1 = MASKF;
    float l0 = 0.0f, l1 = 0.0f;             // per-thread partial row sums
    float oacc[8][4] = {};

    for (int j = 0; j < nkv; j++) {
        const uint32_t stb = sb + (j % 3) * STAGEB;
        const bool pre = (j + 2 < nkv);
        if (pre) {
            load_kv_stage(sb, (j + 2) % 3, tid, gbase, (j + 2) * 64, khi, vhi);
            CP_COMMIT();
        }

        float s[8][4];
        #pragma unroll
        for (int nt = 0; nt < 8; nt++)
            #pragma unroll
            for (int e = 0; e < 4; e++) s[nt][e] = 0.0f;
        #pragma unroll
        for (int ks = 0; ks < 4; ks++) {
            #pragma unroll
            for (int ng = 0; ng < 4; ng++) {
                uint32_t bhf[4];
                const uint32_t boff =
                    (uint32_t)((ng * 16 + b_row) * AROW + (ks * 16 + b_koff) * 2);
                LDSM4(bhf, stb + KO_KH + boff);
                MMA16816(s[2 * ng], qfh[ks], &bhf[0]);
                MMA16816(s[2 * ng + 1], qfh[ks], &bhf[2]);
            }
        }

        const int kv0 = j * 64;
        if (kv0 + 63 > q0 + wm) {
            #pragma unroll
            for (int nt = 0; nt < 8; nt++)
                #pragma unroll
                for (int e = 0; e < 4; e++) {
                    const int tk = kv0 + nt * 8 + cb + (e & 1);
                    const int tq = tq0 + ((e >> 1) << 3);
                    if (tk > tq) s[nt][e] = MASKF;
                }
        }

        float zm0 = MASKF, zm1 = MASKF;
        #pragma unroll
        for (int nt = 0; nt < 8; nt++) {
            zm0 = fmaxf(zm0, fmaxf(s[nt][0], s[nt][1]));
            zm1 = fmaxf(zm1, fmaxf(s[nt][2], s[nt][3]));
        }
        zm0 = fmaxf(zm0, __shfl_xor_sync(0xffffffffu, zm0, 1));
        zm0 = fmaxf(zm0, __shfl_xor_sync(0xffffffffu, zm0, 2));
        zm1 = fmaxf(zm1, __shfl_xor_sync(0xffffffffu, zm1, 1));
        zm1 = fmaxf(zm1, __shfl_xor_sync(0xffffffffu, zm1, 2));
        const float mn0 = fmaxf(m0, zm0);
        const float mn1 = fmaxf(m1, zm1);
        const float rs0 = fexp2(m0 - mn0);
        const float rs1 = fexp2(m1 - mn1);
        float sum0 = 0.0f, sum1 = 0.0f;
        uint32_t pah[4][4];
        #pragma unroll
        for (int nt = 0; nt < 8; nt++) {
            float p0 = fexp2(s[nt][0] - mn0);
            float p1 = fexp2(s[nt][1] - mn0);
            float p2 = fexp2(s[nt][2] - mn1);
            float p3 = fexp2(s[nt][3] - mn1);
            sum0 += p0 + p1;
            sum1 += p2 + p3;
            const int kt = nt >> 1;
            const int o = (nt & 1) << 1;
            pah[kt][o]     = pack_h(p0, p1);
            pah[kt][o + 1] = pack_h(p2, p3);
        }
        l0 = l0 * rs0 + sum0;
        l1 = l1 * rs1 + sum1;
        m0 = mn0;
        m1 = mn1;

        if (!__all_sync(0xffffffffu, (rs0 == 1.0f) && (rs1 == 1.0f))) {
            #pragma unroll
            for (int nt = 0; nt < 8; nt++) {
                oacc[nt][0] *= rs0;
                oacc[nt][1] *= rs0;
                oacc[nt][2] *= rs1;
                oacc[nt][3] *= rs1;
            }
        }

        #pragma unroll
        for (int ks = 0; ks < 4; ks++) {
            #pragma unroll
            for (int ng = 0; ng < 4; ng++) {
                uint32_t vhf[4];
                const uint32_t voff =
                    (uint32_t)((ks * 16 + v_krow) * AROW + (ng * 16 + v_noff) * 2);
                LDSM4T(vhf, stb + KO_VH + voff);
                MMA16816(oacc[2 * ng], pah[ks], &vhf[0]);
                MMA16816(oacc[2 * ng + 1], pah[ks], &vhf[2]);
            }
        }

        if (j + 1 < nkv) {
            if (pre) { CP_WAIT1(); } else { CP_WAIT0(); }
        }
        __syncthreads();
    }

    // epilogue: quad-reduce l, normalize, fp16-hi, write [m, c]
    l0 += __shfl_xor_sync(0xffffffffu, l0, 1);
    l0 += __shfl_xor_sync(0xffffffffu, l0, 2);
    l1 += __shfl_xor_sync(0xffffffffu, l1, 1);
    l1 += __shfl_xor_sync(0xffffffffu, l1, 2);
    const float inv0 = 1.0f / l0;
    const float inv1 = 1.0f / l1;
    const int b = bh >> 4;
    const int h = bh & 15;
    const int trow0 = q0 + wm + r0;
    const int trow1 = trow0 + 8;
    #pragma unroll
    for (int nt = 0; nt < 8; nt++) {
        const int col = h * DH + nt * 8 + cb;
        *(uint32_t*)&Ohi[((size_t)b * TT + trow0) * CC + col] =
            pack_h(oacc[nt][0] * inv0, oacc[nt][1] * inv0);
        *(uint32_t*)&Ohi[((size_t)b * TT + trow1) * CC + col] =
            pack_h(oacc[nt][2] * inv1, oacc[nt][3] * inv1);
    }
}

// ---------------------------------------------------------------------------
// Launch
// ---------------------------------------------------------------------------
extern "C" void kernel_launch(void* const* d_in, const int* in_sizes, int n_in,
                              void* d_out, int out_size)
{
    const float* x   = (const float*)d_in[0];
    const float* W_Q = (const float*)d_in[1];
    const float* W_K = (const float*)d_in[2];
    const float* W_V = (const float*)d_in[3];
    const float* W_O = (const float*)d_in[4];
    float* out = (float*)d_out;

    __half *xhi, *wh, *qh, *kh, *vh, *ah;
    cudaGetSymbolAddress((void**)&xhi, g_xhi);
    cudaGetSymbolAddress((void**)&wh, g_wh);
    cudaGetSymbolAddress((void**)&qh, g_qhi);
    cudaGetSymbolAddress((void**)&kh, g_khi);
    cudaGetSymbolAddress((void**)&vh, g_vhi);
    cudaGetSymbolAddress((void**)&ah, g_ahi);

    cudaFuncSetAttribute(gemm_tc_kernel,
                         cudaFuncAttributeMaxDynamicSharedMemorySize, GEMM_SMEM);
    cudaFuncSetAttribute(flash_attn_tc_kernel,
                         cudaFuncAttributeMaxDynamicSharedMemorySize, ATTN_SMEM);

    const size_t WSZ = (size_t)CC * CC;

    convert_all_kernel<<<8192 + 4 * 1024, 256>>>(x, xhi, W_Q, W_K, W_V, W_O, wh);

    dim3 qkv_grid(3 * CC / BNG, MM / BMG);   // (24, 64)
    gemm_tc_kernel<<<qkv_grid, 256, GEMM_SMEM>>>(
        xhi, wh, nullptr, qh, kh, vh, 1);

    dim3 attn_grid(TT / 64, BB * HH);        // (32, 64)
    flash_attn_tc_kernel<<<attn_grid, 128, ATTN_SMEM>>>(qh, kh, vh, ah);

    dim3 out_grid(CC / BNG, MM / BMG);       // (8, 64)
    gemm_tc_kernel<<<out_grid, 256, GEMM_SMEM>>>(
        ah, wh + 3 * WSZ, out, nullptr, nullptr, nullptr, 0);
}